// round 2
// baseline (speedup 1.0000x reference)
#include <cuda_runtime.h>
#include <cstdint>

typedef unsigned long long ull;

#define NN   30000
#define INC  128
#define OC   64
#define MP   4
#define EE   480000
#define FFD  2048
#define TOK  (NN*MP)
#define LN_EPS 1e-5f

// ---- device scratch (allocation-free rule: __device__ globals) ----
__device__ float g_agg[(size_t)MP * NN * INC];   // 61.4 MB
__device__ float g_e[(size_t)TOK * OC];          // 30.7 MB

// ---- packed fp32x2 helpers (exact fp32 semantics) ----
__device__ __forceinline__ ull fma2(ull a, ull b, ull c) {
    ull d; asm("fma.rn.f32x2 %0, %1, %2, %3;" : "=l"(d) : "l"(a), "l"(b), "l"(c)); return d;
}
__device__ __forceinline__ ull splat2(float x) {
    ull v; asm("mov.b64 %0, {%1, %1};" : "=l"(v) : "f"(x)); return v;
}
__device__ __forceinline__ float2 u2f(ull v) {
    float2 f; asm("mov.b64 {%0, %1}, %2;" : "=f"(f.x), "=f"(f.y) : "l"(v)); return f;
}
__device__ __forceinline__ ull f2u(float x, float y) {
    ull v; asm("mov.b64 %0, {%1, %2};" : "=l"(v) : "f"(x), "f"(y)); return v;
}

// =====================================================================
// K0: zero agg buffer
// =====================================================================
__global__ void k_zero() {
    size_t i = (size_t)blockIdx.x * 256 + threadIdx.x;
    ((float4*)g_agg)[i] = make_float4(0.f, 0.f, 0.f, 0.f);
}

// =====================================================================
// K1: edge scatter: agg[m][src] += x[dst]. warp/edge, lane = float4 (RED.128)
// =====================================================================
__global__ void k_scatter(const float* __restrict__ x, const int* __restrict__ ei) {
    int wid  = (blockIdx.x * blockDim.x + threadIdx.x) >> 5;
    int lane = threadIdx.x & 31;
    int m = wid / EE;
    int e = wid - m * EE;
    const int* b = ei + (size_t)m * 2 * EE;
    int src = __ldg(b + e);
    int dst = __ldg(b + EE + e);
    float4 v = ((const float4*)(x + (size_t)dst * INC))[lane];
    atomicAdd(((float4*)(g_agg + ((size_t)m * NN + src) * INC)) + lane, v);
}

// =====================================================================
// K2: per-metapath GNN:
//   h = relu(agg@Wl^T + x@(W0+W1)^T + bsum); e_m = (h@Wo^T + bo)*mpw[m]
// blockIdx.y = metapath; warp per node.
// =====================================================================
__global__ void __launch_bounds__(256, 1) k_gnn(
    const float* __restrict__ x,
    const float* __restrict__ W0, const float* __restrict__ b0,
    const float* __restrict__ Wl, const float* __restrict__ bl,
    const float* __restrict__ W1, const float* __restrict__ b1,
    const float* __restrict__ Wo, const float* __restrict__ bo,
    const float* __restrict__ mpw)
{
    extern __shared__ float sm[];
    float* sWlT = sm;            // [128 k][65]
    float* sWcT = sm + 8320;     // [128 k][65]
    float* sWoT = sm + 16640;    // [64 i][65]
    float* sHB  = sm + 20800;    // 64
    float* sBo  = sm + 20864;    // 64
    float* sH   = sm + 20928;    // 8 warps * 64
    float* sRow = sm + 21440;    // 8 warps * 256
    int t = threadIdx.x;
    int m = blockIdx.y;

    for (int i = t; i < 8192; i += 256) {
        int j = i >> 7, k = i & 127;
        size_t off = (size_t)m * 8192 + (size_t)j * 128 + k;
        sWlT[k * 65 + j] = Wl[off];
        sWcT[k * 65 + j] = W0[off] + W1[off];
    }
    for (int i = t; i < 4096; i += 256) {
        int j = i >> 6, k = i & 63;
        sWoT[k * 65 + j] = Wo[(size_t)m * 4096 + j * 64 + k];
    }
    if (t < 64) {
        sHB[t] = bl[m * 64 + t] + b0[m * 64 + t] + b1[m * 64 + t];
        sBo[t] = bo[m * 64 + t];
    }
    __syncthreads();

    float wgt = mpw[m];
    int w = t >> 5, lane = t & 31;
    float* row  = sRow + w * 256;
    float* hrow = sH + w * 64;

    for (int n = blockIdx.x * 8 + w; n < NN; n += gridDim.x * 8) {
        ((float4*)row)[lane]         = ((const float4*)(g_agg + ((size_t)m * NN + n) * INC))[lane];
        ((float4*)(row + 128))[lane] = ((const float4*)(x + (size_t)n * INC))[lane];
        __syncwarp();
        float a0 = 0.f, a1 = 0.f;
        #pragma unroll 4
        for (int k = 0; k < 128; k++) {
            float av = row[k], xv = row[128 + k];
            a0 = fmaf(av, sWlT[k * 65 + lane], a0);
            a0 = fmaf(xv, sWcT[k * 65 + lane], a0);
            a1 = fmaf(av, sWlT[k * 65 + lane + 32], a1);
            a1 = fmaf(xv, sWcT[k * 65 + lane + 32], a1);
        }
        hrow[lane]      = fmaxf(a0 + sHB[lane], 0.f);
        hrow[lane + 32] = fmaxf(a1 + sHB[lane + 32], 0.f);
        __syncwarp();
        float o0 = sBo[lane], o1 = sBo[lane + 32];
        #pragma unroll 8
        for (int i = 0; i < 64; i++) {
            float hv = hrow[i];
            o0 = fmaf(hv, sWoT[i * 65 + lane], o0);
            o1 = fmaf(hv, sWoT[i * 65 + lane + 32], o1);
        }
        float* eo = g_e + ((size_t)n * MP + m) * OC;
        eo[lane]      = o0 * wgt;
        eo[lane + 32] = o1 * wgt;
        __syncwarp();
    }
}

// =====================================================================
// K3: attention sublayer (qkv, MHA over M=4, proj, residual, LN1), in-place on g_e
// block = 4 nodes x 64 threads
// =====================================================================
__global__ void __launch_bounds__(256, 1) k_attn(
    const float* __restrict__ tinw, const float* __restrict__ tinb,
    const float* __restrict__ tow,  const float* __restrict__ tob,
    const float* __restrict__ g1,   const float* __restrict__ b1v, int l)
{
    extern __shared__ float sm[];
    float* sTinT = sm;           // [64 k][193]
    float* sTowT = sm + 12352;   // [64 i][65]
    float* sTinB = sm + 16512;   // 192
    float* sToB  = sm + 16704;   // 64
    float* sE    = sm + 16768;   // 4 * 256
    float* sQKV  = sm + 17792;   // 4 * 768
    float* sAO   = sm + 20864;   // 4 * 256
    int t = threadIdx.x;

    const float* tw = tinw + (size_t)l * 192 * 64;
    for (int i = t; i < 12288; i += 256) {
        int r = i >> 6, k = i & 63;
        sTinT[k * 193 + r] = tw[r * 64 + k];
    }
    const float* twO = tow + (size_t)l * 64 * 64;
    for (int i = t; i < 4096; i += 256) {
        int j = i >> 6, k = i & 63;
        sTowT[k * 65 + j] = twO[j * 64 + k];
    }
    if (t < 192) sTinB[t] = tinb[l * 192 + t];
    if (t < 64)  sToB[t]  = tob[l * 64 + t];

    int s = t >> 6, tt = t & 63;
    int node = blockIdx.x * 4 + s;
    float* eN   = sE + s * 256;
    float* qkvN = sQKV + s * 768;
    float* aoN  = sAO + s * 256;
    for (int i = tt; i < 256; i += 64) eN[i] = g_e[(size_t)node * 256 + i];
    __syncthreads();

    // qkv
    {
        float aq[4], ak[4], av[4];
        #pragma unroll
        for (int m2 = 0; m2 < 4; m2++) {
            aq[m2] = sTinB[tt]; ak[m2] = sTinB[64 + tt]; av[m2] = sTinB[128 + tt];
        }
        #pragma unroll 2
        for (int k = 0; k < 64; k++) {
            float wq = sTinT[k * 193 + tt];
            float wk = sTinT[k * 193 + 64 + tt];
            float wv = sTinT[k * 193 + 128 + tt];
            #pragma unroll
            for (int m2 = 0; m2 < 4; m2++) {
                float ev = eN[m2 * 64 + k];
                aq[m2] = fmaf(ev, wq, aq[m2]);
                ak[m2] = fmaf(ev, wk, ak[m2]);
                av[m2] = fmaf(ev, wv, av[m2]);
            }
        }
        #pragma unroll
        for (int m2 = 0; m2 < 4; m2++) {
            qkvN[m2 * 192 + tt]       = aq[m2];
            qkvN[m2 * 192 + 64 + tt]  = ak[m2];
            qkvN[m2 * 192 + 128 + tt] = av[m2];
        }
    }
    __syncthreads();

    // attention core: thread (h, mq), h = tt>>2, mq = tt&3, for tt < 32
    if (tt < 32) {
        int h = tt >> 2, mq = tt & 3;
        float q[8];
        #pragma unroll
        for (int d = 0; d < 8; d++) q[d] = qkvN[mq * 192 + h * 8 + d];
        float sc[4];
        #pragma unroll
        for (int mk = 0; mk < 4; mk++) {
            float a = 0.f;
            #pragma unroll
            for (int d = 0; d < 8; d++) a = fmaf(q[d], qkvN[mk * 192 + 64 + h * 8 + d], a);
            sc[mk] = a * 0.35355339059327373f;
        }
        float mx = fmaxf(fmaxf(sc[0], sc[1]), fmaxf(sc[2], sc[3]));
        float p[4]; float psum = 0.f;
        #pragma unroll
        for (int mk = 0; mk < 4; mk++) { p[mk] = __expf(sc[mk] - mx); psum += p[mk]; }
        float inv = 1.0f / psum;
        #pragma unroll
        for (int d = 0; d < 8; d++) {
            float o = 0.f;
            #pragma unroll
            for (int mk = 0; mk < 4; mk++) o = fmaf(p[mk] * inv, qkvN[mk * 192 + 128 + h * 8 + d], o);
            aoN[mq * 64 + h * 8 + d] = o;
        }
    }
    __syncthreads();

    // proj + residual (channel = tt)
    {
        float acc[4];
        #pragma unroll
        for (int m2 = 0; m2 < 4; m2++) acc[m2] = sToB[tt];
        #pragma unroll 4
        for (int i = 0; i < 64; i++) {
            float wv = sTowT[i * 65 + tt];
            #pragma unroll
            for (int m2 = 0; m2 < 4; m2++) acc[m2] = fmaf(aoN[m2 * 64 + i], wv, acc[m2]);
        }
        #pragma unroll
        for (int m2 = 0; m2 < 4; m2++) eN[m2 * 64 + tt] += acc[m2];
    }
    __syncthreads();

    // LN1: 16 tokens/block; 16 threads each cover 4 channels
    int tl = t >> 4, part = t & 15;
    int ss = tl >> 2, m2 = tl & 3;
    const float* base = sE + ss * 256 + m2 * 64;
    float sum = 0.f, sq = 0.f;
    #pragma unroll
    for (int i2 = 0; i2 < 4; i2++) { float v = base[part * 4 + i2]; sum += v; sq += v * v; }
    #pragma unroll
    for (int off = 1; off < 16; off <<= 1) {
        sum += __shfl_xor_sync(0xffffffffu, sum, off);
        sq  += __shfl_xor_sync(0xffffffffu, sq,  off);
    }
    float mu   = sum * (1.f / 64.f);
    float rstd = rsqrtf(sq * (1.f / 64.f) - mu * mu + LN_EPS);
    int nodeW = blockIdx.x * 4 + ss;
    #pragma unroll
    for (int i2 = 0; i2 < 4; i2++) {
        int c = part * 4 + i2;
        float v = base[c];
        g_e[((size_t)nodeW * 4 + m2) * 64 + c] = (v - mu) * rstd * g1[l * 64 + c] + b1v[l * 64 + c];
    }
}

// =====================================================================
// K4: FF sublayer (64->2048->relu->64) + residual + LN2, in-place on g_e.
// block = 64 tokens; f32x2 token-pair packing; 16 chunks of 128 j.
// =====================================================================
__global__ void __launch_bounds__(256, 1) k_ff(
    const float* __restrict__ ff1w, const float* __restrict__ ff1b,
    const float* __restrict__ ff2w, const float* __restrict__ ff2b,
    const float* __restrict__ g2,   const float* __restrict__ b2, int l)
{
    extern __shared__ float sm[];
    float* sEt = sm;             // [64 c][72]  token-major rows (original e, kept for residual)
    float* sHt = sm + 4608;      // [128 j][72]
    float* sW1 = sm + 13824;     // [128 j][65]
    float* sW2 = sm + 22144;     // [64 c][130]
    float* sO  = sm + 30464;     // [64 tok][65]
    float* sB1 = sm + 34624;     // [128]
    int t = threadIdx.x;
    int tok0 = blockIdx.x * 64;

    const float* f1w = ff1w + (size_t)l * FFD * OC;
    const float* f1b = ff1b + (size_t)l * FFD;
    const float* f2w = ff2w + (size_t)l * OC * FFD;

    // transpose E tile into smem: sEt[c][tok]
    for (int i = t; i < 4096; i += 256) {
        int tk = i >> 6, c = i & 63;
        sEt[c * 72 + tk] = g_e[(size_t)tok0 * 64 + i];
    }

    // GEMM2 persistent accumulators (init with ff2 bias)
    int cg = t >> 4, pg2 = t & 15;
    ull o2[4][2];
    #pragma unroll
    for (int cc = 0; cc < 4; cc++) {
        ull b = splat2(ff2b[l * OC + 4 * cg + cc]);
        o2[cc][0] = b; o2[cc][1] = b;
    }
    int jg = t >> 3, pg = t & 7;

    for (int ch = 0; ch < 16; ch++) {
        __syncthreads();
        int jbaseG = ch * 128;
        for (int i = t; i < 8192; i += 256) {
            int jl = i >> 6, k = i & 63;
            sW1[jl * 65 + k] = f1w[(size_t)(jbaseG + jl) * 64 + k];
        }
        for (int i = t; i < 8192; i += 256) {
            int c = i >> 7, jl = i & 127;
            sW2[c * 130 + jl] = f2w[(size_t)c * FFD + jbaseG + jl];
        }
        if (t < 128) sB1[t] = f1b[jbaseG + t];
        __syncthreads();

        // GEMM1: H[j][tok] = relu(bias + E^T W1^T), thread: 4 j x 4 token-pairs
        ull acc[4][4];
        #pragma unroll
        for (int jj = 0; jj < 4; jj++) {
            ull b = splat2(sB1[4 * jg + jj]);
            acc[jj][0] = b; acc[jj][1] = b; acc[jj][2] = b; acc[jj][3] = b;
        }
        #pragma unroll 2
        for (int k = 0; k < 64; k++) {
            const ull* er = (const ull*)(sEt + k * 72) + 4 * pg;
            ull e0 = er[0], e1 = er[1], e2v = er[2], e3v = er[3];
            const float* wr = sW1 + k;
            #pragma unroll
            for (int jj = 0; jj < 4; jj++) {
                ull wv = splat2(wr[(4 * jg + jj) * 65]);
                acc[jj][0] = fma2(e0,  wv, acc[jj][0]);
                acc[jj][1] = fma2(e1,  wv, acc[jj][1]);
                acc[jj][2] = fma2(e2v, wv, acc[jj][2]);
                acc[jj][3] = fma2(e3v, wv, acc[jj][3]);
            }
        }
        #pragma unroll
        for (int jj = 0; jj < 4; jj++) {
            ull* hr = (ull*)(sHt + (4 * jg + jj) * 72) + 4 * pg;
            #pragma unroll
            for (int p = 0; p < 4; p++) {
                float2 f = u2f(acc[jj][p]);
                f.x = fmaxf(f.x, 0.f); f.y = fmaxf(f.y, 0.f);
                hr[p] = f2u(f.x, f.y);
            }
        }
        __syncthreads();

        // GEMM2: O[tok][c] += H^T W2^T, thread: 4 c x 2 token-pairs
        #pragma unroll 4
        for (int j = 0; j < 128; j++) {
            const ull* hr = (const ull*)(sHt + j * 72) + 2 * pg2;
            ull h0 = hr[0], h1 = hr[1];
            const float* wr = sW2 + j;
            #pragma unroll
            for (int cc = 0; cc < 4; cc++) {
                ull wv = splat2(wr[(4 * cg + cc) * 130]);
                o2[cc][0] = fma2(h0, wv, o2[cc][0]);
                o2[cc][1] = fma2(h1, wv, o2[cc][1]);
            }
        }
    }

    // epilogue: residual then LN2
    #pragma unroll
    for (int cc = 0; cc < 4; cc++) {
        int c = 4 * cg + cc;
        #pragma unroll
        for (int q = 0; q < 2; q++) {
            float2 f = u2f(o2[cc][q]);
            int tk = 4 * pg2 + 2 * q;
            sO[tk * 65 + c]       = f.x + sEt[c * 72 + tk];
            sO[(tk + 1) * 65 + c] = f.y + sEt[c * 72 + tk + 1];
        }
    }
    __syncthreads();

    int tk = t >> 2, part = t & 3;
    const float* ob = sO + tk * 65 + part * 16;
    float s = 0.f, s2 = 0.f;
    #pragma unroll
    for (int i = 0; i < 16; i++) { float v = ob[i]; s += v; s2 += v * v; }
    s  += __shfl_xor_sync(0xffffffffu, s, 1);  s2 += __shfl_xor_sync(0xffffffffu, s2, 1);
    s  += __shfl_xor_sync(0xffffffffu, s, 2);  s2 += __shfl_xor_sync(0xffffffffu, s2, 2);
    float mu   = s * (1.f / 64.f);
    float rstd = rsqrtf(s2 * (1.f / 64.f) - mu * mu + LN_EPS);
    #pragma unroll
    for (int i = 0; i < 16; i++) {
        int c = part * 16 + i;
        float v = sO[tk * 65 + c];
        g_e[(size_t)(tok0 + tk) * 64 + c] = (v - mu) * rstd * g2[l * OC + c] + b2[l * OC + c];
    }
}

// =====================================================================
// K5: head: pooled mean over M; relu(pooled@r1^T+b1)@r2^T + b2
// =====================================================================
__global__ void __launch_bounds__(256) k_head(
    const float* __restrict__ r1w, const float* __restrict__ r1b,
    const float* __restrict__ r2w, const float* __restrict__ r2b,
    float* __restrict__ out)
{
    __shared__ float sR1T[64 * 65];
    __shared__ float sR2[64];
    __shared__ float sP[8][64];
    int t = threadIdx.x;
    for (int i = t; i < 4096; i += 256) {
        int c = i >> 6, k = i & 63;
        sR1T[k * 65 + c] = r1w[c * 64 + k];
    }
    if (t < 64) sR2[t] = r2w[t];
    __syncthreads();
    int w = t >> 5, lane = t & 31;
    int n = blockIdx.x * 8 + w;
    const float* eb = g_e + (size_t)n * 256;
    float p0 = (eb[lane] + eb[64 + lane] + eb[128 + lane] + eb[192 + lane]) * 0.25f;
    float p1 = (eb[32 + lane] + eb[96 + lane] + eb[160 + lane] + eb[224 + lane]) * 0.25f;
    sP[w][lane]      = p0;
    sP[w][lane + 32] = p1;
    __syncwarp();
    float a0 = r1b[lane], a1 = r1b[lane + 32];
    #pragma unroll 8
    for (int k = 0; k < 64; k++) {
        float pv = sP[w][k];
        a0 = fmaf(pv, sR1T[k * 65 + lane], a0);
        a1 = fmaf(pv, sR1T[k * 65 + lane + 32], a1);
    }
    a0 = fmaxf(a0, 0.f); a1 = fmaxf(a1, 0.f);
    float acc = a0 * sR2[lane] + a1 * sR2[lane + 32];
    #pragma unroll
    for (int off = 16; off; off >>= 1) acc += __shfl_xor_sync(0xffffffffu, acc, off);
    if (lane == 0) out[n] = acc + r2b[0];
}

// =====================================================================
extern "C" void kernel_launch(void* const* d_in, const int* in_sizes, int n_in,
                              void* d_out, int out_size) {
    const float* x    = (const float*)d_in[0];
    const int*   ei   = (const int*)  d_in[1];
    const float* mpw  = (const float*)d_in[2];
    const float* W0   = (const float*)d_in[3];
    const float* b0   = (const float*)d_in[4];
    const float* Wl   = (const float*)d_in[5];
    const float* bl   = (const float*)d_in[6];
    const float* W1   = (const float*)d_in[7];
    const float* b1   = (const float*)d_in[8];
    const float* Wo   = (const float*)d_in[9];
    const float* bo   = (const float*)d_in[10];
    const float* tinw = (const float*)d_in[11];
    const float* tinb = (const float*)d_in[12];
    const float* tow  = (const float*)d_in[13];
    const float* tob  = (const float*)d_in[14];
    const float* ln1g = (const float*)d_in[15];
    const float* ln1b = (const float*)d_in[16];
    const float* ff1w = (const float*)d_in[17];
    const float* ff1b = (const float*)d_in[18];
    const float* ff2w = (const float*)d_in[19];
    const float* ff2b = (const float*)d_in[20];
    const float* ln2g = (const float*)d_in[21];
    const float* ln2b = (const float*)d_in[22];
    const float* r1w  = (const float*)d_in[23];
    const float* r1b  = (const float*)d_in[24];
    const float* r2w  = (const float*)d_in[25];
    const float* r2b  = (const float*)d_in[26];
    float* out = (float*)d_out;
    (void)in_sizes; (void)n_in; (void)out_size;

    cudaFuncSetAttribute(k_gnn,  cudaFuncAttributeMaxDynamicSharedMemorySize, 23488 * 4);
    cudaFuncSetAttribute(k_attn, cudaFuncAttributeMaxDynamicSharedMemorySize, 21888 * 4);
    cudaFuncSetAttribute(k_ff,   cudaFuncAttributeMaxDynamicSharedMemorySize, 34752 * 4);

    k_zero<<<15000, 256>>>();
    k_scatter<<<240000, 256>>>(x, ei);
    dim3 gg(235, 4);
    k_gnn<<<gg, 256, 23488 * 4>>>(x, W0, b0, Wl, bl, W1, b1, Wo, bo, mpw);
    for (int l = 0; l < 2; l++) {
        k_attn<<<7500, 256, 21888 * 4>>>(tinw, tinb, tow, tob, ln1g, ln1b, l);
        k_ff<<<1875, 256, 34752 * 4>>>(ff1w, ff1b, ff2w, ff2b, ln2g, ln2b, l);
    }
    k_head<<<3750, 256>>>(r1w, r1b, r2w, r2b, out);
}

// round 3
// speedup vs baseline: 1.3657x; 1.3657x over previous
#include <cuda_runtime.h>
#include <cstdint>

typedef unsigned long long ull;

#define NN   30000
#define INC  128
#define OC   64
#define MP   4
#define EE   480000
#define FFD  2048
#define TOK  (NN*MP)
#define TB   128                 // tokens per ff block
#define NBLK ((TOK + TB - 1) / TB)   // 938
#define TOKP (NBLK * TB)             // 120064 (padded)
#define LN_EPS 1e-5f

// ---- device scratch (allocation-free rule: __device__ globals) ----
__device__ float g_agg[(size_t)MP * NN * INC];   // 61.4 MB
__device__ float g_e[(size_t)TOKP * OC];         // 30.7 MB (padded)

// ---- packed fp32x2 helpers (exact fp32 semantics) ----
__device__ __forceinline__ ull fma2(ull a, ull b, ull c) {
    ull d; asm("fma.rn.f32x2 %0, %1, %2, %3;" : "=l"(d) : "l"(a), "l"(b), "l"(c)); return d;
}
__device__ __forceinline__ ull splat2(float x) {
    ull v; asm("mov.b64 %0, {%1, %1};" : "=l"(v) : "f"(x)); return v;
}
__device__ __forceinline__ float2 u2f(ull v) {
    float2 f; asm("mov.b64 {%0, %1}, %2;" : "=f"(f.x), "=f"(f.y) : "l"(v)); return f;
}
__device__ __forceinline__ ull f2u(float x, float y) {
    ull v; asm("mov.b64 %0, {%1, %2};" : "=l"(v) : "f"(x), "f"(y)); return v;
}

// =====================================================================
// K0: zero agg buffer
// =====================================================================
__global__ void k_zero() {
    size_t i = (size_t)blockIdx.x * 256 + threadIdx.x;
    ((float4*)g_agg)[i] = make_float4(0.f, 0.f, 0.f, 0.f);
}

// =====================================================================
// K1: edge scatter: agg[m][src] += x[dst]. warp/edge, lane = float4 (RED.128)
// =====================================================================
__global__ void k_scatter(const float* __restrict__ x, const int* __restrict__ ei) {
    int wid  = (blockIdx.x * blockDim.x + threadIdx.x) >> 5;
    int lane = threadIdx.x & 31;
    int m = wid / EE;
    int e = wid - m * EE;
    const int* b = ei + (size_t)m * 2 * EE;
    int src = __ldg(b + e);
    int dst = __ldg(b + EE + e);
    float4 v = ((const float4*)(x + (size_t)dst * INC))[lane];
    atomicAdd(((float4*)(g_agg + ((size_t)m * NN + src) * INC)) + lane, v);
}

// =====================================================================
// K2: per-metapath GNN
// =====================================================================
__global__ void __launch_bounds__(256, 1) k_gnn(
    const float* __restrict__ x,
    const float* __restrict__ W0, const float* __restrict__ b0,
    const float* __restrict__ Wl, const float* __restrict__ bl,
    const float* __restrict__ W1, const float* __restrict__ b1,
    const float* __restrict__ Wo, const float* __restrict__ bo,
    const float* __restrict__ mpw)
{
    extern __shared__ float sm[];
    float* sWlT = sm;            // [128 k][65]
    float* sWcT = sm + 8320;     // [128 k][65]
    float* sWoT = sm + 16640;    // [64 i][65]
    float* sHB  = sm + 20800;    // 64
    float* sBo  = sm + 20864;    // 64
    float* sH   = sm + 20928;    // 8 warps * 64
    float* sRow = sm + 21440;    // 8 warps * 256
    int t = threadIdx.x;
    int m = blockIdx.y;

    for (int i = t; i < 8192; i += 256) {
        int j = i >> 7, k = i & 127;
        size_t off = (size_t)m * 8192 + (size_t)j * 128 + k;
        sWlT[k * 65 + j] = Wl[off];
        sWcT[k * 65 + j] = W0[off] + W1[off];
    }
    for (int i = t; i < 4096; i += 256) {
        int j = i >> 6, k = i & 63;
        sWoT[k * 65 + j] = Wo[(size_t)m * 4096 + j * 64 + k];
    }
    if (t < 64) {
        sHB[t] = bl[m * 64 + t] + b0[m * 64 + t] + b1[m * 64 + t];
        sBo[t] = bo[m * 64 + t];
    }
    __syncthreads();

    float wgt = mpw[m];
    int w = t >> 5, lane = t & 31;
    float* row  = sRow + w * 256;
    float* hrow = sH + w * 64;

    for (int n = blockIdx.x * 8 + w; n < NN; n += gridDim.x * 8) {
        ((float4*)row)[lane]         = ((const float4*)(g_agg + ((size_t)m * NN + n) * INC))[lane];
        ((float4*)(row + 128))[lane] = ((const float4*)(x + (size_t)n * INC))[lane];
        __syncwarp();
        float a0 = 0.f, a1 = 0.f;
        #pragma unroll 4
        for (int k = 0; k < 128; k++) {
            float av = row[k], xv = row[128 + k];
            a0 = fmaf(av, sWlT[k * 65 + lane], a0);
            a0 = fmaf(xv, sWcT[k * 65 + lane], a0);
            a1 = fmaf(av, sWlT[k * 65 + lane + 32], a1);
            a1 = fmaf(xv, sWcT[k * 65 + lane + 32], a1);
        }
        hrow[lane]      = fmaxf(a0 + sHB[lane], 0.f);
        hrow[lane + 32] = fmaxf(a1 + sHB[lane + 32], 0.f);
        __syncwarp();
        float o0 = sBo[lane], o1 = sBo[lane + 32];
        #pragma unroll 8
        for (int i = 0; i < 64; i++) {
            float hv = hrow[i];
            o0 = fmaf(hv, sWoT[i * 65 + lane], o0);
            o1 = fmaf(hv, sWoT[i * 65 + lane + 32], o1);
        }
        float* eo = g_e + ((size_t)n * MP + m) * OC;
        eo[lane]      = o0 * wgt;
        eo[lane + 32] = o1 * wgt;
        __syncwarp();
    }
}

// =====================================================================
// K3: attention sublayer, 8 nodes per block (512 threads)
// =====================================================================
__global__ void __launch_bounds__(512, 1) k_attn(
    const float* __restrict__ tinw, const float* __restrict__ tinb,
    const float* __restrict__ tow,  const float* __restrict__ tob,
    const float* __restrict__ g1,   const float* __restrict__ b1v, int l)
{
    extern __shared__ float sm[];
    float* sTinT = sm;           // [64 k][193]
    float* sTowT = sm + 12352;   // [64 i][65]
    float* sTinB = sm + 16512;   // 192
    float* sToB  = sm + 16704;   // 64
    float* sE    = sm + 16768;   // 8 * 256
    float* sQKV  = sm + 18816;   // 8 * 768
    float* sAO   = sm + 24960;   // 8 * 256
    int t = threadIdx.x;

    const float* tw = tinw + (size_t)l * 192 * 64;
    for (int i = t; i < 12288; i += 512) {
        int r = i >> 6, k = i & 63;
        sTinT[k * 193 + r] = tw[r * 64 + k];
    }
    const float* twO = tow + (size_t)l * 64 * 64;
    for (int i = t; i < 4096; i += 512) {
        int j = i >> 6, k = i & 63;
        sTowT[k * 65 + j] = twO[j * 64 + k];
    }
    if (t < 192) sTinB[t] = tinb[l * 192 + t];
    if (t >= 192 && t < 256) sToB[t - 192] = tob[l * 64 + (t - 192)];

    int s = t >> 6, tt = t & 63;
    int node = blockIdx.x * 8 + s;
    float* eN   = sE + s * 256;
    float* qkvN = sQKV + s * 768;
    float* aoN  = sAO + s * 256;
    for (int i = tt; i < 256; i += 64) eN[i] = g_e[(size_t)node * 256 + i];
    __syncthreads();

    // qkv
    {
        float aq[4], ak[4], av[4];
        #pragma unroll
        for (int m2 = 0; m2 < 4; m2++) {
            aq[m2] = sTinB[tt]; ak[m2] = sTinB[64 + tt]; av[m2] = sTinB[128 + tt];
        }
        #pragma unroll 2
        for (int k = 0; k < 64; k++) {
            float wq = sTinT[k * 193 + tt];
            float wk = sTinT[k * 193 + 64 + tt];
            float wv = sTinT[k * 193 + 128 + tt];
            #pragma unroll
            for (int m2 = 0; m2 < 4; m2++) {
                float ev = eN[m2 * 64 + k];
                aq[m2] = fmaf(ev, wq, aq[m2]);
                ak[m2] = fmaf(ev, wk, ak[m2]);
                av[m2] = fmaf(ev, wv, av[m2]);
            }
        }
        #pragma unroll
        for (int m2 = 0; m2 < 4; m2++) {
            qkvN[m2 * 192 + tt]       = aq[m2];
            qkvN[m2 * 192 + 64 + tt]  = ak[m2];
            qkvN[m2 * 192 + 128 + tt] = av[m2];
        }
    }
    __syncthreads();

    // attention core: 32 threads per node group
    if (tt < 32) {
        int h = tt >> 2, mq = tt & 3;
        float q[8];
        #pragma unroll
        for (int d = 0; d < 8; d++) q[d] = qkvN[mq * 192 + h * 8 + d];
        float sc[4];
        #pragma unroll
        for (int mk = 0; mk < 4; mk++) {
            float a = 0.f;
            #pragma unroll
            for (int d = 0; d < 8; d++) a = fmaf(q[d], qkvN[mk * 192 + 64 + h * 8 + d], a);
            sc[mk] = a * 0.35355339059327373f;
        }
        float mx = fmaxf(fmaxf(sc[0], sc[1]), fmaxf(sc[2], sc[3]));
        float p[4]; float psum = 0.f;
        #pragma unroll
        for (int mk = 0; mk < 4; mk++) { p[mk] = __expf(sc[mk] - mx); psum += p[mk]; }
        float inv = 1.0f / psum;
        #pragma unroll
        for (int d = 0; d < 8; d++) {
            float o = 0.f;
            #pragma unroll
            for (int mk = 0; mk < 4; mk++) o = fmaf(p[mk] * inv, qkvN[mk * 192 + 128 + h * 8 + d], o);
            aoN[mq * 64 + h * 8 + d] = o;
        }
    }
    __syncthreads();

    // proj + residual (channel = tt)
    {
        float acc[4];
        #pragma unroll
        for (int m2 = 0; m2 < 4; m2++) acc[m2] = sToB[tt];
        #pragma unroll 4
        for (int i = 0; i < 64; i++) {
            float wv = sTowT[i * 65 + tt];
            #pragma unroll
            for (int m2 = 0; m2 < 4; m2++) acc[m2] = fmaf(aoN[m2 * 64 + i], wv, acc[m2]);
        }
        #pragma unroll
        for (int m2 = 0; m2 < 4; m2++) eN[m2 * 64 + tt] += acc[m2];
    }
    __syncthreads();

    // LN1: 32 tokens/block; 16 threads each cover 4 channels
    int tl = t >> 4, part = t & 15;
    int ss = tl >> 2, m2 = tl & 3;
    const float* base = sE + ss * 256 + m2 * 64;
    float sum = 0.f, sq = 0.f;
    #pragma unroll
    for (int i2 = 0; i2 < 4; i2++) { float v = base[part * 4 + i2]; sum += v; sq += v * v; }
    #pragma unroll
    for (int off = 1; off < 16; off <<= 1) {
        sum += __shfl_xor_sync(0xffffffffu, sum, off);
        sq  += __shfl_xor_sync(0xffffffffu, sq,  off);
    }
    float mu   = sum * (1.f / 64.f);
    float rstd = rsqrtf(sq * (1.f / 64.f) - mu * mu + LN_EPS);
    int nodeW = blockIdx.x * 8 + ss;
    #pragma unroll
    for (int i2 = 0; i2 < 4; i2++) {
        int c = part * 4 + i2;
        float v = base[c];
        g_e[((size_t)nodeW * 4 + m2) * 64 + c] = (v - mu) * rstd * g1[l * 64 + c] + b1v[l * 64 + c];
    }
}

// =====================================================================
// K4: FF sublayer (64->2048->relu->64) + residual + LN2.
// 128-token tile, 16 chunks of 128 j, ratio-4 register blocking, fma2.
// GEMM1: thread = 8j x 8tok (pairs pg+16p). GEMM2: ksplit2, thread = 8c x 8tok.
// =====================================================================
__global__ void __launch_bounds__(256, 1) k_ff(
    const float* __restrict__ ff1w, const float* __restrict__ ff1b,
    const float* __restrict__ ff2w, const float* __restrict__ ff2b,
    const float* __restrict__ g2,   const float* __restrict__ b2, int l)
{
    extern __shared__ float sm[];
    float* sEt = sm;             // [64 c][132]
    float* sHt = sm + 8448;      // [128 j][132]
    float* sW1 = sm + 25344;     // [128 j][65]
    float* sW2 = sm + 33664;     // [64 c][130]
    float* sB1 = sm + 41984;     // 128
    float* sRed = sW1;           // alias (epilogue)
    float* sO   = sW2;           // alias (epilogue) [128 tok][65]
    int t = threadIdx.x;
    size_t tok0 = (size_t)blockIdx.x * TB;

    const float* f1w = ff1w + (size_t)l * FFD * OC;
    const float* f1b = ff1b + (size_t)l * FFD;
    const float* f2w = ff2w + (size_t)l * OC * FFD;

    // transpose E tile into smem: sEt[c][tok]
    for (int i = t; i < TB * 64; i += 256) {
        int tk = i >> 6, c = i & 63;
        sEt[c * 132 + tk] = g_e[tok0 * 64 + i];
    }

    // GEMM1 mapping
    int jg1 = t >> 4;        // 16 groups of 8 j
    int pg1 = t & 15;        // pairs pg1 + 16p
    // GEMM2 mapping
    int ks  = t >> 7;        // warp-uniform k-split
    int cg  = (t >> 4) & 7;  // 8 groups of 8 c
    int pg2 = t & 15;        // pairs pg2 + 16p

    ull o2[8][4];
    #pragma unroll
    for (int cc = 0; cc < 8; cc++)
        #pragma unroll
        for (int p = 0; p < 4; p++) o2[cc][p] = 0ull;

    for (int ch = 0; ch < 16; ch++) {
        __syncthreads();
        int jb = ch * 128;
        for (int i = t; i < 8192; i += 256) {
            int jl = i >> 6, k = i & 63;
            sW1[jl * 65 + k] = f1w[(size_t)(jb + jl) * 64 + k];
        }
        for (int i = t; i < 8192; i += 256) {
            int c = i >> 7, jl = i & 127;
            sW2[c * 130 + jl] = f2w[(size_t)c * FFD + jb + jl];
        }
        if (t < 128) sB1[t] = f1b[jb + t];
        __syncthreads();

        // GEMM1: H = relu(E @ W1^T + b1)
        ull a1[8][4];
        #pragma unroll
        for (int jj = 0; jj < 8; jj++) {
            ull b = splat2(sB1[jg1 * 8 + jj]);
            #pragma unroll
            for (int p = 0; p < 4; p++) a1[jj][p] = b;
        }
        #pragma unroll 2
        for (int k = 0; k < 64; k++) {
            const ull* er = (const ull*)(sEt + k * 132);
            ull e0 = er[pg1], e1 = er[pg1 + 16], e2v = er[pg1 + 32], e3v = er[pg1 + 48];
            const float* wr = sW1 + k;
            #pragma unroll
            for (int jj = 0; jj < 8; jj++) {
                ull wv = splat2(wr[(jg1 * 8 + jj) * 65]);
                a1[jj][0] = fma2(e0,  wv, a1[jj][0]);
                a1[jj][1] = fma2(e1,  wv, a1[jj][1]);
                a1[jj][2] = fma2(e2v, wv, a1[jj][2]);
                a1[jj][3] = fma2(e3v, wv, a1[jj][3]);
            }
        }
        #pragma unroll
        for (int jj = 0; jj < 8; jj++) {
            ull* hr = (ull*)(sHt + (jg1 * 8 + jj) * 132);
            #pragma unroll
            for (int p = 0; p < 4; p++) {
                float2 f = u2f(a1[jj][p]);
                hr[pg1 + 16 * p] = f2u(fmaxf(f.x, 0.f), fmaxf(f.y, 0.f));
            }
        }
        __syncthreads();

        // GEMM2: O += H @ W2^T (k-split by warp-half)
        #pragma unroll 2
        for (int q = 0; q < 64; q++) {
            int jl = ks * 64 + q;
            const ull* hr = (const ull*)(sHt + jl * 132);
            ull h0 = hr[pg2], h1 = hr[pg2 + 16], h2 = hr[pg2 + 32], h3 = hr[pg2 + 48];
            const float* wr = sW2 + jl;
            #pragma unroll
            for (int cc = 0; cc < 8; cc++) {
                ull wv = splat2(wr[(cg * 8 + cc) * 130]);
                o2[cc][0] = fma2(h0, wv, o2[cc][0]);
                o2[cc][1] = fma2(h1, wv, o2[cc][1]);
                o2[cc][2] = fma2(h2, wv, o2[cc][2]);
                o2[cc][3] = fma2(h3, wv, o2[cc][3]);
            }
        }
    }

    // ---- epilogue: ksplit reduce, bias, residual, LN2 ----
    __syncthreads();
    if (ks == 1) {
        ull* r = (ull*)sRed;
        #pragma unroll
        for (int cc = 0; cc < 8; cc++)
            #pragma unroll
            for (int p = 0; p < 4; p++)
                r[(cg * 8 + cc) * 64 + pg2 + 16 * p] = o2[cc][p];
    }
    __syncthreads();
    if (ks == 0) {
        const ull* r = (const ull*)sRed;
        #pragma unroll
        for (int cc = 0; cc < 8; cc++) {
            int c = cg * 8 + cc;
            float bias = ff2b[l * OC + c];
            #pragma unroll
            for (int p = 0; p < 4; p++) {
                float2 a = u2f(o2[cc][p]);
                float2 bb = u2f(r[c * 64 + pg2 + 16 * p]);
                int tk = 2 * (pg2 + 16 * p);
                sO[tk * 65 + c]       = a.x + bb.x + bias + sEt[c * 132 + tk];
                sO[(tk + 1) * 65 + c] = a.y + bb.y + bias + sEt[c * 132 + tk + 1];
            }
        }
    }
    __syncthreads();

    // LN2: 2 threads per token
    int tk2 = t >> 1, half = t & 1;
    const float* ob = sO + tk2 * 65 + half * 32;
    float s = 0.f, s2 = 0.f;
    #pragma unroll
    for (int i = 0; i < 32; i++) { float v = ob[i]; s += v; s2 += v * v; }
    s  += __shfl_xor_sync(0xffffffffu, s, 1);
    s2 += __shfl_xor_sync(0xffffffffu, s2, 1);
    float mu   = s * (1.f / 64.f);
    float rstd = rsqrtf(s2 * (1.f / 64.f) - mu * mu + LN_EPS);
    float* go = g_e + (tok0 + tk2) * 64 + half * 32;
    #pragma unroll
    for (int i = 0; i < 32; i++) {
        int c = half * 32 + i;
        go[i] = (ob[i] - mu) * rstd * g2[l * OC + c] + b2[l * OC + c];
    }
}

// =====================================================================
// K5: head
// =====================================================================
__global__ void __launch_bounds__(256) k_head(
    const float* __restrict__ r1w, const float* __restrict__ r1b,
    const float* __restrict__ r2w, const float* __restrict__ r2b,
    float* __restrict__ out)
{
    __shared__ float sR1T[64 * 65];
    __shared__ float sR2[64];
    __shared__ float sP[8][64];
    int t = threadIdx.x;
    for (int i = t; i < 4096; i += 256) {
        int c = i >> 6, k = i & 63;
        sR1T[k * 65 + c] = r1w[c * 64 + k];
    }
    if (t < 64) sR2[t] = r2w[t];
    __syncthreads();
    int w = t >> 5, lane = t & 31;
    int n = blockIdx.x * 8 + w;
    const float* eb = g_e + (size_t)n * 256;
    float p0 = (eb[lane] + eb[64 + lane] + eb[128 + lane] + eb[192 + lane]) * 0.25f;
    float p1 = (eb[32 + lane] + eb[96 + lane] + eb[160 + lane] + eb[224 + lane]) * 0.25f;
    sP[w][lane]      = p0;
    sP[w][lane + 32] = p1;
    __syncwarp();
    float a0 = r1b[lane], a1 = r1b[lane + 32];
    #pragma unroll 8
    for (int k = 0; k < 64; k++) {
        float pv = sP[w][k];
        a0 = fmaf(pv, sR1T[k * 65 + lane], a0);
        a1 = fmaf(pv, sR1T[k * 65 + lane + 32], a1);
    }
    a0 = fmaxf(a0, 0.f); a1 = fmaxf(a1, 0.f);
    float acc = a0 * sR2[lane] + a1 * sR2[lane + 32];
    #pragma unroll
    for (int off = 16; off; off >>= 1) acc += __shfl_xor_sync(0xffffffffu, acc, off);
    if (lane == 0) out[n] = acc + r2b[0];
}

// =====================================================================
extern "C" void kernel_launch(void* const* d_in, const int* in_sizes, int n_in,
                              void* d_out, int out_size) {
    const float* x    = (const float*)d_in[0];
    const int*   ei   = (const int*)  d_in[1];
    const float* mpw  = (const float*)d_in[2];
    const float* W0   = (const float*)d_in[3];
    const float* b0   = (const float*)d_in[4];
    const float* Wl   = (const float*)d_in[5];
    const float* bl   = (const float*)d_in[6];
    const float* W1   = (const float*)d_in[7];
    const float* b1   = (const float*)d_in[8];
    const float* Wo   = (const float*)d_in[9];
    const float* bo   = (const float*)d_in[10];
    const float* tinw = (const float*)d_in[11];
    const float* tinb = (const float*)d_in[12];
    const float* tow  = (const float*)d_in[13];
    const float* tob  = (const float*)d_in[14];
    const float* ln1g = (const float*)d_in[15];
    const float* ln1b = (const float*)d_in[16];
    const float* ff1w = (const float*)d_in[17];
    const float* ff1b = (const float*)d_in[18];
    const float* ff2w = (const float*)d_in[19];
    const float* ff2b = (const float*)d_in[20];
    const float* ln2g = (const float*)d_in[21];
    const float* ln2b = (const float*)d_in[22];
    const float* r1w  = (const float*)d_in[23];
    const float* r1b  = (const float*)d_in[24];
    const float* r2w  = (const float*)d_in[25];
    const float* r2b  = (const float*)d_in[26];
    float* out = (float*)d_out;
    (void)in_sizes; (void)n_in; (void)out_size;

    cudaFuncSetAttribute(k_gnn,  cudaFuncAttributeMaxDynamicSharedMemorySize, 23488 * 4);
    cudaFuncSetAttribute(k_attn, cudaFuncAttributeMaxDynamicSharedMemorySize, 27008 * 4);
    cudaFuncSetAttribute(k_ff,   cudaFuncAttributeMaxDynamicSharedMemorySize, 42112 * 4);

    k_zero<<<15000, 256>>>();
    k_scatter<<<240000, 256>>>(x, ei);
    dim3 gg(235, 4);
    k_gnn<<<gg, 256, 23488 * 4>>>(x, W0, b0, Wl, bl, W1, b1, Wo, bo, mpw);
    for (int l = 0; l < 2; l++) {
        k_attn<<<3750, 512, 27008 * 4>>>(tinw, tinb, tow, tob, ln1g, ln1b, l);
        k_ff<<<NBLK, 256, 42112 * 4>>>(ff1w, ff1b, ff2w, ff2b, ln2g, ln2b, l);
    }
    k_head<<<3750, 256>>>(r1w, r1b, r2w, r2b, out);
}

// round 4
// speedup vs baseline: 1.4144x; 1.0356x over previous
#include <cuda_runtime.h>
#include <cstdint>

typedef unsigned long long ull;

#define NN   30000
#define INC  128
#define OC   64
#define MP   4
#define EE   480000
#define FFD  2048
#define TOK  (NN*MP)
#define TB   128
#define NBLK ((TOK + TB - 1) / TB)   // 938
#define TOKP (NBLK * TB)             // 120064 (padded)
#define LN_EPS 1e-5f

// ---- device scratch (allocation-free rule: __device__ globals) ----
__device__ float g_y[(size_t)MP * NN * OC];     // x @ Wl^T          (30.7 MB)
__device__ float g_c[(size_t)MP * NN * OC];     // x @ Wc^T + bias   (30.7 MB)
__device__ float g_aggY[(size_t)MP * NN * OC];  // scatter target    (30.7 MB)
__device__ float g_e[(size_t)TOKP * OC];        // token embeddings  (30.7 MB)

// ---- packed fp32x2 helpers (exact fp32 semantics) ----
__device__ __forceinline__ ull fma2(ull a, ull b, ull c) {
    ull d; asm("fma.rn.f32x2 %0, %1, %2, %3;" : "=l"(d) : "l"(a), "l"(b), "l"(c)); return d;
}
__device__ __forceinline__ ull splat2(float x) {
    ull v; asm("mov.b64 %0, {%1, %1};" : "=l"(v) : "f"(x)); return v;
}
__device__ __forceinline__ float2 u2f(ull v) {
    float2 f; asm("mov.b64 {%0, %1}, %2;" : "=f"(f.x), "=f"(f.y) : "l"(v)); return f;
}
__device__ __forceinline__ ull f2u(float x, float y) {
    ull v; asm("mov.b64 %0, {%1, %2};" : "=l"(v) : "f"(x), "f"(y)); return v;
}

// =====================================================================
// K_xw: y[m] = x @ Wl[m]^T ; c[m] = x @ (W0[m]+W1[m])^T + (b0+bl+b1)
// blockIdx.y = metapath, warp per node, fma2-paired output channels.
// =====================================================================
__global__ void __launch_bounds__(256, 1) k_xw(
    const float* __restrict__ x,
    const float* __restrict__ W0, const float* __restrict__ b0,
    const float* __restrict__ Wl, const float* __restrict__ bl,
    const float* __restrict__ W1, const float* __restrict__ b1)
{
    extern __shared__ float sm[];
    float* sWlT = sm;            // [128 k][66]
    float* sWcT = sm + 8448;     // [128 k][66]
    float* sB   = sm + 16896;    // 64
    float* sRow = sm + 16960;    // 8 warps * 128
    int t = threadIdx.x;
    int m = blockIdx.y;

    for (int i = t; i < 8192; i += 256) {
        int j = i >> 7, k = i & 127;
        size_t off = (size_t)m * 8192 + (size_t)j * 128 + k;
        sWlT[k * 66 + j] = Wl[off];
        sWcT[k * 66 + j] = W0[off] + W1[off];
    }
    if (t < 64) sB[t] = bl[m * 64 + t] + b0[m * 64 + t] + b1[m * 64 + t];
    __syncthreads();

    int w = t >> 5, lane = t & 31;
    float* row = sRow + w * 128;

    for (int n = blockIdx.x * 8 + w; n < NN; n += gridDim.x * 8) {
        ((float4*)row)[lane] = ((const float4*)(x + (size_t)n * INC))[lane];
        __syncwarp();
        ull ay = 0ull;
        ull ac = f2u(sB[2 * lane], sB[2 * lane + 1]);
        #pragma unroll 4
        for (int k = 0; k < 128; k++) {
            ull xv = splat2(row[k]);
            ull wl = *(const ull*)(sWlT + k * 66 + 2 * lane);
            ull wc = *(const ull*)(sWcT + k * 66 + 2 * lane);
            ay = fma2(wl, xv, ay);
            ac = fma2(wc, xv, ac);
        }
        size_t base = ((size_t)m * NN + n) * OC;
        *(float2*)(g_y + base + 2 * lane) = u2f(ay);
        *(float2*)(g_c + base + 2 * lane) = u2f(ac);
        __syncwarp();
    }
}

// =====================================================================
// K0: zero aggY buffer (7.68M floats)
// =====================================================================
__global__ void k_zero() {
    size_t i = (size_t)blockIdx.x * 256 + threadIdx.x;
    ((float4*)g_aggY)[i] = make_float4(0.f, 0.f, 0.f, 0.f);
}

// =====================================================================
// K1: edge scatter: aggY[m][src] += y[m][dst].  half-warp per edge (64 floats).
// =====================================================================
__global__ void k_scatter(const int* __restrict__ ei) {
    int wid  = (blockIdx.x * blockDim.x + threadIdx.x) >> 5;
    int lane = threadIdx.x & 31;
    int pair = lane >> 4;        // which of 2 edges this half-warp handles
    int sub  = lane & 15;        // float4 slot within 64-float row
    int eg = wid * 2 + pair;     // global edge id, 0..MP*EE-1
    int m = eg / EE;
    int e = eg - m * EE;
    const int* b = ei + (size_t)m * 2 * EE;
    int src = __ldg(b + e);
    int dst = __ldg(b + EE + e);
    float4 v = ((const float4*)(g_y + ((size_t)m * NN + dst) * OC))[sub];
    atomicAdd(((float4*)(g_aggY + ((size_t)m * NN + src) * OC)) + sub, v);
}

// =====================================================================
// K2: per-metapath GNN tail: h = relu(aggY + c); e_m = (h@Wo^T + bo)*mpw
// =====================================================================
__global__ void __launch_bounds__(256, 1) k_gnn(
    const float* __restrict__ Wo, const float* __restrict__ bo,
    const float* __restrict__ mpw)
{
    __shared__ float sWoT[64 * 66];   // [64 i][66]
    __shared__ float sBo[64];
    __shared__ float sH[8 * 64];
    int t = threadIdx.x;
    int m = blockIdx.y;

    for (int i = t; i < 4096; i += 256) {
        int j = i >> 6, k = i & 63;
        sWoT[k * 66 + j] = Wo[(size_t)m * 4096 + j * 64 + k];
    }
    if (t < 64) sBo[t] = bo[m * 64 + t];
    __syncthreads();

    float wgt = mpw[m];
    int w = t >> 5, lane = t & 31;
    float* hrow = sH + w * 64;

    for (int n = blockIdx.x * 8 + w; n < NN; n += gridDim.x * 8) {
        size_t base = ((size_t)m * NN + n) * OC;
        hrow[lane]      = fmaxf(g_aggY[base + lane]      + g_c[base + lane], 0.f);
        hrow[lane + 32] = fmaxf(g_aggY[base + lane + 32] + g_c[base + lane + 32], 0.f);
        __syncwarp();
        ull o = f2u(sBo[2 * lane], sBo[2 * lane + 1]);
        #pragma unroll 8
        for (int i = 0; i < 64; i++) {
            o = fma2(*(const ull*)(sWoT + i * 66 + 2 * lane), splat2(hrow[i]), o);
        }
        float2 f = u2f(o);
        *(float2*)(g_e + ((size_t)n * MP + m) * OC + 2 * lane) =
            make_float2(f.x * wgt, f.y * wgt);
        __syncwarp();
    }
}

// =====================================================================
// K3: attention sublayer, 8 nodes per block (512 threads)
// =====================================================================
__global__ void __launch_bounds__(512, 1) k_attn(
    const float* __restrict__ tinw, const float* __restrict__ tinb,
    const float* __restrict__ tow,  const float* __restrict__ tob,
    const float* __restrict__ g1,   const float* __restrict__ b1v, int l)
{
    extern __shared__ float sm[];
    float* sTinT = sm;           // [64 k][193]
    float* sTowT = sm + 12352;   // [64 i][65]
    float* sTinB = sm + 16512;   // 192
    float* sToB  = sm + 16704;   // 64
    float* sE    = sm + 16768;   // 8 * 256
    float* sQKV  = sm + 18816;   // 8 * 768
    float* sAO   = sm + 24960;   // 8 * 256
    int t = threadIdx.x;

    const float* tw = tinw + (size_t)l * 192 * 64;
    for (int i = t; i < 12288; i += 512) {
        int r = i >> 6, k = i & 63;
        sTinT[k * 193 + r] = tw[r * 64 + k];
    }
    const float* twO = tow + (size_t)l * 64 * 64;
    for (int i = t; i < 4096; i += 512) {
        int j = i >> 6, k = i & 63;
        sTowT[k * 65 + j] = twO[j * 64 + k];
    }
    if (t < 192) sTinB[t] = tinb[l * 192 + t];
    if (t >= 192 && t < 256) sToB[t - 192] = tob[l * 64 + (t - 192)];

    int s = t >> 6, tt = t & 63;
    int node = blockIdx.x * 8 + s;
    float* eN   = sE + s * 256;
    float* qkvN = sQKV + s * 768;
    float* aoN  = sAO + s * 256;
    for (int i = tt; i < 256; i += 64) eN[i] = g_e[(size_t)node * 256 + i];
    __syncthreads();

    // qkv
    {
        float aq[4], ak[4], av[4];
        #pragma unroll
        for (int m2 = 0; m2 < 4; m2++) {
            aq[m2] = sTinB[tt]; ak[m2] = sTinB[64 + tt]; av[m2] = sTinB[128 + tt];
        }
        #pragma unroll 2
        for (int k = 0; k < 64; k++) {
            float wq = sTinT[k * 193 + tt];
            float wk = sTinT[k * 193 + 64 + tt];
            float wv = sTinT[k * 193 + 128 + tt];
            #pragma unroll
            for (int m2 = 0; m2 < 4; m2++) {
                float ev = eN[m2 * 64 + k];
                aq[m2] = fmaf(ev, wq, aq[m2]);
                ak[m2] = fmaf(ev, wk, ak[m2]);
                av[m2] = fmaf(ev, wv, av[m2]);
            }
        }
        #pragma unroll
        for (int m2 = 0; m2 < 4; m2++) {
            qkvN[m2 * 192 + tt]       = aq[m2];
            qkvN[m2 * 192 + 64 + tt]  = ak[m2];
            qkvN[m2 * 192 + 128 + tt] = av[m2];
        }
    }
    __syncthreads();

    // attention core: 32 threads per node group
    if (tt < 32) {
        int h = tt >> 2, mq = tt & 3;
        float q[8];
        #pragma unroll
        for (int d = 0; d < 8; d++) q[d] = qkvN[mq * 192 + h * 8 + d];
        float sc[4];
        #pragma unroll
        for (int mk = 0; mk < 4; mk++) {
            float a = 0.f;
            #pragma unroll
            for (int d = 0; d < 8; d++) a = fmaf(q[d], qkvN[mk * 192 + 64 + h * 8 + d], a);
            sc[mk] = a * 0.35355339059327373f;
        }
        float mx = fmaxf(fmaxf(sc[0], sc[1]), fmaxf(sc[2], sc[3]));
        float p[4]; float psum = 0.f;
        #pragma unroll
        for (int mk = 0; mk < 4; mk++) { p[mk] = __expf(sc[mk] - mx); psum += p[mk]; }
        float inv = 1.0f / psum;
        #pragma unroll
        for (int d = 0; d < 8; d++) {
            float o = 0.f;
            #pragma unroll
            for (int mk = 0; mk < 4; mk++) o = fmaf(p[mk] * inv, qkvN[mk * 192 + 128 + h * 8 + d], o);
            aoN[mq * 64 + h * 8 + d] = o;
        }
    }
    __syncthreads();

    // proj + residual (channel = tt)
    {
        float acc[4];
        #pragma unroll
        for (int m2 = 0; m2 < 4; m2++) acc[m2] = sToB[tt];
        #pragma unroll 4
        for (int i = 0; i < 64; i++) {
            float wv = sTowT[i * 65 + tt];
            #pragma unroll
            for (int m2 = 0; m2 < 4; m2++) acc[m2] = fmaf(aoN[m2 * 64 + i], wv, acc[m2]);
        }
        #pragma unroll
        for (int m2 = 0; m2 < 4; m2++) eN[m2 * 64 + tt] += acc[m2];
    }
    __syncthreads();

    // LN1: 32 tokens/block; 16 threads each cover 4 channels
    int tl = t >> 4, part = t & 15;
    int ss = tl >> 2, m2 = tl & 3;
    const float* base = sE + ss * 256 + m2 * 64;
    float sum = 0.f, sq = 0.f;
    #pragma unroll
    for (int i2 = 0; i2 < 4; i2++) { float v = base[part * 4 + i2]; sum += v; sq += v * v; }
    #pragma unroll
    for (int off = 1; off < 16; off <<= 1) {
        sum += __shfl_xor_sync(0xffffffffu, sum, off);
        sq  += __shfl_xor_sync(0xffffffffu, sq,  off);
    }
    float mu   = sum * (1.f / 64.f);
    float rstd = rsqrtf(sq * (1.f / 64.f) - mu * mu + LN_EPS);
    int nodeW = blockIdx.x * 8 + ss;
    #pragma unroll
    for (int i2 = 0; i2 < 4; i2++) {
        int c = part * 4 + i2;
        float v = base[c];
        g_e[((size_t)nodeW * 4 + m2) * 64 + c] = (v - mu) * rstd * g1[l * 64 + c] + b1v[l * 64 + c];
    }
}

// =====================================================================
// K4: FF sublayer (64->2048->relu->64) + residual + LN2.
// =====================================================================
__global__ void __launch_bounds__(256, 1) k_ff(
    const float* __restrict__ ff1w, const float* __restrict__ ff1b,
    const float* __restrict__ ff2w, const float* __restrict__ ff2b,
    const float* __restrict__ g2,   const float* __restrict__ b2, int l)
{
    extern __shared__ float sm[];
    float* sEt = sm;             // [64 c][132]
    float* sHt = sm + 8448;      // [128 j][132]
    float* sW1 = sm + 25344;     // [128 j][65]
    float* sW2 = sm + 33664;     // [64 c][130]
    float* sB1 = sm + 41984;     // 128
    float* sRed = sW1;           // alias (epilogue)
    float* sO   = sW2;           // alias (epilogue) [128 tok][65]
    int t = threadIdx.x;
    size_t tok0 = (size_t)blockIdx.x * TB;

    const float* f1w = ff1w + (size_t)l * FFD * OC;
    const float* f1b = ff1b + (size_t)l * FFD;
    const float* f2w = ff2w + (size_t)l * OC * FFD;

    for (int i = t; i < TB * 64; i += 256) {
        int tk = i >> 6, c = i & 63;
        sEt[c * 132 + tk] = g_e[tok0 * 64 + i];
    }

    int jg1 = t >> 4;
    int pg1 = t & 15;
    int ks  = t >> 7;
    int cg  = (t >> 4) & 7;
    int pg2 = t & 15;

    ull o2[8][4];
    #pragma unroll
    for (int cc = 0; cc < 8; cc++)
        #pragma unroll
        for (int p = 0; p < 4; p++) o2[cc][p] = 0ull;

    for (int ch = 0; ch < 16; ch++) {
        __syncthreads();
        int jb = ch * 128;
        for (int i = t; i < 8192; i += 256) {
            int jl = i >> 6, k = i & 63;
            sW1[jl * 65 + k] = f1w[(size_t)(jb + jl) * 64 + k];
        }
        for (int i = t; i < 8192; i += 256) {
            int c = i >> 7, jl = i & 127;
            sW2[c * 130 + jl] = f2w[(size_t)c * FFD + jb + jl];
        }
        if (t < 128) sB1[t] = f1b[jb + t];
        __syncthreads();

        // GEMM1: H = relu(E @ W1^T + b1)
        ull a1[8][4];
        #pragma unroll
        for (int jj = 0; jj < 8; jj++) {
            ull b = splat2(sB1[jg1 * 8 + jj]);
            #pragma unroll
            for (int p = 0; p < 4; p++) a1[jj][p] = b;
        }
        #pragma unroll 2
        for (int k = 0; k < 64; k++) {
            const ull* er = (const ull*)(sEt + k * 132);
            ull e0 = er[pg1], e1 = er[pg1 + 16], e2v = er[pg1 + 32], e3v = er[pg1 + 48];
            const float* wr = sW1 + k;
            #pragma unroll
            for (int jj = 0; jj < 8; jj++) {
                ull wv = splat2(wr[(jg1 * 8 + jj) * 65]);
                a1[jj][0] = fma2(e0,  wv, a1[jj][0]);
                a1[jj][1] = fma2(e1,  wv, a1[jj][1]);
                a1[jj][2] = fma2(e2v, wv, a1[jj][2]);
                a1[jj][3] = fma2(e3v, wv, a1[jj][3]);
            }
        }
        #pragma unroll
        for (int jj = 0; jj < 8; jj++) {
            ull* hr = (ull*)(sHt + (jg1 * 8 + jj) * 132);
            #pragma unroll
            for (int p = 0; p < 4; p++) {
                float2 f = u2f(a1[jj][p]);
                hr[pg1 + 16 * p] = f2u(fmaxf(f.x, 0.f), fmaxf(f.y, 0.f));
            }
        }
        __syncthreads();

        // GEMM2: O += H @ W2^T (k-split by warp-half)
        #pragma unroll 2
        for (int q = 0; q < 64; q++) {
            int jl = ks * 64 + q;
            const ull* hr = (const ull*)(sHt + jl * 132);
            ull h0 = hr[pg2], h1 = hr[pg2 + 16], h2 = hr[pg2 + 32], h3 = hr[pg2 + 48];
            const float* wr = sW2 + jl;
            #pragma unroll
            for (int cc = 0; cc < 8; cc++) {
                ull wv = splat2(wr[(cg * 8 + cc) * 130]);
                o2[cc][0] = fma2(h0, wv, o2[cc][0]);
                o2[cc][1] = fma2(h1, wv, o2[cc][1]);
                o2[cc][2] = fma2(h2, wv, o2[cc][2]);
                o2[cc][3] = fma2(h3, wv, o2[cc][3]);
            }
        }
    }

    // ---- epilogue: ksplit reduce, bias, residual, LN2 ----
    __syncthreads();
    if (ks == 1) {
        ull* r = (ull*)sRed;
        #pragma unroll
        for (int cc = 0; cc < 8; cc++)
            #pragma unroll
            for (int p = 0; p < 4; p++)
                r[(cg * 8 + cc) * 64 + pg2 + 16 * p] = o2[cc][p];
    }
    __syncthreads();
    if (ks == 0) {
        const ull* r = (const ull*)sRed;
        #pragma unroll
        for (int cc = 0; cc < 8; cc++) {
            int c = cg * 8 + cc;
            float bias = ff2b[l * OC + c];
            #pragma unroll
            for (int p = 0; p < 4; p++) {
                float2 a = u2f(o2[cc][p]);
                float2 bb = u2f(r[c * 64 + pg2 + 16 * p]);
                int tk = 2 * (pg2 + 16 * p);
                sO[tk * 65 + c]       = a.x + bb.x + bias + sEt[c * 132 + tk];
                sO[(tk + 1) * 65 + c] = a.y + bb.y + bias + sEt[c * 132 + tk + 1];
            }
        }
    }
    __syncthreads();

    // LN2: 2 threads per token
    int tk2 = t >> 1, half = t & 1;
    const float* ob = sO + tk2 * 65 + half * 32;
    float s = 0.f, s2 = 0.f;
    #pragma unroll
    for (int i = 0; i < 32; i++) { float v = ob[i]; s += v; s2 += v * v; }
    s  += __shfl_xor_sync(0xffffffffu, s, 1);
    s2 += __shfl_xor_sync(0xffffffffu, s2, 1);
    float mu   = s * (1.f / 64.f);
    float rstd = rsqrtf(s2 * (1.f / 64.f) - mu * mu + LN_EPS);
    float* go = g_e + (tok0 + tk2) * 64 + half * 32;
    #pragma unroll
    for (int i = 0; i < 32; i++) {
        int c = half * 32 + i;
        go[i] = (ob[i] - mu) * rstd * g2[l * OC + c] + b2[l * OC + c];
    }
}

// =====================================================================
// K5: head
// =====================================================================
__global__ void __launch_bounds__(256) k_head(
    const float* __restrict__ r1w, const float* __restrict__ r1b,
    const float* __restrict__ r2w, const float* __restrict__ r2b,
    float* __restrict__ out)
{
    __shared__ float sR1T[64 * 65];
    __shared__ float sR2[64];
    __shared__ float sP[8][64];
    int t = threadIdx.x;
    for (int i = t; i < 4096; i += 256) {
        int c = i >> 6, k = i & 63;
        sR1T[k * 65 + c] = r1w[c * 64 + k];
    }
    if (t < 64) sR2[t] = r2w[t];
    __syncthreads();
    int w = t >> 5, lane = t & 31;
    int n = blockIdx.x * 8 + w;
    const float* eb = g_e + (size_t)n * 256;
    float p0 = (eb[lane] + eb[64 + lane] + eb[128 + lane] + eb[192 + lane]) * 0.25f;
    float p1 = (eb[32 + lane] + eb[96 + lane] + eb[160 + lane] + eb[224 + lane]) * 0.25f;
    sP[w][lane]      = p0;
    sP[w][lane + 32] = p1;
    __syncwarp();
    float a0 = r1b[lane], a1 = r1b[lane + 32];
    #pragma unroll 8
    for (int k = 0; k < 64; k++) {
        float pv = sP[w][k];
        a0 = fmaf(pv, sR1T[k * 65 + lane], a0);
        a1 = fmaf(pv, sR1T[k * 65 + lane + 32], a1);
    }
    a0 = fmaxf(a0, 0.f); a1 = fmaxf(a1, 0.f);
    float acc = a0 * sR2[lane] + a1 * sR2[lane + 32];
    #pragma unroll
    for (int off = 16; off; off >>= 1) acc += __shfl_xor_sync(0xffffffffu, acc, off);
    if (lane == 0) out[n] = acc + r2b[0];
}

// =====================================================================
extern "C" void kernel_launch(void* const* d_in, const int* in_sizes, int n_in,
                              void* d_out, int out_size) {
    const float* x    = (const float*)d_in[0];
    const int*   ei   = (const int*)  d_in[1];
    const float* mpw  = (const float*)d_in[2];
    const float* W0   = (const float*)d_in[3];
    const float* b0   = (const float*)d_in[4];
    const float* Wl   = (const float*)d_in[5];
    const float* bl   = (const float*)d_in[6];
    const float* W1   = (const float*)d_in[7];
    const float* b1   = (const float*)d_in[8];
    const float* Wo   = (const float*)d_in[9];
    const float* bo   = (const float*)d_in[10];
    const float* tinw = (const float*)d_in[11];
    const float* tinb = (const float*)d_in[12];
    const float* tow  = (const float*)d_in[13];
    const float* tob  = (const float*)d_in[14];
    const float* ln1g = (const float*)d_in[15];
    const float* ln1b = (const float*)d_in[16];
    const float* ff1w = (const float*)d_in[17];
    const float* ff1b = (const float*)d_in[18];
    const float* ff2w = (const float*)d_in[19];
    const float* ff2b = (const float*)d_in[20];
    const float* ln2g = (const float*)d_in[21];
    const float* ln2b = (const float*)d_in[22];
    const float* r1w  = (const float*)d_in[23];
    const float* r1b  = (const float*)d_in[24];
    const float* r2w  = (const float*)d_in[25];
    const float* r2b  = (const float*)d_in[26];
    float* out = (float*)d_out;
    (void)in_sizes; (void)n_in; (void)out_size;

    cudaFuncSetAttribute(k_xw,   cudaFuncAttributeMaxDynamicSharedMemorySize, 17984 * 4);
    cudaFuncSetAttribute(k_attn, cudaFuncAttributeMaxDynamicSharedMemorySize, 27008 * 4);
    cudaFuncSetAttribute(k_ff,   cudaFuncAttributeMaxDynamicSharedMemorySize, 42112 * 4);

    // launch order chosen so ncu (-s 5 -c 1) captures k_ff (6th launch)
    dim3 gx(469, 4);
    k_xw<<<gx, 256, 17984 * 4>>>(x, W0, b0, Wl, bl, W1, b1);          // 1
    k_zero<<<7500, 256>>>();                                          // 2
    k_scatter<<<120000, 256>>>(ei);                                   // 3
    k_gnn<<<gx, 256>>>(Wo, bo, mpw);                                  // 4
    k_attn<<<3750, 512, 27008 * 4>>>(tinw, tinb, tow, tob, ln1g, ln1b, 0);   // 5
    k_ff<<<NBLK, 256, 42112 * 4>>>(ff1w, ff1b, ff2w, ff2b, ln2g, ln2b, 0);   // 6 <- ncu
    k_attn<<<3750, 512, 27008 * 4>>>(tinw, tinb, tow, tob, ln1g, ln1b, 1);
    k_ff<<<NBLK, 256, 42112 * 4>>>(ff1w, ff1b, ff2w, ff2b, ln2g, ln2b, 1);
    k_head<<<3750, 256>>>(r1w, r1b, r2w, r2b, out);
}

// round 5
// speedup vs baseline: 2.4726x; 1.7482x over previous
#include <cuda_runtime.h>
#include <cstdint>

typedef unsigned long long ull;

#define NN   30000
#define INC  128
#define OC   64
#define MP   4
#define EE   480000
#define FFD  2048
#define TOK  (NN*MP)
#define TB   128
#define NBLK ((TOK + TB - 1) / TB)   // 938
#define TOKP (NBLK * TB)             // 120064 (padded)
#define LN_EPS 1e-5f

// ---- device scratch (allocation-free rule: __device__ globals) ----
__device__ float g_y[(size_t)MP * NN * OC];     // x @ Wl^T
__device__ float g_c[(size_t)MP * NN * OC];     // x @ Wc^T + bias
__device__ float g_aggY[(size_t)MP * NN * OC];  // scatter target
__device__ float g_e[(size_t)TOKP * OC];        // token embeddings

// ---- packed fp32x2 helpers (exact fp32 semantics) ----
__device__ __forceinline__ ull fma2(ull a, ull b, ull c) {
    ull d; asm("fma.rn.f32x2 %0, %1, %2, %3;" : "=l"(d) : "l"(a), "l"(b), "l"(c)); return d;
}
__device__ __forceinline__ ull splat2(float x) {
    ull v; asm("mov.b64 %0, {%1, %1};" : "=l"(v) : "f"(x)); return v;
}
__device__ __forceinline__ float2 u2f(ull v) {
    float2 f; asm("mov.b64 {%0, %1}, %2;" : "=f"(f.x), "=f"(f.y) : "l"(v)); return f;
}
__device__ __forceinline__ ull f2u(float x, float y) {
    ull v; asm("mov.b64 %0, {%1, %2};" : "=l"(v) : "f"(x), "f"(y)); return v;
}

// ---- tf32 mma helpers ----
__device__ __forceinline__ float tf32r(float f) {
    unsigned u; asm("cvt.rna.tf32.f32 %0, %1;" : "=r"(u) : "f"(f));
    return __uint_as_float(u);
}
__device__ __forceinline__ void mma_tf32(float* c, const unsigned* a, const unsigned* b) {
    asm volatile(
        "mma.sync.aligned.m16n8k8.row.col.f32.tf32.tf32.f32 "
        "{%0,%1,%2,%3}, {%4,%5,%6,%7}, {%8,%9}, {%0,%1,%2,%3};"
        : "+f"(c[0]), "+f"(c[1]), "+f"(c[2]), "+f"(c[3])
        : "r"(a[0]), "r"(a[1]), "r"(a[2]), "r"(a[3]), "r"(b[0]), "r"(b[1]));
}

// =====================================================================
// K_xw: y[m] = x @ Wl[m]^T ; c[m] = x @ (W0[m]+W1[m])^T + bias
// =====================================================================
__global__ void __launch_bounds__(256, 1) k_xw(
    const float* __restrict__ x,
    const float* __restrict__ W0, const float* __restrict__ b0,
    const float* __restrict__ Wl, const float* __restrict__ bl,
    const float* __restrict__ W1, const float* __restrict__ b1)
{
    extern __shared__ float sm[];
    float* sWlT = sm;            // [128 k][66]
    float* sWcT = sm + 8448;     // [128 k][66]
    float* sB   = sm + 16896;    // 64
    float* sRow = sm + 16960;    // 8 warps * 128
    int t = threadIdx.x;
    int m = blockIdx.y;

    for (int i = t; i < 8192; i += 256) {
        int j = i >> 7, k = i & 127;
        size_t off = (size_t)m * 8192 + (size_t)j * 128 + k;
        sWlT[k * 66 + j] = Wl[off];
        sWcT[k * 66 + j] = W0[off] + W1[off];
    }
    if (t < 64) sB[t] = bl[m * 64 + t] + b0[m * 64 + t] + b1[m * 64 + t];
    __syncthreads();

    int w = t >> 5, lane = t & 31;
    float* row = sRow + w * 128;

    for (int n = blockIdx.x * 8 + w; n < NN; n += gridDim.x * 8) {
        ((float4*)row)[lane] = ((const float4*)(x + (size_t)n * INC))[lane];
        __syncwarp();
        ull ay = 0ull;
        ull ac = f2u(sB[2 * lane], sB[2 * lane + 1]);
        #pragma unroll 4
        for (int k = 0; k < 128; k++) {
            ull xv = splat2(row[k]);
            ull wl = *(const ull*)(sWlT + k * 66 + 2 * lane);
            ull wc = *(const ull*)(sWcT + k * 66 + 2 * lane);
            ay = fma2(wl, xv, ay);
            ac = fma2(wc, xv, ac);
        }
        size_t base = ((size_t)m * NN + n) * OC;
        *(float2*)(g_y + base + 2 * lane) = u2f(ay);
        *(float2*)(g_c + base + 2 * lane) = u2f(ac);
        __syncwarp();
    }
}

// =====================================================================
// K0: zero aggY buffer
// =====================================================================
__global__ void k_zero() {
    size_t i = (size_t)blockIdx.x * 256 + threadIdx.x;
    ((float4*)g_aggY)[i] = make_float4(0.f, 0.f, 0.f, 0.f);
}

// =====================================================================
// K1: edge scatter: aggY[m][src] += y[m][dst]. half-warp per edge.
// =====================================================================
__global__ void k_scatter(const int* __restrict__ ei) {
    int wid  = (blockIdx.x * blockDim.x + threadIdx.x) >> 5;
    int lane = threadIdx.x & 31;
    int pair = lane >> 4;
    int sub  = lane & 15;
    int eg = wid * 2 + pair;
    int m = eg / EE;
    int e = eg - m * EE;
    const int* b = ei + (size_t)m * 2 * EE;
    int src = __ldg(b + e);
    int dst = __ldg(b + EE + e);
    float4 v = ((const float4*)(g_y + ((size_t)m * NN + dst) * OC))[sub];
    atomicAdd(((float4*)(g_aggY + ((size_t)m * NN + src) * OC)) + sub, v);
}

// =====================================================================
// K2: GNN tail: h = relu(aggY + c); e_m = (h@Wo^T + bo)*mpw
// =====================================================================
__global__ void __launch_bounds__(256, 1) k_gnn(
    const float* __restrict__ Wo, const float* __restrict__ bo,
    const float* __restrict__ mpw)
{
    __shared__ float sWoT[64 * 66];
    __shared__ float sBo[64];
    __shared__ float sH[8 * 64];
    int t = threadIdx.x;
    int m = blockIdx.y;

    for (int i = t; i < 4096; i += 256) {
        int j = i >> 6, k = i & 63;
        sWoT[k * 66 + j] = Wo[(size_t)m * 4096 + j * 64 + k];
    }
    if (t < 64) sBo[t] = bo[m * 64 + t];
    __syncthreads();

    float wgt = mpw[m];
    int w = t >> 5, lane = t & 31;
    float* hrow = sH + w * 64;

    for (int n = blockIdx.x * 8 + w; n < NN; n += gridDim.x * 8) {
        size_t base = ((size_t)m * NN + n) * OC;
        hrow[lane]      = fmaxf(g_aggY[base + lane]      + g_c[base + lane], 0.f);
        hrow[lane + 32] = fmaxf(g_aggY[base + lane + 32] + g_c[base + lane + 32], 0.f);
        __syncwarp();
        ull o = f2u(sBo[2 * lane], sBo[2 * lane + 1]);
        #pragma unroll 8
        for (int i = 0; i < 64; i++) {
            o = fma2(*(const ull*)(sWoT + i * 66 + 2 * lane), splat2(hrow[i]), o);
        }
        float2 f = u2f(o);
        *(float2*)(g_e + ((size_t)n * MP + m) * OC + 2 * lane) =
            make_float2(f.x * wgt, f.y * wgt);
        __syncwarp();
    }
}

// =====================================================================
// K3: attention sublayer, 8 nodes per block (512 threads)
// =====================================================================
__global__ void __launch_bounds__(512, 1) k_attn(
    const float* __restrict__ tinw, const float* __restrict__ tinb,
    const float* __restrict__ tow,  const float* __restrict__ tob,
    const float* __restrict__ g1,   const float* __restrict__ b1v, int l)
{
    extern __shared__ float sm[];
    float* sTinT = sm;           // [64 k][193]
    float* sTowT = sm + 12352;   // [64 i][65]
    float* sTinB = sm + 16512;   // 192
    float* sToB  = sm + 16704;   // 64
    float* sE    = sm + 16768;   // 8 * 256
    float* sQKV  = sm + 18816;   // 8 * 768
    float* sAO   = sm + 24960;   // 8 * 256
    int t = threadIdx.x;

    const float* tw = tinw + (size_t)l * 192 * 64;
    for (int i = t; i < 12288; i += 512) {
        int r = i >> 6, k = i & 63;
        sTinT[k * 193 + r] = tw[r * 64 + k];
    }
    const float* twO = tow + (size_t)l * 64 * 64;
    for (int i = t; i < 4096; i += 512) {
        int j = i >> 6, k = i & 63;
        sTowT[k * 65 + j] = twO[j * 64 + k];
    }
    if (t < 192) sTinB[t] = tinb[l * 192 + t];
    if (t >= 192 && t < 256) sToB[t - 192] = tob[l * 64 + (t - 192)];

    int s = t >> 6, tt = t & 63;
    int node = blockIdx.x * 8 + s;
    float* eN   = sE + s * 256;
    float* qkvN = sQKV + s * 768;
    float* aoN  = sAO + s * 256;
    for (int i = tt; i < 256; i += 64) eN[i] = g_e[(size_t)node * 256 + i];
    __syncthreads();

    {
        float aq[4], ak[4], av[4];
        #pragma unroll
        for (int m2 = 0; m2 < 4; m2++) {
            aq[m2] = sTinB[tt]; ak[m2] = sTinB[64 + tt]; av[m2] = sTinB[128 + tt];
        }
        #pragma unroll 2
        for (int k = 0; k < 64; k++) {
            float wq = sTinT[k * 193 + tt];
            float wk = sTinT[k * 193 + 64 + tt];
            float wv = sTinT[k * 193 + 128 + tt];
            #pragma unroll
            for (int m2 = 0; m2 < 4; m2++) {
                float ev = eN[m2 * 64 + k];
                aq[m2] = fmaf(ev, wq, aq[m2]);
                ak[m2] = fmaf(ev, wk, ak[m2]);
                av[m2] = fmaf(ev, wv, av[m2]);
            }
        }
        #pragma unroll
        for (int m2 = 0; m2 < 4; m2++) {
            qkvN[m2 * 192 + tt]       = aq[m2];
            qkvN[m2 * 192 + 64 + tt]  = ak[m2];
            qkvN[m2 * 192 + 128 + tt] = av[m2];
        }
    }
    __syncthreads();

    if (tt < 32) {
        int h = tt >> 2, mq = tt & 3;
        float q[8];
        #pragma unroll
        for (int d = 0; d < 8; d++) q[d] = qkvN[mq * 192 + h * 8 + d];
        float sc[4];
        #pragma unroll
        for (int mk = 0; mk < 4; mk++) {
            float a = 0.f;
            #pragma unroll
            for (int d = 0; d < 8; d++) a = fmaf(q[d], qkvN[mk * 192 + 64 + h * 8 + d], a);
            sc[mk] = a * 0.35355339059327373f;
        }
        float mx = fmaxf(fmaxf(sc[0], sc[1]), fmaxf(sc[2], sc[3]));
        float p[4]; float psum = 0.f;
        #pragma unroll
        for (int mk = 0; mk < 4; mk++) { p[mk] = __expf(sc[mk] - mx); psum += p[mk]; }
        float inv = 1.0f / psum;
        #pragma unroll
        for (int d = 0; d < 8; d++) {
            float o = 0.f;
            #pragma unroll
            for (int mk = 0; mk < 4; mk++) o = fmaf(p[mk] * inv, qkvN[mk * 192 + 128 + h * 8 + d], o);
            aoN[mq * 64 + h * 8 + d] = o;
        }
    }
    __syncthreads();

    {
        float acc[4];
        #pragma unroll
        for (int m2 = 0; m2 < 4; m2++) acc[m2] = sToB[tt];
        #pragma unroll 4
        for (int i = 0; i < 64; i++) {
            float wv = sTowT[i * 65 + tt];
            #pragma unroll
            for (int m2 = 0; m2 < 4; m2++) acc[m2] = fmaf(aoN[m2 * 64 + i], wv, acc[m2]);
        }
        #pragma unroll
        for (int m2 = 0; m2 < 4; m2++) eN[m2 * 64 + tt] += acc[m2];
    }
    __syncthreads();

    int tl = t >> 4, part = t & 15;
    int ss = tl >> 2, m2 = tl & 3;
    const float* base = sE + ss * 256 + m2 * 64;
    float sum = 0.f, sq = 0.f;
    #pragma unroll
    for (int i2 = 0; i2 < 4; i2++) { float v = base[part * 4 + i2]; sum += v; sq += v * v; }
    #pragma unroll
    for (int off = 1; off < 16; off <<= 1) {
        sum += __shfl_xor_sync(0xffffffffu, sum, off);
        sq  += __shfl_xor_sync(0xffffffffu, sq,  off);
    }
    float mu   = sum * (1.f / 64.f);
    float rstd = rsqrtf(sq * (1.f / 64.f) - mu * mu + LN_EPS);
    int nodeW = blockIdx.x * 8 + ss;
    #pragma unroll
    for (int i2 = 0; i2 < 4; i2++) {
        int c = part * 4 + i2;
        float v = base[c];
        g_e[((size_t)nodeW * 4 + m2) * 64 + c] = (v - mu) * rstd * g1[l * 64 + c] + b1v[l * 64 + c];
    }
}

// =====================================================================
// K4: FF sublayer on TF32 tensor cores (mma.sync m16n8k8) + residual + LN2.
// 128-token tile, 16 chunks of 128 j. 8 warps = 4 M-strips x 2 N-halves.
//   sE  [128 tok][68]  tf32-rounded E (A for GEMM1)
//   sH  [128 tok][132] tf32-rounded relu hidden (A for GEMM2)
//   sW1 [128 j][68]    tf32 W1 chunk (B for GEMM1, natural [j][k])
//   sW2 [64 c][132]    tf32 W2 chunk (B for GEMM2, natural [c][j])
// =====================================================================
__global__ void __launch_bounds__(256, 1) k_ff(
    const float* __restrict__ ff1w, const float* __restrict__ ff1b,
    const float* __restrict__ ff2w, const float* __restrict__ ff2b,
    const float* __restrict__ g2,   const float* __restrict__ b2, int l)
{
    extern __shared__ float sm[];
    float* sE  = sm;                 // 128*68  = 8704
    float* sH  = sm + 8704;          // 128*132 = 16896
    float* sW1 = sm + 25600;         // 128*68  = 8704
    float* sW2 = sm + 34304;         // 64*132  = 8448
    float* sB1 = sm + 42752;         // 128
    float* sO  = sW1;                // alias: epilogue [128 tok][68]
    int t = threadIdx.x, w = t >> 5, lane = t & 31;
    int qr = lane >> 2, qc = lane & 3;
    size_t tok0 = (size_t)blockIdx.x * TB;

    const float* f1w = ff1w + (size_t)l * FFD * OC;
    const float* f1b = ff1b + (size_t)l * FFD;
    const float* f2w = ff2w + (size_t)l * OC * FFD;

    // stage E tile (tf32-rounded)
    for (int i = t; i < TB * 64; i += 256) {
        int tk = i >> 6, c = i & 63;
        sE[tk * 68 + c] = tf32r(g_e[tok0 * 64 + i]);
    }

    int mrow  = (w & 3) * 32;   // 32-row M strip
    int nhalf = w >> 2;         // 0/1: N half

    float acc2[4][2][4];
    #pragma unroll
    for (int nt = 0; nt < 4; nt++)
        #pragma unroll
        for (int mt = 0; mt < 2; mt++)
            #pragma unroll
            for (int q = 0; q < 4; q++) acc2[nt][mt][q] = 0.f;

    for (int ch = 0; ch < 16; ch++) {
        __syncthreads();
        int jb = ch * 128;
        for (int i = t; i < 8192; i += 256) {
            int j = i >> 6, k = i & 63;
            sW1[j * 68 + k] = tf32r(f1w[(size_t)(jb + j) * 64 + k]);
        }
        for (int i = t; i < 8192; i += 256) {
            int c = i >> 7, j = i & 127;
            sW2[c * 132 + j] = tf32r(f2w[(size_t)c * FFD + jb + j]);
        }
        if (t < 128) sB1[t] = f1b[jb + t];
        __syncthreads();

        // ---- GEMM1: H[128 tok x 128 j] = relu(E @ W1^T + b1), this chunk ----
        float acc1[8][2][4];
        #pragma unroll
        for (int nt = 0; nt < 8; nt++) {
            float bv0 = sB1[nhalf * 64 + nt * 8 + 2 * qc];
            float bv1 = sB1[nhalf * 64 + nt * 8 + 2 * qc + 1];
            #pragma unroll
            for (int mt = 0; mt < 2; mt++) {
                acc1[nt][mt][0] = bv0; acc1[nt][mt][1] = bv1;
                acc1[nt][mt][2] = bv0; acc1[nt][mt][3] = bv1;
            }
        }
        #pragma unroll
        for (int k0 = 0; k0 < 64; k0 += 8) {
            unsigned a[2][4];
            #pragma unroll
            for (int mt = 0; mt < 2; mt++) {
                int mr = mrow + mt * 16;
                a[mt][0] = __float_as_uint(sE[(mr + qr) * 68 + k0 + qc]);
                a[mt][1] = __float_as_uint(sE[(mr + 8 + qr) * 68 + k0 + qc]);
                a[mt][2] = __float_as_uint(sE[(mr + qr) * 68 + k0 + 4 + qc]);
                a[mt][3] = __float_as_uint(sE[(mr + 8 + qr) * 68 + k0 + 4 + qc]);
            }
            #pragma unroll
            for (int nt = 0; nt < 8; nt++) {
                int nr = nhalf * 64 + nt * 8 + qr;
                unsigned b[2];
                b[0] = __float_as_uint(sW1[nr * 68 + k0 + qc]);
                b[1] = __float_as_uint(sW1[nr * 68 + k0 + 4 + qc]);
                mma_tf32(acc1[nt][0], a[0], b);
                mma_tf32(acc1[nt][1], a[1], b);
            }
        }
        // relu + tf32 round + store H (c-layout float2 stores)
        #pragma unroll
        for (int nt = 0; nt < 8; nt++) {
            int col = nhalf * 64 + nt * 8 + 2 * qc;
            #pragma unroll
            for (int mt = 0; mt < 2; mt++) {
                int r0 = mrow + mt * 16 + qr;
                *(float2*)(sH + r0 * 132 + col) = make_float2(
                    tf32r(fmaxf(acc1[nt][mt][0], 0.f)),
                    tf32r(fmaxf(acc1[nt][mt][1], 0.f)));
                *(float2*)(sH + (r0 + 8) * 132 + col) = make_float2(
                    tf32r(fmaxf(acc1[nt][mt][2], 0.f)),
                    tf32r(fmaxf(acc1[nt][mt][3], 0.f)));
            }
        }
        __syncthreads();

        // ---- GEMM2: O[128 tok x 64 c] += H @ W2^T (this chunk's K=128) ----
        #pragma unroll
        for (int k0 = 0; k0 < 128; k0 += 8) {
            unsigned a[2][4];
            #pragma unroll
            for (int mt = 0; mt < 2; mt++) {
                int mr = mrow + mt * 16;
                a[mt][0] = __float_as_uint(sH[(mr + qr) * 132 + k0 + qc]);
                a[mt][1] = __float_as_uint(sH[(mr + 8 + qr) * 132 + k0 + qc]);
                a[mt][2] = __float_as_uint(sH[(mr + qr) * 132 + k0 + 4 + qc]);
                a[mt][3] = __float_as_uint(sH[(mr + 8 + qr) * 132 + k0 + 4 + qc]);
            }
            #pragma unroll
            for (int nt = 0; nt < 4; nt++) {
                int nr = nhalf * 32 + nt * 8 + qr;
                unsigned b[2];
                b[0] = __float_as_uint(sW2[nr * 132 + k0 + qc]);
                b[1] = __float_as_uint(sW2[nr * 132 + k0 + 4 + qc]);
                mma_tf32(acc2[nt][0], a[0], b);
                mma_tf32(acc2[nt][1], a[1], b);
            }
        }
    }

    // ---- epilogue: bias + residual (exact fp32 from g_e) -> sO, then LN2 ----
    __syncthreads();   // done with sW1 (sO aliases it)
    #pragma unroll
    for (int nt = 0; nt < 4; nt++) {
        int col = nhalf * 32 + nt * 8 + 2 * qc;
        float bias0 = ff2b[l * OC + col];
        float bias1 = ff2b[l * OC + col + 1];
        #pragma unroll
        for (int mt = 0; mt < 2; mt++) {
            int r0 = mrow + mt * 16 + qr;
            int r1 = r0 + 8;
            float2 e0 = *(const float2*)(g_e + (tok0 + r0) * 64 + col);
            float2 e1 = *(const float2*)(g_e + (tok0 + r1) * 64 + col);
            sO[r0 * 68 + col]     = acc2[nt][mt][0] + bias0 + e0.x;
            sO[r0 * 68 + col + 1] = acc2[nt][mt][1] + bias1 + e0.y;
            sO[r1 * 68 + col]     = acc2[nt][mt][2] + bias0 + e1.x;
            sO[r1 * 68 + col + 1] = acc2[nt][mt][3] + bias1 + e1.y;
        }
    }
    __syncthreads();

    // LN2: 2 threads per token
    int tk2 = t >> 1, half = t & 1;
    const float* ob = sO + tk2 * 68 + half * 32;
    float s = 0.f, s2 = 0.f;
    #pragma unroll
    for (int i = 0; i < 32; i++) { float v = ob[i]; s += v; s2 += v * v; }
    s  += __shfl_xor_sync(0xffffffffu, s, 1);
    s2 += __shfl_xor_sync(0xffffffffu, s2, 1);
    float mu   = s * (1.f / 64.f);
    float rstd = rsqrtf(s2 * (1.f / 64.f) - mu * mu + LN_EPS);
    float* go = g_e + (tok0 + tk2) * 64 + half * 32;
    #pragma unroll
    for (int i = 0; i < 32; i++) {
        int c = half * 32 + i;
        go[i] = (ob[i] - mu) * rstd * g2[l * OC + c] + b2[l * OC + c];
    }
}

// =====================================================================
// K5: head
// =====================================================================
__global__ void __launch_bounds__(256) k_head(
    const float* __restrict__ r1w, const float* __restrict__ r1b,
    const float* __restrict__ r2w, const float* __restrict__ r2b,
    float* __restrict__ out)
{
    __shared__ float sR1T[64 * 65];
    __shared__ float sR2[64];
    __shared__ float sP[8][64];
    int t = threadIdx.x;
    for (int i = t; i < 4096; i += 256) {
        int c = i >> 6, k = i & 63;
        sR1T[k * 65 + c] = r1w[c * 64 + k];
    }
    if (t < 64) sR2[t] = r2w[t];
    __syncthreads();
    int w = t >> 5, lane = t & 31;
    int n = blockIdx.x * 8 + w;
    const float* eb = g_e + (size_t)n * 256;
    float p0 = (eb[lane] + eb[64 + lane] + eb[128 + lane] + eb[192 + lane]) * 0.25f;
    float p1 = (eb[32 + lane] + eb[96 + lane] + eb[160 + lane] + eb[224 + lane]) * 0.25f;
    sP[w][lane]      = p0;
    sP[w][lane + 32] = p1;
    __syncwarp();
    float a0 = r1b[lane], a1 = r1b[lane + 32];
    #pragma unroll 8
    for (int k = 0; k < 64; k++) {
        float pv = sP[w][k];
        a0 = fmaf(pv, sR1T[k * 65 + lane], a0);
        a1 = fmaf(pv, sR1T[k * 65 + lane + 32], a1);
    }
    a0 = fmaxf(a0, 0.f); a1 = fmaxf(a1, 0.f);
    float acc = a0 * sR2[lane] + a1 * sR2[lane + 32];
    #pragma unroll
    for (int off = 16; off; off >>= 1) acc += __shfl_xor_sync(0xffffffffu, acc, off);
    if (lane == 0) out[n] = acc + r2b[0];
}

// =====================================================================
extern "C" void kernel_launch(void* const* d_in, const int* in_sizes, int n_in,
                              void* d_out, int out_size) {
    const float* x    = (const float*)d_in[0];
    const int*   ei   = (const int*)  d_in[1];
    const float* mpw  = (const float*)d_in[2];
    const float* W0   = (const float*)d_in[3];
    const float* b0   = (const float*)d_in[4];
    const float* Wl   = (const float*)d_in[5];
    const float* bl   = (const float*)d_in[6];
    const float* W1   = (const float*)d_in[7];
    const float* b1   = (const float*)d_in[8];
    const float* Wo   = (const float*)d_in[9];
    const float* bo   = (const float*)d_in[10];
    const float* tinw = (const float*)d_in[11];
    const float* tinb = (const float*)d_in[12];
    const float* tow  = (const float*)d_in[13];
    const float* tob  = (const float*)d_in[14];
    const float* ln1g = (const float*)d_in[15];
    const float* ln1b = (const float*)d_in[16];
    const float* ff1w = (const float*)d_in[17];
    const float* ff1b = (const float*)d_in[18];
    const float* ff2w = (const float*)d_in[19];
    const float* ff2b = (const float*)d_in[20];
    const float* ln2g = (const float*)d_in[21];
    const float* ln2b = (const float*)d_in[22];
    const float* r1w  = (const float*)d_in[23];
    const float* r1b  = (const float*)d_in[24];
    const float* r2w  = (const float*)d_in[25];
    const float* r2b  = (const float*)d_in[26];
    float* out = (float*)d_out;
    (void)in_sizes; (void)n_in; (void)out_size;

    cudaFuncSetAttribute(k_xw,   cudaFuncAttributeMaxDynamicSharedMemorySize, 17984 * 4);
    cudaFuncSetAttribute(k_attn, cudaFuncAttributeMaxDynamicSharedMemorySize, 27008 * 4);
    cudaFuncSetAttribute(k_ff,   cudaFuncAttributeMaxDynamicSharedMemorySize, 42880 * 4);

    // launch order chosen so ncu (-s 5 -c 1) captures k_ff (6th launch)
    dim3 gx(469, 4);
    k_xw<<<gx, 256, 17984 * 4>>>(x, W0, b0, Wl, bl, W1, b1);                 // 1
    k_zero<<<7500, 256>>>();                                                 // 2
    k_scatter<<<120000, 256>>>(ei);                                          // 3
    k_gnn<<<gx, 256>>>(Wo, bo, mpw);                                         // 4
    k_attn<<<3750, 512, 27008 * 4>>>(tinw, tinb, tow, tob, ln1g, ln1b, 0);   // 5
    k_ff<<<NBLK, 256, 42880 * 4>>>(ff1w, ff1b, ff2w, ff2b, ln2g, ln2b, 0);   // 6 <- ncu
    k_attn<<<3750, 512, 27008 * 4>>>(tinw, tinb, tow, tob, ln1g, ln1b, 1);
    k_ff<<<NBLK, 256, 42880 * 4>>>(ff1w, ff1b, ff2w, ff2b, ln2g, ln2b, 1);
    k_head<<<3750, 256>>>(r1w, r1b, r2w, r2b, out);
}

// round 6
// speedup vs baseline: 2.8097x; 1.1363x over previous
#include <cuda_runtime.h>
#include <cstdint>

typedef unsigned long long ull;

#define NN   30000
#define INC  128
#define OC   64
#define MP   4
#define EE   480000
#define FFD  2048
#define TOK  (NN*MP)
#define TB   128
#define NBLK ((TOK + TB - 1) / TB)   // 938
#define TOKP (NBLK * TB)             // 120064 (padded)
#define LN_EPS 1e-5f

// ---- device scratch (allocation-free rule: __device__ globals) ----
__device__ float g_y[(size_t)MP * NN * OC];     // x @ Wl^T
__device__ float g_c[(size_t)MP * NN * OC];     // x @ Wc^T + bias
__device__ float g_aggY[(size_t)MP * NN * OC];  // scatter target
__device__ float g_e[(size_t)TOKP * OC];        // token embeddings

// ---- packed fp32x2 helpers (exact fp32 semantics) ----
__device__ __forceinline__ ull fma2(ull a, ull b, ull c) {
    ull d; asm("fma.rn.f32x2 %0, %1, %2, %3;" : "=l"(d) : "l"(a), "l"(b), "l"(c)); return d;
}
__device__ __forceinline__ ull splat2(float x) {
    ull v; asm("mov.b64 %0, {%1, %1};" : "=l"(v) : "f"(x)); return v;
}
__device__ __forceinline__ float2 u2f(ull v) {
    float2 f; asm("mov.b64 {%0, %1}, %2;" : "=f"(f.x), "=f"(f.y) : "l"(v)); return f;
}
__device__ __forceinline__ ull f2u(float x, float y) {
    ull v; asm("mov.b64 %0, {%1, %2};" : "=l"(v) : "f"(x), "f"(y)); return v;
}

// ---- tf32 mma helpers ----
__device__ __forceinline__ float tf32r(float f) {
    unsigned u; asm("cvt.rna.tf32.f32 %0, %1;" : "=r"(u) : "f"(f));
    return __uint_as_float(u);
}
__device__ __forceinline__ void mma_tf32(float* c, const unsigned* a, const unsigned* b) {
    asm volatile(
        "mma.sync.aligned.m16n8k8.row.col.f32.tf32.tf32.f32 "
        "{%0,%1,%2,%3}, {%4,%5,%6,%7}, {%8,%9}, {%0,%1,%2,%3};"
        : "+f"(c[0]), "+f"(c[1]), "+f"(c[2]), "+f"(c[3])
        : "r"(a[0]), "r"(a[1]), "r"(a[2]), "r"(a[3]), "r"(b[0]), "r"(b[1]));
}

// =====================================================================
// K_xw: y[m] = x @ Wl[m]^T ; c[m] = x @ (W0[m]+W1[m])^T + bias
// =====================================================================
__global__ void __launch_bounds__(256, 1) k_xw(
    const float* __restrict__ x,
    const float* __restrict__ W0, const float* __restrict__ b0,
    const float* __restrict__ Wl, const float* __restrict__ bl,
    const float* __restrict__ W1, const float* __restrict__ b1)
{
    extern __shared__ float sm[];
    float* sWlT = sm;            // [128 k][66]
    float* sWcT = sm + 8448;     // [128 k][66]
    float* sB   = sm + 16896;    // 64
    float* sRow = sm + 16960;    // 8 warps * 128
    int t = threadIdx.x;
    int m = blockIdx.y;

    for (int i = t; i < 8192; i += 256) {
        int j = i >> 7, k = i & 127;
        size_t off = (size_t)m * 8192 + (size_t)j * 128 + k;
        sWlT[k * 66 + j] = Wl[off];
        sWcT[k * 66 + j] = W0[off] + W1[off];
    }
    if (t < 64) sB[t] = bl[m * 64 + t] + b0[m * 64 + t] + b1[m * 64 + t];
    __syncthreads();

    int w = t >> 5, lane = t & 31;
    float* row = sRow + w * 128;

    for (int n = blockIdx.x * 8 + w; n < NN; n += gridDim.x * 8) {
        ((float4*)row)[lane] = ((const float4*)(x + (size_t)n * INC))[lane];
        __syncwarp();
        ull ay = 0ull;
        ull ac = f2u(sB[2 * lane], sB[2 * lane + 1]);
        #pragma unroll 4
        for (int k = 0; k < 128; k++) {
            ull xv = splat2(row[k]);
            ull wl = *(const ull*)(sWlT + k * 66 + 2 * lane);
            ull wc = *(const ull*)(sWcT + k * 66 + 2 * lane);
            ay = fma2(wl, xv, ay);
            ac = fma2(wc, xv, ac);
        }
        size_t base = ((size_t)m * NN + n) * OC;
        *(float2*)(g_y + base + 2 * lane) = u2f(ay);
        *(float2*)(g_c + base + 2 * lane) = u2f(ac);
        __syncwarp();
    }
}

// =====================================================================
// K0: zero aggY buffer
// =====================================================================
__global__ void k_zero() {
    size_t i = (size_t)blockIdx.x * 256 + threadIdx.x;
    ((float4*)g_aggY)[i] = make_float4(0.f, 0.f, 0.f, 0.f);
}

// =====================================================================
// K1: edge scatter: aggY[m][src] += y[m][dst]. half-warp per edge.
// =====================================================================
__global__ void k_scatter(const int* __restrict__ ei) {
    int wid  = (blockIdx.x * blockDim.x + threadIdx.x) >> 5;
    int lane = threadIdx.x & 31;
    int pair = lane >> 4;
    int sub  = lane & 15;
    int eg = wid * 2 + pair;
    int m = eg / EE;
    int e = eg - m * EE;
    const int* b = ei + (size_t)m * 2 * EE;
    int src = __ldg(b + e);
    int dst = __ldg(b + EE + e);
    float4 v = ((const float4*)(g_y + ((size_t)m * NN + dst) * OC))[sub];
    atomicAdd(((float4*)(g_aggY + ((size_t)m * NN + src) * OC)) + sub, v);
}

// =====================================================================
// K2: GNN tail: h = relu(aggY + c); e_m = (h@Wo^T + bo)*mpw
// =====================================================================
__global__ void __launch_bounds__(256, 1) k_gnn(
    const float* __restrict__ Wo, const float* __restrict__ bo,
    const float* __restrict__ mpw)
{
    __shared__ float sWoT[64 * 66];
    __shared__ float sBo[64];
    __shared__ float sH[8 * 64];
    int t = threadIdx.x;
    int m = blockIdx.y;

    for (int i = t; i < 4096; i += 256) {
        int j = i >> 6, k = i & 63;
        sWoT[k * 66 + j] = Wo[(size_t)m * 4096 + j * 64 + k];
    }
    if (t < 64) sBo[t] = bo[m * 64 + t];
    __syncthreads();

    float wgt = mpw[m];
    int w = t >> 5, lane = t & 31;
    float* hrow = sH + w * 64;

    for (int n = blockIdx.x * 8 + w; n < NN; n += gridDim.x * 8) {
        size_t base = ((size_t)m * NN + n) * OC;
        hrow[lane]      = fmaxf(g_aggY[base + lane]      + g_c[base + lane], 0.f);
        hrow[lane + 32] = fmaxf(g_aggY[base + lane + 32] + g_c[base + lane + 32], 0.f);
        __syncwarp();
        ull o = f2u(sBo[2 * lane], sBo[2 * lane + 1]);
        #pragma unroll 8
        for (int i = 0; i < 64; i++) {
            o = fma2(*(const ull*)(sWoT + i * 66 + 2 * lane), splat2(hrow[i]), o);
        }
        float2 f = u2f(o);
        *(float2*)(g_e + ((size_t)n * MP + m) * OC + 2 * lane) =
            make_float2(f.x * wgt, f.y * wgt);
        __syncwarp();
    }
}

// =====================================================================
// K3: attention sublayer, 8 nodes per block (512 threads), fma2 packed.
// =====================================================================
__global__ void __launch_bounds__(512, 1) k_attn(
    const float* __restrict__ tinw, const float* __restrict__ tinb,
    const float* __restrict__ tow,  const float* __restrict__ tob,
    const float* __restrict__ g1,   const float* __restrict__ b1v, int l)
{
    extern __shared__ float sm[];
    float* sTinT = sm;           // [64 k][193]
    float* sTowT = sm + 12352;   // [64 i][65]
    float* sTinB = sm + 16512;   // 192
    float* sToB  = sm + 16704;   // 64
    float* sE    = sm + 16768;   // 8 * 256 (m-major, residual/LN)
    float* sEkT  = sm + 18816;   // 8 * 384 (k-major: k*6 + m)
    float* sQKV  = sm + 21888;   // 8 * 768
    float* sAO   = sm + 28032;   // 8 * 384 (i-major: i*6 + m)
    int t = threadIdx.x;

    const float* tw = tinw + (size_t)l * 192 * 64;
    for (int i = t; i < 12288; i += 512) {
        int r = i >> 6, k = i & 63;
        sTinT[k * 193 + r] = tw[r * 64 + k];
    }
    const float* twO = tow + (size_t)l * 64 * 64;
    for (int i = t; i < 4096; i += 512) {
        int j = i >> 6, k = i & 63;
        sTowT[k * 65 + j] = twO[j * 64 + k];
    }
    if (t < 192) sTinB[t] = tinb[l * 192 + t];
    if (t >= 192 && t < 256) sToB[t - 192] = tob[l * 64 + (t - 192)];

    int s = t >> 6, tt = t & 63;
    int node = blockIdx.x * 8 + s;
    float* eN   = sE + s * 256;
    float* eKT  = sEkT + s * 384;
    float* qkvN = sQKV + s * 768;
    float* aoT  = sAO + s * 384;
    for (int i = tt; i < 256; i += 64) {
        float v = g_e[(size_t)node * 256 + i];
        eN[i] = v;
        eKT[(i & 63) * 6 + (i >> 6)] = v;
    }
    __syncthreads();

    // qkv: 2 m-pairs packed fma2, weight splat
    {
        ull q01 = splat2(sTinB[tt]),       q23 = q01;
        ull k01 = splat2(sTinB[64 + tt]),  k23 = k01;
        ull v01 = splat2(sTinB[128 + tt]), v23 = v01;
        #pragma unroll 4
        for (int k = 0; k < 64; k++) {
            ull e01 = *(const ull*)(eKT + k * 6);
            ull e23 = *(const ull*)(eKT + k * 6 + 2);
            ull wq = splat2(sTinT[k * 193 + tt]);
            ull wk = splat2(sTinT[k * 193 + 64 + tt]);
            ull wv = splat2(sTinT[k * 193 + 128 + tt]);
            q01 = fma2(e01, wq, q01); q23 = fma2(e23, wq, q23);
            k01 = fma2(e01, wk, k01); k23 = fma2(e23, wk, k23);
            v01 = fma2(e01, wv, v01); v23 = fma2(e23, wv, v23);
        }
        float2 f;
        f = u2f(q01); qkvN[tt]             = f.x; qkvN[192 + tt]       = f.y;
        f = u2f(q23); qkvN[384 + tt]       = f.x; qkvN[576 + tt]       = f.y;
        f = u2f(k01); qkvN[64 + tt]        = f.x; qkvN[192 + 64 + tt]  = f.y;
        f = u2f(k23); qkvN[384 + 64 + tt]  = f.x; qkvN[576 + 64 + tt]  = f.y;
        f = u2f(v01); qkvN[128 + tt]       = f.x; qkvN[192 + 128 + tt] = f.y;
        f = u2f(v23); qkvN[384 + 128 + tt] = f.x; qkvN[576 + 128 + tt] = f.y;
    }
    __syncthreads();

    // attention core: 32 threads per node group; output transposed (i*6+m)
    if (tt < 32) {
        int h = tt >> 2, mq = tt & 3;
        float q[8];
        #pragma unroll
        for (int d = 0; d < 8; d++) q[d] = qkvN[mq * 192 + h * 8 + d];
        float sc[4];
        #pragma unroll
        for (int mk = 0; mk < 4; mk++) {
            float a = 0.f;
            #pragma unroll
            for (int d = 0; d < 8; d++) a = fmaf(q[d], qkvN[mk * 192 + 64 + h * 8 + d], a);
            sc[mk] = a * 0.35355339059327373f;
        }
        float mx = fmaxf(fmaxf(sc[0], sc[1]), fmaxf(sc[2], sc[3]));
        float p[4]; float psum = 0.f;
        #pragma unroll
        for (int mk = 0; mk < 4; mk++) { p[mk] = __expf(sc[mk] - mx); psum += p[mk]; }
        float inv = 1.0f / psum;
        #pragma unroll
        for (int d = 0; d < 8; d++) {
            float o = 0.f;
            #pragma unroll
            for (int mk = 0; mk < 4; mk++) o = fmaf(p[mk] * inv, qkvN[mk * 192 + 128 + h * 8 + d], o);
            aoT[(h * 8 + d) * 6 + mq] = o;
        }
    }
    __syncthreads();

    // proj + residual (channel = tt), m-pairs packed
    {
        ull a01 = splat2(sToB[tt]), a23 = a01;
        #pragma unroll 4
        for (int i = 0; i < 64; i++) {
            ull h01 = *(const ull*)(aoT + i * 6);
            ull h23 = *(const ull*)(aoT + i * 6 + 2);
            ull wv = splat2(sTowT[i * 65 + tt]);
            a01 = fma2(h01, wv, a01);
            a23 = fma2(h23, wv, a23);
        }
        float2 f0 = u2f(a01), f1 = u2f(a23);
        eN[tt]       += f0.x;
        eN[64 + tt]  += f0.y;
        eN[128 + tt] += f1.x;
        eN[192 + tt] += f1.y;
    }
    __syncthreads();

    // LN1: 32 tokens/block; 16 threads each cover 4 channels
    int tl = t >> 4, part = t & 15;
    int ss = tl >> 2, m2 = tl & 3;
    const float* base = sE + ss * 256 + m2 * 64;
    float sum = 0.f, sq = 0.f;
    #pragma unroll
    for (int i2 = 0; i2 < 4; i2++) { float v = base[part * 4 + i2]; sum += v; sq += v * v; }
    #pragma unroll
    for (int off = 1; off < 16; off <<= 1) {
        sum += __shfl_xor_sync(0xffffffffu, sum, off);
        sq  += __shfl_xor_sync(0xffffffffu, sq,  off);
    }
    float mu   = sum * (1.f / 64.f);
    float rstd = rsqrtf(sq * (1.f / 64.f) - mu * mu + LN_EPS);
    int nodeW = blockIdx.x * 8 + ss;
    #pragma unroll
    for (int i2 = 0; i2 < 4; i2++) {
        int c = part * 4 + i2;
        float v = base[c];
        g_e[((size_t)nodeW * 4 + m2) * 64 + c] = (v - mu) * rstd * g1[l * 64 + c] + b1v[l * 64 + c];
    }
}

// =====================================================================
// K4: FF sublayer on TF32 tensor cores, 512 threads, pipelined staging.
// warp = 16-token M-strip x N-half. 16 chunks of 128 j.
// =====================================================================
__global__ void __launch_bounds__(512, 1) k_ff(
    const float* __restrict__ ff1w, const float* __restrict__ ff1b,
    const float* __restrict__ ff2w, const float* __restrict__ ff2b,
    const float* __restrict__ g2,   const float* __restrict__ b2, int l)
{
    extern __shared__ float sm[];
    float* sE  = sm;                 // 128*68  = 8704
    float* sH  = sm + 8704;          // 128*132 = 16896
    float* sW1 = sm + 25600;         // 128*68  = 8704
    float* sW2 = sm + 34304;         // 64*132  = 8448
    float* sB1 = sm + 42752;         // 128
    float* sO  = sW1;                // alias: epilogue [128 tok][68]
    int t = threadIdx.x, w = t >> 5, lane = t & 31;
    int qr = lane >> 2, qc = lane & 3;
    size_t tok0 = (size_t)blockIdx.x * TB;
    int mrow  = (w & 7) * 16;
    int nhalf = w >> 3;

    const float* f1w = ff1w + (size_t)l * FFD * OC;
    const float* f1b = ff1b + (size_t)l * FFD;
    const float* f2w = ff2w + (size_t)l * OC * FFD;

    // stage E tile (tf32-rounded) + chunk 0 weights
    for (int i = t; i < TB * 64; i += 512) {
        int tk = i >> 6, c = i & 63;
        sE[tk * 68 + c] = tf32r(g_e[tok0 * 64 + i]);
    }
    for (int i = t; i < 8192; i += 512) {
        int j = i >> 6, k = i & 63;
        sW1[j * 68 + k] = tf32r(f1w[(size_t)j * 64 + k]);
    }
    for (int i = t; i < 8192; i += 512) {
        int c = i >> 7, j = i & 127;
        sW2[c * 132 + j] = tf32r(f2w[(size_t)c * FFD + j]);
    }
    if (t < 128) sB1[t] = f1b[t];
    __syncthreads();

    float acc2[4][4];
    #pragma unroll
    for (int nt = 0; nt < 4; nt++)
        #pragma unroll
        for (int q = 0; q < 4; q++) acc2[nt][q] = 0.f;

    for (int ch = 0; ch < 16; ch++) {
        int jb2 = (ch + 1) * 128;
        // prefetch W1(ch+1) + B1(ch+1) into registers during GEMM1
        float w1n[16]; float b1n = 0.f;
        if (ch < 15) {
            #pragma unroll
            for (int r = 0; r < 16; r++) {
                int idx = t + r * 512;
                int j = idx >> 6, k = idx & 63;
                w1n[r] = f1w[(size_t)(jb2 + j) * 64 + k];
            }
            if (t < 128) b1n = f1b[jb2 + t];
        }

        // ---- GEMM1: H = relu(E @ W1^T + b1) ----
        float acc1[8][4];
        #pragma unroll
        for (int nt = 0; nt < 8; nt++) {
            float bv0 = sB1[nhalf * 64 + nt * 8 + 2 * qc];
            float bv1 = sB1[nhalf * 64 + nt * 8 + 2 * qc + 1];
            acc1[nt][0] = bv0; acc1[nt][1] = bv1;
            acc1[nt][2] = bv0; acc1[nt][3] = bv1;
        }
        #pragma unroll
        for (int k0 = 0; k0 < 64; k0 += 8) {
            unsigned a[4];
            a[0] = __float_as_uint(sE[(mrow + qr) * 68 + k0 + qc]);
            a[1] = __float_as_uint(sE[(mrow + 8 + qr) * 68 + k0 + qc]);
            a[2] = __float_as_uint(sE[(mrow + qr) * 68 + k0 + 4 + qc]);
            a[3] = __float_as_uint(sE[(mrow + 8 + qr) * 68 + k0 + 4 + qc]);
            #pragma unroll
            for (int nt = 0; nt < 8; nt++) {
                int nr = nhalf * 64 + nt * 8 + qr;
                unsigned b[2];
                b[0] = __float_as_uint(sW1[nr * 68 + k0 + qc]);
                b[1] = __float_as_uint(sW1[nr * 68 + k0 + 4 + qc]);
                mma_tf32(acc1[nt], a, b);
            }
        }
        // relu + tf32 + store H
        #pragma unroll
        for (int nt = 0; nt < 8; nt++) {
            int col = nhalf * 64 + nt * 8 + 2 * qc;
            int r0 = mrow + qr;
            *(float2*)(sH + r0 * 132 + col) = make_float2(
                tf32r(fmaxf(acc1[nt][0], 0.f)), tf32r(fmaxf(acc1[nt][1], 0.f)));
            *(float2*)(sH + (r0 + 8) * 132 + col) = make_float2(
                tf32r(fmaxf(acc1[nt][2], 0.f)), tf32r(fmaxf(acc1[nt][3], 0.f)));
        }
        __syncthreads();   // sync1: H visible; sW1/sB1 free

        // store prefetched W1(ch+1)/B1(ch+1); prefetch W2(ch+1)
        float w2n[16];
        if (ch < 15) {
            #pragma unroll
            for (int r = 0; r < 16; r++) {
                int idx = t + r * 512;
                int j = idx >> 6, k = idx & 63;
                sW1[j * 68 + k] = tf32r(w1n[r]);
            }
            if (t < 128) sB1[t] = b1n;
            #pragma unroll
            for (int r = 0; r < 16; r++) {
                int idx = t + r * 512;
                int c = idx >> 7, j = idx & 127;
                w2n[r] = f2w[(size_t)c * FFD + jb2 + j];
            }
        }

        // ---- GEMM2: O += H @ W2^T ----
        #pragma unroll
        for (int k0 = 0; k0 < 128; k0 += 8) {
            unsigned a[4];
            a[0] = __float_as_uint(sH[(mrow + qr) * 132 + k0 + qc]);
            a[1] = __float_as_uint(sH[(mrow + 8 + qr) * 132 + k0 + qc]);
            a[2] = __float_as_uint(sH[(mrow + qr) * 132 + k0 + 4 + qc]);
            a[3] = __float_as_uint(sH[(mrow + 8 + qr) * 132 + k0 + 4 + qc]);
            #pragma unroll
            for (int nt = 0; nt < 4; nt++) {
                int nr = nhalf * 32 + nt * 8 + qr;
                unsigned b[2];
                b[0] = __float_as_uint(sW2[nr * 132 + k0 + qc]);
                b[1] = __float_as_uint(sW2[nr * 132 + k0 + 4 + qc]);
                mma_tf32(acc2[nt], a, b);
            }
        }
        __syncthreads();   // sync2: sW2/sH free

        if (ch < 15) {
            #pragma unroll
            for (int r = 0; r < 16; r++) {
                int idx = t + r * 512;
                int c = idx >> 7, j = idx & 127;
                sW2[c * 132 + j] = tf32r(w2n[r]);
            }
        }
    }

    // ---- epilogue: bias + residual (exact fp32 from g_e) -> sO, then LN2 ----
    #pragma unroll
    for (int nt = 0; nt < 4; nt++) {
        int col = nhalf * 32 + nt * 8 + 2 * qc;
        float bias0 = ff2b[l * OC + col];
        float bias1 = ff2b[l * OC + col + 1];
        int r0 = mrow + qr;
        int r1 = r0 + 8;
        float2 e0 = *(const float2*)(g_e + (tok0 + r0) * 64 + col);
        float2 e1 = *(const float2*)(g_e + (tok0 + r1) * 64 + col);
        sO[r0 * 68 + col]     = acc2[nt][0] + bias0 + e0.x;
        sO[r0 * 68 + col + 1] = acc2[nt][1] + bias1 + e0.y;
        sO[r1 * 68 + col]     = acc2[nt][2] + bias0 + e1.x;
        sO[r1 * 68 + col + 1] = acc2[nt][3] + bias1 + e1.y;
    }
    __syncthreads();

    // LN2: 4 threads per token (16 channels each)
    int tk2 = t >> 2, part = t & 3;
    const float* ob = sO + tk2 * 68 + part * 16;
    float s = 0.f, s2 = 0.f;
    #pragma unroll
    for (int i = 0; i < 16; i++) { float v = ob[i]; s += v; s2 += v * v; }
    s  += __shfl_xor_sync(0xffffffffu, s, 1);  s2 += __shfl_xor_sync(0xffffffffu, s2, 1);
    s  += __shfl_xor_sync(0xffffffffu, s, 2);  s2 += __shfl_xor_sync(0xffffffffu, s2, 2);
    float mu   = s * (1.f / 64.f);
    float rstd = rsqrtf(s2 * (1.f / 64.f) - mu * mu + LN_EPS);
    float* go = g_e + (tok0 + tk2) * 64 + part * 16;
    #pragma unroll
    for (int i = 0; i < 16; i++) {
        int c = part * 16 + i;
        go[i] = (ob[i] - mu) * rstd * g2[l * OC + c] + b2[l * OC + c];
    }
}

// =====================================================================
// K5: head
// =====================================================================
__global__ void __launch_bounds__(256) k_head(
    const float* __restrict__ r1w, const float* __restrict__ r1b,
    const float* __restrict__ r2w, const float* __restrict__ r2b,
    float* __restrict__ out)
{
    __shared__ float sR1T[64 * 65];
    __shared__ float sR2[64];
    __shared__ float sP[8][64];
    int t = threadIdx.x;
    for (int i = t; i < 4096; i += 256) {
        int c = i >> 6, k = i & 63;
        sR1T[k * 65 + c] = r1w[c * 64 + k];
    }
    if (t < 64) sR2[t] = r2w[t];
    __syncthreads();
    int w = t >> 5, lane = t & 31;
    int n = blockIdx.x * 8 + w;
    const float* eb = g_e + (size_t)n * 256;
    float p0 = (eb[lane] + eb[64 + lane] + eb[128 + lane] + eb[192 + lane]) * 0.25f;
    float p1 = (eb[32 + lane] + eb[96 + lane] + eb[160 + lane] + eb[224 + lane]) * 0.25f;
    sP[w][lane]      = p0;
    sP[w][lane + 32] = p1;
    __syncwarp();
    float a0 = r1b[lane], a1 = r1b[lane + 32];
    #pragma unroll 8
    for (int k = 0; k < 64; k++) {
        float pv = sP[w][k];
        a0 = fmaf(pv, sR1T[k * 65 + lane], a0);
        a1 = fmaf(pv, sR1T[k * 65 + lane + 32], a1);
    }
    a0 = fmaxf(a0, 0.f); a1 = fmaxf(a1, 0.f);
    float acc = a0 * sR2[lane] + a1 * sR2[lane + 32];
    #pragma unroll
    for (int off = 16; off; off >>= 1) acc += __shfl_xor_sync(0xffffffffu, acc, off);
    if (lane == 0) out[n] = acc + r2b[0];
}

// =====================================================================
extern "C" void kernel_launch(void* const* d_in, const int* in_sizes, int n_in,
                              void* d_out, int out_size) {
    const float* x    = (const float*)d_in[0];
    const int*   ei   = (const int*)  d_in[1];
    const float* mpw  = (const float*)d_in[2];
    const float* W0   = (const float*)d_in[3];
    const float* b0   = (const float*)d_in[4];
    const float* Wl   = (const float*)d_in[5];
    const float* bl   = (const float*)d_in[6];
    const float* W1   = (const float*)d_in[7];
    const float* b1   = (const float*)d_in[8];
    const float* Wo   = (const float*)d_in[9];
    const float* bo   = (const float*)d_in[10];
    const float* tinw = (const float*)d_in[11];
    const float* tinb = (const float*)d_in[12];
    const float* tow  = (const float*)d_in[13];
    const float* tob  = (const float*)d_in[14];
    const float* ln1g = (const float*)d_in[15];
    const float* ln1b = (const float*)d_in[16];
    const float* ff1w = (const float*)d_in[17];
    const float* ff1b = (const float*)d_in[18];
    const float* ff2w = (const float*)d_in[19];
    const float* ff2b = (const float*)d_in[20];
    const float* ln2g = (const float*)d_in[21];
    const float* ln2b = (const float*)d_in[22];
    const float* r1w  = (const float*)d_in[23];
    const float* r1b  = (const float*)d_in[24];
    const float* r2w  = (const float*)d_in[25];
    const float* r2b  = (const float*)d_in[26];
    float* out = (float*)d_out;
    (void)in_sizes; (void)n_in; (void)out_size;

    cudaFuncSetAttribute(k_xw,   cudaFuncAttributeMaxDynamicSharedMemorySize, 17984 * 4);
    cudaFuncSetAttribute(k_attn, cudaFuncAttributeMaxDynamicSharedMemorySize, 31104 * 4);
    cudaFuncSetAttribute(k_ff,   cudaFuncAttributeMaxDynamicSharedMemorySize, 42880 * 4);

    // launch order: ncu (-s 5 -c 1) captures k_ff (6th launch)
    dim3 gx(469, 4);
    k_xw<<<gx, 256, 17984 * 4>>>(x, W0, b0, Wl, bl, W1, b1);                 // 1
    k_zero<<<7500, 256>>>();                                                 // 2
    k_scatter<<<120000, 256>>>(ei);                                          // 3
    k_gnn<<<gx, 256>>>(Wo, bo, mpw);                                         // 4
    k_attn<<<3750, 512, 31104 * 4>>>(tinw, tinb, tow, tob, ln1g, ln1b, 0);   // 5
    k_ff<<<NBLK, 512, 42880 * 4>>>(ff1w, ff1b, ff2w, ff2b, ln2g, ln2b, 0);   // 6 <- ncu
    k_attn<<<3750, 512, 31104 * 4>>>(tinw, tinb, tow, tob, ln1g, ln1b, 1);
    k_ff<<<NBLK, 512, 42880 * 4>>>(ff1w, ff1b, ff2w, ff2b, ln2g, ln2b, 1);
    k_head<<<3750, 256>>>(r1w, r1b, r2w, r2b, out);
}

// round 7
// speedup vs baseline: 2.9564x; 1.0522x over previous
#include <cuda_runtime.h>
#include <cstdint>

typedef unsigned long long ull;

#define NN   30000
#define INC  128
#define OC   64
#define MP   4
#define EE   480000
#define FFD  2048
#define TOK  (NN*MP)
#define TB   256                     // tokens per ff block
#define NBLK ((TOK + TB - 1) / TB)   // 469
#define TOKP (NBLK * TB)             // 120064 (padded)
#define JC   64                      // j per chunk
#define NCH  (FFD / JC)              // 32 chunks
#define LN_EPS 1e-5f

// ---- device scratch (allocation-free rule: __device__ globals) ----
__device__ float g_y[(size_t)MP * NN * OC];     // x @ Wl^T
__device__ float g_c[(size_t)MP * NN * OC];     // x @ Wc^T + bias
__device__ float g_aggY[(size_t)MP * NN * OC];  // scatter target
__device__ float g_e[(size_t)TOKP * OC];        // token embeddings

// ---- packed fp32x2 helpers (exact fp32 semantics) ----
__device__ __forceinline__ ull fma2(ull a, ull b, ull c) {
    ull d; asm("fma.rn.f32x2 %0, %1, %2, %3;" : "=l"(d) : "l"(a), "l"(b), "l"(c)); return d;
}
__device__ __forceinline__ ull splat2(float x) {
    ull v; asm("mov.b64 %0, {%1, %1};" : "=l"(v) : "f"(x)); return v;
}
__device__ __forceinline__ float2 u2f(ull v) {
    float2 f; asm("mov.b64 {%0, %1}, %2;" : "=f"(f.x), "=f"(f.y) : "l"(v)); return f;
}
__device__ __forceinline__ ull f2u(float x, float y) {
    ull v; asm("mov.b64 %0, {%1, %2};" : "=l"(v) : "f"(x), "f"(y)); return v;
}

// ---- tf32 mma helpers ----
__device__ __forceinline__ float tf32r(float f) {
    unsigned u; asm("cvt.rna.tf32.f32 %0, %1;" : "=r"(u) : "f"(f));
    return __uint_as_float(u);
}
__device__ __forceinline__ void mma_tf32(float* c, const unsigned* a, const unsigned* b) {
    asm volatile(
        "mma.sync.aligned.m16n8k8.row.col.f32.tf32.tf32.f32 "
        "{%0,%1,%2,%3}, {%4,%5,%6,%7}, {%8,%9}, {%0,%1,%2,%3};"
        : "+f"(c[0]), "+f"(c[1]), "+f"(c[2]), "+f"(c[3])
        : "r"(a[0]), "r"(a[1]), "r"(a[2]), "r"(a[3]), "r"(b[0]), "r"(b[1]));
}
// interleaved-k column permutation within 8-groups: frag pairs become adjacent
__device__ __forceinline__ int pc8(int k) {
    return (k & ~7) | ((k & 3) << 1) | ((k >> 2) & 1);
}

// =====================================================================
// K_xw: y[m] = x @ Wl[m]^T ; c[m] = x @ (W0[m]+W1[m])^T + bias
// =====================================================================
__global__ void __launch_bounds__(256, 1) k_xw(
    const float* __restrict__ x,
    const float* __restrict__ W0, const float* __restrict__ b0,
    const float* __restrict__ Wl, const float* __restrict__ bl,
    const float* __restrict__ W1, const float* __restrict__ b1)
{
    extern __shared__ float sm[];
    float* sWlT = sm;            // [128 k][66]
    float* sWcT = sm + 8448;     // [128 k][66]
    float* sB   = sm + 16896;    // 64
    float* sRow = sm + 16960;    // 8 warps * 128
    int t = threadIdx.x;
    int m = blockIdx.y;

    for (int i = t; i < 8192; i += 256) {
        int j = i >> 7, k = i & 127;
        size_t off = (size_t)m * 8192 + (size_t)j * 128 + k;
        sWlT[k * 66 + j] = Wl[off];
        sWcT[k * 66 + j] = W0[off] + W1[off];
    }
    if (t < 64) sB[t] = bl[m * 64 + t] + b0[m * 64 + t] + b1[m * 64 + t];
    __syncthreads();

    int w = t >> 5, lane = t & 31;
    float* row = sRow + w * 128;

    for (int n = blockIdx.x * 8 + w; n < NN; n += gridDim.x * 8) {
        ((float4*)row)[lane] = ((const float4*)(x + (size_t)n * INC))[lane];
        __syncwarp();
        ull ay = 0ull;
        ull ac = f2u(sB[2 * lane], sB[2 * lane + 1]);
        #pragma unroll 4
        for (int k = 0; k < 128; k++) {
            ull xv = splat2(row[k]);
            ull wl = *(const ull*)(sWlT + k * 66 + 2 * lane);
            ull wc = *(const ull*)(sWcT + k * 66 + 2 * lane);
            ay = fma2(wl, xv, ay);
            ac = fma2(wc, xv, ac);
        }
        size_t base = ((size_t)m * NN + n) * OC;
        *(float2*)(g_y + base + 2 * lane) = u2f(ay);
        *(float2*)(g_c + base + 2 * lane) = u2f(ac);
        __syncwarp();
    }
}

// =====================================================================
// K0: zero aggY buffer
// =====================================================================
__global__ void k_zero() {
    size_t i = (size_t)blockIdx.x * 256 + threadIdx.x;
    ((float4*)g_aggY)[i] = make_float4(0.f, 0.f, 0.f, 0.f);
}

// =====================================================================
// K1: edge scatter: aggY[m][src] += y[m][dst]. half-warp per edge.
// =====================================================================
__global__ void k_scatter(const int* __restrict__ ei) {
    int wid  = (blockIdx.x * blockDim.x + threadIdx.x) >> 5;
    int lane = threadIdx.x & 31;
    int pair = lane >> 4;
    int sub  = lane & 15;
    int eg = wid * 2 + pair;
    int m = eg / EE;
    int e = eg - m * EE;
    const int* b = ei + (size_t)m * 2 * EE;
    int src = __ldg(b + e);
    int dst = __ldg(b + EE + e);
    float4 v = ((const float4*)(g_y + ((size_t)m * NN + dst) * OC))[sub];
    atomicAdd(((float4*)(g_aggY + ((size_t)m * NN + src) * OC)) + sub, v);
}

// =====================================================================
// K2: GNN tail: h = relu(aggY + c); e_m = (h@Wo^T + bo)*mpw
// =====================================================================
__global__ void __launch_bounds__(256, 1) k_gnn(
    const float* __restrict__ Wo, const float* __restrict__ bo,
    const float* __restrict__ mpw)
{
    __shared__ float sWoT[64 * 66];
    __shared__ float sBo[64];
    __shared__ float sH[8 * 64];
    int t = threadIdx.x;
    int m = blockIdx.y;

    for (int i = t; i < 4096; i += 256) {
        int j = i >> 6, k = i & 63;
        sWoT[k * 66 + j] = Wo[(size_t)m * 4096 + j * 64 + k];
    }
    if (t < 64) sBo[t] = bo[m * 64 + t];
    __syncthreads();

    float wgt = mpw[m];
    int w = t >> 5, lane = t & 31;
    float* hrow = sH + w * 64;

    for (int n = blockIdx.x * 8 + w; n < NN; n += gridDim.x * 8) {
        size_t base = ((size_t)m * NN + n) * OC;
        hrow[lane]      = fmaxf(g_aggY[base + lane]      + g_c[base + lane], 0.f);
        hrow[lane + 32] = fmaxf(g_aggY[base + lane + 32] + g_c[base + lane + 32], 0.f);
        __syncwarp();
        ull o = f2u(sBo[2 * lane], sBo[2 * lane + 1]);
        #pragma unroll 8
        for (int i = 0; i < 64; i++) {
            o = fma2(*(const ull*)(sWoT + i * 66 + 2 * lane), splat2(hrow[i]), o);
        }
        float2 f = u2f(o);
        *(float2*)(g_e + ((size_t)n * MP + m) * OC + 2 * lane) =
            make_float2(f.x * wgt, f.y * wgt);
        __syncwarp();
    }
}

// =====================================================================
// K3: attention sublayer, 8 nodes per block (512 threads), fma2 packed.
// =====================================================================
__global__ void __launch_bounds__(512, 1) k_attn(
    const float* __restrict__ tinw, const float* __restrict__ tinb,
    const float* __restrict__ tow,  const float* __restrict__ tob,
    const float* __restrict__ g1,   const float* __restrict__ b1v, int l)
{
    extern __shared__ float sm[];
    float* sTinT = sm;           // [64 k][193]
    float* sTowT = sm + 12352;   // [64 i][65]
    float* sTinB = sm + 16512;   // 192
    float* sToB  = sm + 16704;   // 64
    float* sE    = sm + 16768;   // 8 * 256
    float* sEkT  = sm + 18816;   // 8 * 384
    float* sQKV  = sm + 21888;   // 8 * 768
    float* sAO   = sm + 28032;   // 8 * 384
    int t = threadIdx.x;

    const float* tw = tinw + (size_t)l * 192 * 64;
    for (int i = t; i < 12288; i += 512) {
        int r = i >> 6, k = i & 63;
        sTinT[k * 193 + r] = tw[r * 64 + k];
    }
    const float* twO = tow + (size_t)l * 64 * 64;
    for (int i = t; i < 4096; i += 512) {
        int j = i >> 6, k = i & 63;
        sTowT[k * 65 + j] = twO[j * 64 + k];
    }
    if (t < 192) sTinB[t] = tinb[l * 192 + t];
    if (t >= 192 && t < 256) sToB[t - 192] = tob[l * 64 + (t - 192)];

    int s = t >> 6, tt = t & 63;
    int node = blockIdx.x * 8 + s;
    float* eN   = sE + s * 256;
    float* eKT  = sEkT + s * 384;
    float* qkvN = sQKV + s * 768;
    float* aoT  = sAO + s * 384;
    for (int i = tt; i < 256; i += 64) {
        float v = g_e[(size_t)node * 256 + i];
        eN[i] = v;
        eKT[(i & 63) * 6 + (i >> 6)] = v;
    }
    __syncthreads();

    {
        ull q01 = splat2(sTinB[tt]),       q23 = q01;
        ull k01 = splat2(sTinB[64 + tt]),  k23 = k01;
        ull v01 = splat2(sTinB[128 + tt]), v23 = v01;
        #pragma unroll 4
        for (int k = 0; k < 64; k++) {
            ull e01 = *(const ull*)(eKT + k * 6);
            ull e23 = *(const ull*)(eKT + k * 6 + 2);
            ull wq = splat2(sTinT[k * 193 + tt]);
            ull wk = splat2(sTinT[k * 193 + 64 + tt]);
            ull wv = splat2(sTinT[k * 193 + 128 + tt]);
            q01 = fma2(e01, wq, q01); q23 = fma2(e23, wq, q23);
            k01 = fma2(e01, wk, k01); k23 = fma2(e23, wk, k23);
            v01 = fma2(e01, wv, v01); v23 = fma2(e23, wv, v23);
        }
        float2 f;
        f = u2f(q01); qkvN[tt]             = f.x; qkvN[192 + tt]       = f.y;
        f = u2f(q23); qkvN[384 + tt]       = f.x; qkvN[576 + tt]       = f.y;
        f = u2f(k01); qkvN[64 + tt]        = f.x; qkvN[192 + 64 + tt]  = f.y;
        f = u2f(k23); qkvN[384 + 64 + tt]  = f.x; qkvN[576 + 64 + tt]  = f.y;
        f = u2f(v01); qkvN[128 + tt]       = f.x; qkvN[192 + 128 + tt] = f.y;
        f = u2f(v23); qkvN[384 + 128 + tt] = f.x; qkvN[576 + 128 + tt] = f.y;
    }
    __syncthreads();

    if (tt < 32) {
        int h = tt >> 2, mq = tt & 3;
        float q[8];
        #pragma unroll
        for (int d = 0; d < 8; d++) q[d] = qkvN[mq * 192 + h * 8 + d];
        float sc[4];
        #pragma unroll
        for (int mk = 0; mk < 4; mk++) {
            float a = 0.f;
            #pragma unroll
            for (int d = 0; d < 8; d++) a = fmaf(q[d], qkvN[mk * 192 + 64 + h * 8 + d], a);
            sc[mk] = a * 0.35355339059327373f;
        }
        float mx = fmaxf(fmaxf(sc[0], sc[1]), fmaxf(sc[2], sc[3]));
        float p[4]; float psum = 0.f;
        #pragma unroll
        for (int mk = 0; mk < 4; mk++) { p[mk] = __expf(sc[mk] - mx); psum += p[mk]; }
        float inv = 1.0f / psum;
        #pragma unroll
        for (int d = 0; d < 8; d++) {
            float o = 0.f;
            #pragma unroll
            for (int mk = 0; mk < 4; mk++) o = fmaf(p[mk] * inv, qkvN[mk * 192 + 128 + h * 8 + d], o);
            aoT[(h * 8 + d) * 6 + mq] = o;
        }
    }
    __syncthreads();

    {
        ull a01 = splat2(sToB[tt]), a23 = a01;
        #pragma unroll 4
        for (int i = 0; i < 64; i++) {
            ull h01 = *(const ull*)(aoT + i * 6);
            ull h23 = *(const ull*)(aoT + i * 6 + 2);
            ull wv = splat2(sTowT[i * 65 + tt]);
            a01 = fma2(h01, wv, a01);
            a23 = fma2(h23, wv, a23);
        }
        float2 f0 = u2f(a01), f1 = u2f(a23);
        eN[tt]       += f0.x;
        eN[64 + tt]  += f0.y;
        eN[128 + tt] += f1.x;
        eN[192 + tt] += f1.y;
    }
    __syncthreads();

    int tl = t >> 4, part = t & 15;
    int ss = tl >> 2, m2 = tl & 3;
    const float* base = sE + ss * 256 + m2 * 64;
    float sum = 0.f, sq = 0.f;
    #pragma unroll
    for (int i2 = 0; i2 < 4; i2++) { float v = base[part * 4 + i2]; sum += v; sq += v * v; }
    #pragma unroll
    for (int off = 1; off < 16; off <<= 1) {
        sum += __shfl_xor_sync(0xffffffffu, sum, off);
        sq  += __shfl_xor_sync(0xffffffffu, sq,  off);
    }
    float mu   = sum * (1.f / 64.f);
    float rstd = rsqrtf(sq * (1.f / 64.f) - mu * mu + LN_EPS);
    int nodeW = blockIdx.x * 8 + ss;
    #pragma unroll
    for (int i2 = 0; i2 < 4; i2++) {
        int c = part * 4 + i2;
        float v = base[c];
        g_e[((size_t)nodeW * 4 + m2) * 64 + c] = (v - mu) * rstd * g1[l * 64 + c] + b1v[l * 64 + c];
    }
}

// =====================================================================
// K4: FF sublayer on TF32 tensor cores. 256-token tile, 32 chunks of 64 j.
// 16 warps = 8 m-strips(32 tok) x 2 halves. Interleaved-k columns (pitch 72)
// -> A-frag = 2 LDS.64, B-frag = 1 LDS.64, all conflict-free.
// =====================================================================
__global__ void __launch_bounds__(512, 1) k_ff(
    const float* __restrict__ ff1w, const float* __restrict__ ff1b,
    const float* __restrict__ ff2w, const float* __restrict__ ff2b,
    const float* __restrict__ g2,   const float* __restrict__ b2, int l)
{
    extern __shared__ float sm[];
    float* sE  = sm;                 // [256][72] = 18432 (perm cols, tf32)
    float* sH  = sm + 18432;         // [256][72] = 18432 (perm cols, tf32)
    float* sW1 = sm + 36864;         // [64 j][72] = 4608
    float* sW2 = sm + 41472;         // [64 c][72] = 4608
    float* sB1 = sm + 46080;         // 64
    float* sO  = sE;                 // alias: epilogue [256 tok][72] plain cols
    int t = threadIdx.x, w = t >> 5, lane = t & 31;
    int qr = lane >> 2, qc = lane & 3;
    size_t tok0 = (size_t)blockIdx.x * TB;
    int mrow = (w & 7) * 32;         // 32-token m-strip
    int nh   = w >> 3;               // 0/1 half (j-half in GEMM1, c-half in GEMM2)
    int nbase = nh * 32;

    const float* f1w = ff1w + (size_t)l * FFD * OC;
    const float* f1b = ff1b + (size_t)l * FFD;
    const float* f2w = ff2w + (size_t)l * OC * FFD;

    // stage E tile (tf32, perm cols) + chunk-0 weights
    for (int i = t; i < TB * 64; i += 512) {
        int tk = i >> 6, c = i & 63;
        sE[tk * 72 + pc8(c)] = tf32r(g_e[tok0 * 64 + i]);
    }
    for (int i = t; i < JC * 64; i += 512) {
        int j = i >> 6, k = i & 63;
        sW1[j * 72 + pc8(k)] = tf32r(f1w[(size_t)j * 64 + k]);
    }
    for (int i = t; i < 64 * JC; i += 512) {
        int c = i >> 6, j = i & 63;
        sW2[c * 72 + pc8(j)] = tf32r(f2w[(size_t)c * FFD + j]);
    }
    if (t < 64) sB1[t] = f1b[t];
    __syncthreads();

    float acc2[2][4][4];
    #pragma unroll
    for (int mt = 0; mt < 2; mt++)
        #pragma unroll
        for (int nt = 0; nt < 4; nt++)
            #pragma unroll
            for (int q = 0; q < 4; q++) acc2[mt][nt][q] = 0.f;

    int p0 = pc8(2 * qc);       // perm offset of col 2qc within 8-group
    int p1 = pc8(2 * qc + 1);

    for (int ch = 0; ch < NCH; ch++) {
        int jb2 = (ch + 1) * JC;
        // prefetch W1(ch+1)+B1(ch+1) during GEMM1
        float w1n[8]; float b1n = 0.f;
        if (ch < NCH - 1) {
            #pragma unroll
            for (int r = 0; r < 8; r++) {
                int idx = t + r * 512;
                int j = idx >> 6, k = idx & 63;
                w1n[r] = f1w[(size_t)(jb2 + j) * 64 + k];
            }
            if (t < 64) b1n = f1b[jb2 + t];
        }

        // ---- GEMM1: H(256 x 64j) = relu(E @ W1^T + b1) ----
        float acc1[2][4][4];
        #pragma unroll
        for (int nt = 0; nt < 4; nt++) {
            float bv0 = sB1[nbase + nt * 8 + 2 * qc];
            float bv1 = sB1[nbase + nt * 8 + 2 * qc + 1];
            #pragma unroll
            for (int mt = 0; mt < 2; mt++) {
                acc1[mt][nt][0] = bv0; acc1[mt][nt][1] = bv1;
                acc1[mt][nt][2] = bv0; acc1[mt][nt][3] = bv1;
            }
        }
        #pragma unroll
        for (int k0 = 0; k0 < 64; k0 += 8) {
            unsigned a[2][4];
            #pragma unroll
            for (int mt = 0; mt < 2; mt++) {
                int r0 = mrow + mt * 16;
                float2 lo = *(const float2*)(sE + (r0 + qr) * 72 + k0 + 2 * qc);
                float2 hi = *(const float2*)(sE + (r0 + 8 + qr) * 72 + k0 + 2 * qc);
                a[mt][0] = __float_as_uint(lo.x); a[mt][2] = __float_as_uint(lo.y);
                a[mt][1] = __float_as_uint(hi.x); a[mt][3] = __float_as_uint(hi.y);
            }
            #pragma unroll
            for (int nt = 0; nt < 4; nt++) {
                float2 bv = *(const float2*)(sW1 + (nbase + nt * 8 + qr) * 72 + k0 + 2 * qc);
                unsigned b[2] = { __float_as_uint(bv.x), __float_as_uint(bv.y) };
                mma_tf32(acc1[0][nt], a[0], b);
                mma_tf32(acc1[1][nt], a[1], b);
            }
        }
        // relu + tf32 + store H into perm cols
        #pragma unroll
        for (int nt = 0; nt < 4; nt++) {
            int jbase = nbase + nt * 8;
            #pragma unroll
            for (int mt = 0; mt < 2; mt++) {
                int r0 = mrow + mt * 16 + qr;
                sH[r0 * 72 + jbase + p0]       = tf32r(fmaxf(acc1[mt][nt][0], 0.f));
                sH[r0 * 72 + jbase + p1]       = tf32r(fmaxf(acc1[mt][nt][1], 0.f));
                sH[(r0 + 8) * 72 + jbase + p0] = tf32r(fmaxf(acc1[mt][nt][2], 0.f));
                sH[(r0 + 8) * 72 + jbase + p1] = tf32r(fmaxf(acc1[mt][nt][3], 0.f));
            }
        }
        __syncthreads();   // sync1: H visible; sW1/sB1 free

        // store prefetched W1/B1; prefetch W2(ch+1)
        float w2n[8];
        if (ch < NCH - 1) {
            #pragma unroll
            for (int r = 0; r < 8; r++) {
                int idx = t + r * 512;
                int j = idx >> 6, k = idx & 63;
                sW1[j * 72 + pc8(k)] = tf32r(w1n[r]);
            }
            if (t < 64) sB1[t] = b1n;
            #pragma unroll
            for (int r = 0; r < 8; r++) {
                int idx = t + r * 512;
                int c = idx >> 6, j = idx & 63;
                w2n[r] = f2w[(size_t)c * FFD + jb2 + j];
            }
        }

        // ---- GEMM2: O(256 x 64c) += H @ W2^T (K = 64 j of this chunk) ----
        #pragma unroll
        for (int k0 = 0; k0 < 64; k0 += 8) {
            unsigned a[2][4];
            #pragma unroll
            for (int mt = 0; mt < 2; mt++) {
                int r0 = mrow + mt * 16;
                float2 lo = *(const float2*)(sH + (r0 + qr) * 72 + k0 + 2 * qc);
                float2 hi = *(const float2*)(sH + (r0 + 8 + qr) * 72 + k0 + 2 * qc);
                a[mt][0] = __float_as_uint(lo.x); a[mt][2] = __float_as_uint(lo.y);
                a[mt][1] = __float_as_uint(hi.x); a[mt][3] = __float_as_uint(hi.y);
            }
            #pragma unroll
            for (int nt = 0; nt < 4; nt++) {
                float2 bv = *(const float2*)(sW2 + (nbase + nt * 8 + qr) * 72 + k0 + 2 * qc);
                unsigned b[2] = { __float_as_uint(bv.x), __float_as_uint(bv.y) };
                mma_tf32(acc2[0][nt], a[0], b);
                mma_tf32(acc2[1][nt], a[1], b);
            }
        }
        __syncthreads();   // sync2: sH/sW2 free

        if (ch < NCH - 1) {
            #pragma unroll
            for (int r = 0; r < 8; r++) {
                int idx = t + r * 512;
                int c = idx >> 6, j = idx & 63;
                sW2[c * 72 + pc8(j)] = tf32r(w2n[r]);
            }
        }
    }

    // ---- epilogue: bias + residual (exact fp32 from g_e) -> sO, then LN2 ----
    #pragma unroll
    for (int nt = 0; nt < 4; nt++) {
        int col = nbase + nt * 8 + 2 * qc;
        float bias0 = ff2b[l * OC + col];
        float bias1 = ff2b[l * OC + col + 1];
        #pragma unroll
        for (int mt = 0; mt < 2; mt++) {
            int r0 = mrow + mt * 16 + qr;
            int r1 = r0 + 8;
            float2 e0 = *(const float2*)(g_e + (tok0 + r0) * 64 + col);
            float2 e1 = *(const float2*)(g_e + (tok0 + r1) * 64 + col);
            sO[r0 * 72 + col]     = acc2[mt][nt][0] + bias0 + e0.x;
            sO[r0 * 72 + col + 1] = acc2[mt][nt][1] + bias1 + e0.y;
            sO[r1 * 72 + col]     = acc2[mt][nt][2] + bias0 + e1.x;
            sO[r1 * 72 + col + 1] = acc2[mt][nt][3] + bias1 + e1.y;
        }
    }
    __syncthreads();

    // LN2: 2 threads per token (256 tokens)
    int tk2 = t >> 1, half = t & 1;
    const float* ob = sO + tk2 * 72 + half * 32;
    float s = 0.f, s2 = 0.f;
    #pragma unroll
    for (int i = 0; i < 32; i++) { float v = ob[i]; s += v; s2 += v * v; }
    s  += __shfl_xor_sync(0xffffffffu, s, 1);
    s2 += __shfl_xor_sync(0xffffffffu, s2, 1);
    float mu   = s * (1.f / 64.f);
    float rstd = rsqrtf(s2 * (1.f / 64.f) - mu * mu + LN_EPS);
    float* go = g_e + (tok0 + tk2) * 64 + half * 32;
    #pragma unroll
    for (int i = 0; i < 32; i++) {
        int c = half * 32 + i;
        go[i] = (ob[i] - mu) * rstd * g2[l * OC + c] + b2[l * OC + c];
    }
}

// =====================================================================
// K5: head
// =====================================================================
__global__ void __launch_bounds__(256) k_head(
    const float* __restrict__ r1w, const float* __restrict__ r1b,
    const float* __restrict__ r2w, const float* __restrict__ r2b,
    float* __restrict__ out)
{
    __shared__ float sR1T[64 * 65];
    __shared__ float sR2[64];
    __shared__ float sP[8][64];
    int t = threadIdx.x;
    for (int i = t; i < 4096; i += 256) {
        int c = i >> 6, k = i & 63;
        sR1T[k * 65 + c] = r1w[c * 64 + k];
    }
    if (t < 64) sR2[t] = r2w[t];
    __syncthreads();
    int w = t >> 5, lane = t & 31;
    int n = blockIdx.x * 8 + w;
    const float* eb = g_e + (size_t)n * 256;
    float p0 = (eb[lane] + eb[64 + lane] + eb[128 + lane] + eb[192 + lane]) * 0.25f;
    float p1 = (eb[32 + lane] + eb[96 + lane] + eb[160 + lane] + eb[224 + lane]) * 0.25f;
    sP[w][lane]      = p0;
    sP[w][lane + 32] = p1;
    __syncwarp();
    float a0 = r1b[lane], a1 = r1b[lane + 32];
    #pragma unroll 8
    for (int k = 0; k < 64; k++) {
        float pv = sP[w][k];
        a0 = fmaf(pv, sR1T[k * 65 + lane], a0);
        a1 = fmaf(pv, sR1T[k * 65 + lane + 32], a1);
    }
    a0 = fmaxf(a0, 0.f); a1 = fmaxf(a1, 0.f);
    float acc = a0 * sR2[lane] + a1 * sR2[lane + 32];
    #pragma unroll
    for (int off = 16; off; off >>= 1) acc += __shfl_xor_sync(0xffffffffu, acc, off);
    if (lane == 0) out[n] = acc + r2b[0];
}

// =====================================================================
extern "C" void kernel_launch(void* const* d_in, const int* in_sizes, int n_in,
                              void* d_out, int out_size) {
    const float* x    = (const float*)d_in[0];
    const int*   ei   = (const int*)  d_in[1];
    const float* mpw  = (const float*)d_in[2];
    const float* W0   = (const float*)d_in[3];
    const float* b0   = (const float*)d_in[4];
    const float* Wl   = (const float*)d_in[5];
    const float* bl   = (const float*)d_in[6];
    const float* W1   = (const float*)d_in[7];
    const float* b1   = (const float*)d_in[8];
    const float* Wo   = (const float*)d_in[9];
    const float* bo   = (const float*)d_in[10];
    const float* tinw = (const float*)d_in[11];
    const float* tinb = (const float*)d_in[12];
    const float* tow  = (const float*)d_in[13];
    const float* tob  = (const float*)d_in[14];
    const float* ln1g = (const float*)d_in[15];
    const float* ln1b = (const float*)d_in[16];
    const float* ff1w = (const float*)d_in[17];
    const float* ff1b = (const float*)d_in[18];
    const float* ff2w = (const float*)d_in[19];
    const float* ff2b = (const float*)d_in[20];
    const float* ln2g = (const float*)d_in[21];
    const float* ln2b = (const float*)d_in[22];
    const float* r1w  = (const float*)d_in[23];
    const float* r1b  = (const float*)d_in[24];
    const float* r2w  = (const float*)d_in[25];
    const float* r2b  = (const float*)d_in[26];
    float* out = (float*)d_out;
    (void)in_sizes; (void)n_in; (void)out_size;

    cudaFuncSetAttribute(k_xw,   cudaFuncAttributeMaxDynamicSharedMemorySize, 17984 * 4);
    cudaFuncSetAttribute(k_attn, cudaFuncAttributeMaxDynamicSharedMemorySize, 31104 * 4);
    cudaFuncSetAttribute(k_ff,   cudaFuncAttributeMaxDynamicSharedMemorySize, 46144 * 4);

    // launch order: ncu (-s 5 -c 1) captures k_ff (6th launch)
    dim3 gx(469, 4);
    k_xw<<<gx, 256, 17984 * 4>>>(x, W0, b0, Wl, bl, W1, b1);                 // 1
    k_zero<<<7500, 256>>>();                                                 // 2
    k_scatter<<<120000, 256>>>(ei);                                          // 3
    k_gnn<<<gx, 256>>>(Wo, bo, mpw);                                         // 4
    k_attn<<<3750, 512, 31104 * 4>>>(tinw, tinb, tow, tob, ln1g, ln1b, 0);   // 5
    k_ff<<<NBLK, 512, 46144 * 4>>>(ff1w, ff1b, ff2w, ff2b, ln2g, ln2b, 0);   // 6 <- ncu
    k_attn<<<3750, 512, 31104 * 4>>>(tinw, tinb, tow, tob, ln1g, ln1b, 1);
    k_ff<<<NBLK, 512, 46144 * 4>>>(ff1w, ff1b, ff2w, ff2b, ln2g, ln2b, 1);
    k_head<<<3750, 256>>>(r1w, r1b, r2w, r2b, out);
}

// round 8
// speedup vs baseline: 3.9363x; 1.3314x over previous
#include <cuda_runtime.h>
#include <cuda_fp16.h>
#include <cstdint>

typedef unsigned long long ull;

#define NN   30000
#define INC  128
#define OC   64
#define MP   4
#define EE   480000
#define FFD  2048
#define TOK  (NN*MP)
#define TB   256                     // tokens per ff block
#define NBLK ((TOK + TB - 1) / TB)   // 469
#define TOKP (NBLK * TB)             // 120064 (padded)
#define JC   64                      // j per chunk
#define NCH  (FFD / JC)              // 32 chunks
#define LN_EPS 1e-5f

// ---- device scratch (allocation-free rule: __device__ globals) ----
__device__ float g_y[(size_t)MP * NN * OC];     // x @ Wl^T
__device__ float g_c[(size_t)MP * NN * OC];     // x @ Wc^T + bias
__device__ float g_aggY[(size_t)MP * NN * OC];  // scatter target
__device__ float g_e[(size_t)TOKP * OC];        // token embeddings

// ---- packed fp32x2 helpers (exact fp32 semantics) ----
__device__ __forceinline__ ull fma2(ull a, ull b, ull c) {
    ull d; asm("fma.rn.f32x2 %0, %1, %2, %3;" : "=l"(d) : "l"(a), "l"(b), "l"(c)); return d;
}
__device__ __forceinline__ ull splat2(float x) {
    ull v; asm("mov.b64 %0, {%1, %1};" : "=l"(v) : "f"(x)); return v;
}
__device__ __forceinline__ float2 u2f(ull v) {
    float2 f; asm("mov.b64 {%0, %1}, %2;" : "=f"(f.x), "=f"(f.y) : "l"(v)); return f;
}
__device__ __forceinline__ ull f2u(float x, float y) {
    ull v; asm("mov.b64 %0, {%1, %2};" : "=l"(v) : "f"(x), "f"(y)); return v;
}

// ---- fp16 mma helper (m16n8k16, f32 accumulate) ----
__device__ __forceinline__ void mma_f16(float* c, const unsigned* a, const unsigned* b) {
    asm volatile(
        "mma.sync.aligned.m16n8k16.row.col.f32.f16.f16.f32 "
        "{%0,%1,%2,%3}, {%4,%5,%6,%7}, {%8,%9}, {%0,%1,%2,%3};"
        : "+f"(c[0]), "+f"(c[1]), "+f"(c[2]), "+f"(c[3])
        : "r"(a[0]), "r"(a[1]), "r"(a[2]), "r"(a[3]), "r"(b[0]), "r"(b[1]));
}
// interleaved k-pair permutation within 16-groups: thread qc's pairs (qc, qc+4)
// land at half-positions 4qc..4qc+3 -> A/B frags are single LDS.64
__device__ __forceinline__ int hperm(int k) {
    return (k & ~15) | ((k & 6) << 1) | ((k & 8) >> 2) | (k & 1);
}

// =====================================================================
// K_xw: y[m] = x @ Wl[m]^T ; c[m] = x @ (W0[m]+W1[m])^T + bias
// =====================================================================
__global__ void __launch_bounds__(256, 1) k_xw(
    const float* __restrict__ x,
    const float* __restrict__ W0, const float* __restrict__ b0,
    const float* __restrict__ Wl, const float* __restrict__ bl,
    const float* __restrict__ W1, const float* __restrict__ b1)
{
    extern __shared__ float sm[];
    float* sWlT = sm;            // [128 k][66]
    float* sWcT = sm + 8448;     // [128 k][66]
    float* sB   = sm + 16896;    // 64
    float* sRow = sm + 16960;    // 8 warps * 128
    int t = threadIdx.x;
    int m = blockIdx.y;

    for (int i = t; i < 8192; i += 256) {
        int j = i >> 7, k = i & 127;
        size_t off = (size_t)m * 8192 + (size_t)j * 128 + k;
        sWlT[k * 66 + j] = Wl[off];
        sWcT[k * 66 + j] = W0[off] + W1[off];
    }
    if (t < 64) sB[t] = bl[m * 64 + t] + b0[m * 64 + t] + b1[m * 64 + t];
    __syncthreads();

    int w = t >> 5, lane = t & 31;
    float* row = sRow + w * 128;

    for (int n = blockIdx.x * 8 + w; n < NN; n += gridDim.x * 8) {
        ((float4*)row)[lane] = ((const float4*)(x + (size_t)n * INC))[lane];
        __syncwarp();
        ull ay = 0ull;
        ull ac = f2u(sB[2 * lane], sB[2 * lane + 1]);
        #pragma unroll 4
        for (int k = 0; k < 128; k++) {
            ull xv = splat2(row[k]);
            ull wl = *(const ull*)(sWlT + k * 66 + 2 * lane);
            ull wc = *(const ull*)(sWcT + k * 66 + 2 * lane);
            ay = fma2(wl, xv, ay);
            ac = fma2(wc, xv, ac);
        }
        size_t base = ((size_t)m * NN + n) * OC;
        *(float2*)(g_y + base + 2 * lane) = u2f(ay);
        *(float2*)(g_c + base + 2 * lane) = u2f(ac);
        __syncwarp();
    }
}

// =====================================================================
// K0: zero aggY buffer
// =====================================================================
__global__ void k_zero() {
    size_t i = (size_t)blockIdx.x * 256 + threadIdx.x;
    ((float4*)g_aggY)[i] = make_float4(0.f, 0.f, 0.f, 0.f);
}

// =====================================================================
// K1: edge scatter: aggY[m][src] += y[m][dst]. half-warp per edge.
// =====================================================================
__global__ void k_scatter(const int* __restrict__ ei) {
    int wid  = (blockIdx.x * blockDim.x + threadIdx.x) >> 5;
    int lane = threadIdx.x & 31;
    int pair = lane >> 4;
    int sub  = lane & 15;
    int eg = wid * 2 + pair;
    int m = eg / EE;
    int e = eg - m * EE;
    const int* b = ei + (size_t)m * 2 * EE;
    int src = __ldg(b + e);
    int dst = __ldg(b + EE + e);
    float4 v = ((const float4*)(g_y + ((size_t)m * NN + dst) * OC))[sub];
    atomicAdd(((float4*)(g_aggY + ((size_t)m * NN + src) * OC)) + sub, v);
}

// =====================================================================
// K2: GNN tail: h = relu(aggY + c); e_m = (h@Wo^T + bo)*mpw
// =====================================================================
__global__ void __launch_bounds__(256, 1) k_gnn(
    const float* __restrict__ Wo, const float* __restrict__ bo,
    const float* __restrict__ mpw)
{
    __shared__ float sWoT[64 * 66];
    __shared__ float sBo[64];
    __shared__ float sH[8 * 64];
    int t = threadIdx.x;
    int m = blockIdx.y;

    for (int i = t; i < 4096; i += 256) {
        int j = i >> 6, k = i & 63;
        sWoT[k * 66 + j] = Wo[(size_t)m * 4096 + j * 64 + k];
    }
    if (t < 64) sBo[t] = bo[m * 64 + t];
    __syncthreads();

    float wgt = mpw[m];
    int w = t >> 5, lane = t & 31;
    float* hrow = sH + w * 64;

    for (int n = blockIdx.x * 8 + w; n < NN; n += gridDim.x * 8) {
        size_t base = ((size_t)m * NN + n) * OC;
        hrow[lane]      = fmaxf(g_aggY[base + lane]      + g_c[base + lane], 0.f);
        hrow[lane + 32] = fmaxf(g_aggY[base + lane + 32] + g_c[base + lane + 32], 0.f);
        __syncwarp();
        ull o = f2u(sBo[2 * lane], sBo[2 * lane + 1]);
        #pragma unroll 8
        for (int i = 0; i < 64; i++) {
            o = fma2(*(const ull*)(sWoT + i * 66 + 2 * lane), splat2(hrow[i]), o);
        }
        float2 f = u2f(o);
        *(float2*)(g_e + ((size_t)n * MP + m) * OC + 2 * lane) =
            make_float2(f.x * wgt, f.y * wgt);
        __syncwarp();
    }
}

// =====================================================================
// K3: attention sublayer, 8 nodes per block (512 threads), fma2 packed.
// =====================================================================
__global__ void __launch_bounds__(512, 1) k_attn(
    const float* __restrict__ tinw, const float* __restrict__ tinb,
    const float* __restrict__ tow,  const float* __restrict__ tob,
    const float* __restrict__ g1,   const float* __restrict__ b1v, int l)
{
    extern __shared__ float sm[];
    float* sTinT = sm;           // [64 k][193]
    float* sTowT = sm + 12352;   // [64 i][65]
    float* sTinB = sm + 16512;   // 192
    float* sToB  = sm + 16704;   // 64
    float* sE    = sm + 16768;   // 8 * 256
    float* sEkT  = sm + 18816;   // 8 * 384
    float* sQKV  = sm + 21888;   // 8 * 768
    float* sAO   = sm + 28032;   // 8 * 384
    int t = threadIdx.x;

    const float* tw = tinw + (size_t)l * 192 * 64;
    for (int i = t; i < 12288; i += 512) {
        int r = i >> 6, k = i & 63;
        sTinT[k * 193 + r] = tw[r * 64 + k];
    }
    const float* twO = tow + (size_t)l * 64 * 64;
    for (int i = t; i < 4096; i += 512) {
        int j = i >> 6, k = i & 63;
        sTowT[k * 65 + j] = twO[j * 64 + k];
    }
    if (t < 192) sTinB[t] = tinb[l * 192 + t];
    if (t >= 192 && t < 256) sToB[t - 192] = tob[l * 64 + (t - 192)];

    int s = t >> 6, tt = t & 63;
    int node = blockIdx.x * 8 + s;
    float* eN   = sE + s * 256;
    float* eKT  = sEkT + s * 384;
    float* qkvN = sQKV + s * 768;
    float* aoT  = sAO + s * 384;
    for (int i = tt; i < 256; i += 64) {
        float v = g_e[(size_t)node * 256 + i];
        eN[i] = v;
        eKT[(i & 63) * 6 + (i >> 6)] = v;
    }
    __syncthreads();

    {
        ull q01 = splat2(sTinB[tt]),       q23 = q01;
        ull k01 = splat2(sTinB[64 + tt]),  k23 = k01;
        ull v01 = splat2(sTinB[128 + tt]), v23 = v01;
        #pragma unroll 4
        for (int k = 0; k < 64; k++) {
            ull e01 = *(const ull*)(eKT + k * 6);
            ull e23 = *(const ull*)(eKT + k * 6 + 2);
            ull wq = splat2(sTinT[k * 193 + tt]);
            ull wk = splat2(sTinT[k * 193 + 64 + tt]);
            ull wv = splat2(sTinT[k * 193 + 128 + tt]);
            q01 = fma2(e01, wq, q01); q23 = fma2(e23, wq, q23);
            k01 = fma2(e01, wk, k01); k23 = fma2(e23, wk, k23);
            v01 = fma2(e01, wv, v01); v23 = fma2(e23, wv, v23);
        }
        float2 f;
        f = u2f(q01); qkvN[tt]             = f.x; qkvN[192 + tt]       = f.y;
        f = u2f(q23); qkvN[384 + tt]       = f.x; qkvN[576 + tt]       = f.y;
        f = u2f(k01); qkvN[64 + tt]        = f.x; qkvN[192 + 64 + tt]  = f.y;
        f = u2f(k23); qkvN[384 + 64 + tt]  = f.x; qkvN[576 + 64 + tt]  = f.y;
        f = u2f(v01); qkvN[128 + tt]       = f.x; qkvN[192 + 128 + tt] = f.y;
        f = u2f(v23); qkvN[384 + 128 + tt] = f.x; qkvN[576 + 128 + tt] = f.y;
    }
    __syncthreads();

    if (tt < 32) {
        int h = tt >> 2, mq = tt & 3;
        float q[8];
        #pragma unroll
        for (int d = 0; d < 8; d++) q[d] = qkvN[mq * 192 + h * 8 + d];
        float sc[4];
        #pragma unroll
        for (int mk = 0; mk < 4; mk++) {
            float a = 0.f;
            #pragma unroll
            for (int d = 0; d < 8; d++) a = fmaf(q[d], qkvN[mk * 192 + 64 + h * 8 + d], a);
            sc[mk] = a * 0.35355339059327373f;
        }
        float mx = fmaxf(fmaxf(sc[0], sc[1]), fmaxf(sc[2], sc[3]));
        float p[4]; float psum = 0.f;
        #pragma unroll
        for (int mk = 0; mk < 4; mk++) { p[mk] = __expf(sc[mk] - mx); psum += p[mk]; }
        float inv = 1.0f / psum;
        #pragma unroll
        for (int d = 0; d < 8; d++) {
            float o = 0.f;
            #pragma unroll
            for (int mk = 0; mk < 4; mk++) o = fmaf(p[mk] * inv, qkvN[mk * 192 + 128 + h * 8 + d], o);
            aoT[(h * 8 + d) * 6 + mq] = o;
        }
    }
    __syncthreads();

    {
        ull a01 = splat2(sToB[tt]), a23 = a01;
        #pragma unroll 4
        for (int i = 0; i < 64; i++) {
            ull h01 = *(const ull*)(aoT + i * 6);
            ull h23 = *(const ull*)(aoT + i * 6 + 2);
            ull wv = splat2(sTowT[i * 65 + tt]);
            a01 = fma2(h01, wv, a01);
            a23 = fma2(h23, wv, a23);
        }
        float2 f0 = u2f(a01), f1 = u2f(a23);
        eN[tt]       += f0.x;
        eN[64 + tt]  += f0.y;
        eN[128 + tt] += f1.x;
        eN[192 + tt] += f1.y;
    }
    __syncthreads();

    int tl = t >> 4, part = t & 15;
    int ss = tl >> 2, m2 = tl & 3;
    const float* base = sE + ss * 256 + m2 * 64;
    float sum = 0.f, sq = 0.f;
    #pragma unroll
    for (int i2 = 0; i2 < 4; i2++) { float v = base[part * 4 + i2]; sum += v; sq += v * v; }
    #pragma unroll
    for (int off = 1; off < 16; off <<= 1) {
        sum += __shfl_xor_sync(0xffffffffu, sum, off);
        sq  += __shfl_xor_sync(0xffffffffu, sq,  off);
    }
    float mu   = sum * (1.f / 64.f);
    float rstd = rsqrtf(sq * (1.f / 64.f) - mu * mu + LN_EPS);
    int nodeW = blockIdx.x * 8 + ss;
    #pragma unroll
    for (int i2 = 0; i2 < 4; i2++) {
        int c = part * 4 + i2;
        float v = base[c];
        g_e[((size_t)nodeW * 4 + m2) * 64 + c] = (v - mu) * rstd * g1[l * 64 + c] + b1v[l * 64 + c];
    }
}

// =====================================================================
// K4: FF sublayer on FP16 tensor cores (m16n8k16, fp32 accumulate).
// 256-token tile, 32 chunks of 64 j. 16 warps = 8 m-strips x 2 halves.
// half2 smem with interleaved k-pairs (pitch 80 halves): A/B frags = 1 LDS.64.
// =====================================================================
__global__ void __launch_bounds__(512, 1) k_ff(
    const float* __restrict__ ff1w, const float* __restrict__ ff1b,
    const float* __restrict__ ff2w, const float* __restrict__ ff2b,
    const float* __restrict__ g2,   const float* __restrict__ b2, int l)
{
    extern __shared__ char smb[];
    __half* sE  = (__half*)smb;              // [256][80]h = 40960B
    __half* sH  = (__half*)(smb + 40960);    // [256][80]h = 40960B
    __half* sW1 = (__half*)(smb + 81920);    // [64][80]h  = 10240B
    __half* sW2 = (__half*)(smb + 92160);    // [64][80]h  = 10240B
    float*  sB1 = (float*)(smb + 102400);    // 64 floats
    float*  sO  = (float*)smb;               // alias epilogue [256][72]f = 73728B
    int t = threadIdx.x, w = t >> 5, lane = t & 31;
    int qr = lane >> 2, qc = lane & 3;
    size_t tok0 = (size_t)blockIdx.x * TB;
    int mrow = (w & 7) * 32;         // 32-token m-strip
    int nh   = w >> 3;               // 0/1 half
    int nbase = nh * 32;

    const float* f1w = ff1w + (size_t)l * FFD * OC;
    const float* f1b = ff1b + (size_t)l * FFD;
    const float* f2w = ff2w + (size_t)l * OC * FFD;

    // stage E tile (fp16, perm pairs) + chunk-0 weights
    for (int i = t; i < TB * 32; i += 512) {         // float2 granules
        int row = i >> 5, kk = (i & 31) * 2;
        float2 f = *(const float2*)(g_e + tok0 * 64 + (size_t)row * 64 + kk);
        *(__half2*)(sE + row * 80 + hperm(kk)) = __floats2half2_rn(f.x, f.y);
    }
    for (int i = t; i < JC * 32; i += 512) {
        int j = i >> 5, kk = (i & 31) * 2;
        float2 f = *(const float2*)(f1w + (size_t)j * 64 + kk);
        *(__half2*)(sW1 + j * 80 + hperm(kk)) = __floats2half2_rn(f.x, f.y);
    }
    for (int i = t; i < 64 * 32; i += 512) {
        int c = i >> 5, jj = (i & 31) * 2;
        float2 f = *(const float2*)(f2w + (size_t)c * FFD + jj);
        *(__half2*)(sW2 + c * 80 + hperm(jj)) = __floats2half2_rn(f.x, f.y);
    }
    if (t < 64) sB1[t] = f1b[t];
    __syncthreads();

    float acc2[2][4][4];
    #pragma unroll
    for (int mt = 0; mt < 2; mt++)
        #pragma unroll
        for (int nt = 0; nt < 4; nt++)
            #pragma unroll
            for (int q = 0; q < 4; q++) acc2[mt][nt][q] = 0.f;

    for (int ch = 0; ch < NCH; ch++) {
        int jb2 = (ch + 1) * JC;
        // prefetch W1(ch+1)+B1(ch+1) during GEMM1
        float2 w1n[4]; float b1n = 0.f;
        if (ch < NCH - 1) {
            #pragma unroll
            for (int r = 0; r < 4; r++) {
                int idx = t + r * 512;
                int j = idx >> 5, kk = (idx & 31) * 2;
                w1n[r] = *(const float2*)(f1w + (size_t)(jb2 + j) * 64 + kk);
            }
            if (t < 64) b1n = f1b[jb2 + t];
        }

        // ---- GEMM1: H(256 x 64j) = relu(E @ W1^T + b1) ----
        float acc1[2][4][4];
        #pragma unroll
        for (int nt = 0; nt < 4; nt++) {
            float bv0 = sB1[nbase + nt * 8 + 2 * qc];
            float bv1 = sB1[nbase + nt * 8 + 2 * qc + 1];
            #pragma unroll
            for (int mt = 0; mt < 2; mt++) {
                acc1[mt][nt][0] = bv0; acc1[mt][nt][1] = bv1;
                acc1[mt][nt][2] = bv0; acc1[mt][nt][3] = bv1;
            }
        }
        #pragma unroll
        for (int k0 = 0; k0 < 64; k0 += 16) {
            unsigned a[2][4];
            #pragma unroll
            for (int mt = 0; mt < 2; mt++) {
                int r0 = mrow + mt * 16;
                ull vlo = *(const ull*)(sE + (r0 + qr) * 80 + k0 + 4 * qc);
                ull vhi = *(const ull*)(sE + (r0 + 8 + qr) * 80 + k0 + 4 * qc);
                a[mt][0] = (unsigned)vlo; a[mt][2] = (unsigned)(vlo >> 32);
                a[mt][1] = (unsigned)vhi; a[mt][3] = (unsigned)(vhi >> 32);
            }
            #pragma unroll
            for (int nt = 0; nt < 4; nt++) {
                ull bv = *(const ull*)(sW1 + (nbase + nt * 8 + qr) * 80 + k0 + 4 * qc);
                unsigned b[2] = { (unsigned)bv, (unsigned)(bv >> 32) };
                mma_f16(acc1[0][nt], a[0], b);
                mma_f16(acc1[1][nt], a[1], b);
            }
        }
        // relu + fp16 + store H (half2, perm pairs)
        #pragma unroll
        for (int nt = 0; nt < 4; nt++) {
            int jcol = nbase + nt * 8 + 2 * qc;
            int jpos = hperm(jcol);
            #pragma unroll
            for (int mt = 0; mt < 2; mt++) {
                int r0 = mrow + mt * 16 + qr;
                *(__half2*)(sH + r0 * 80 + jpos) = __floats2half2_rn(
                    fmaxf(acc1[mt][nt][0], 0.f), fmaxf(acc1[mt][nt][1], 0.f));
                *(__half2*)(sH + (r0 + 8) * 80 + jpos) = __floats2half2_rn(
                    fmaxf(acc1[mt][nt][2], 0.f), fmaxf(acc1[mt][nt][3], 0.f));
            }
        }
        __syncthreads();   // sync1: H visible; sW1/sB1 free

        // store prefetched W1/B1; prefetch W2(ch+1)
        float2 w2n[4];
        if (ch < NCH - 1) {
            #pragma unroll
            for (int r = 0; r < 4; r++) {
                int idx = t + r * 512;
                int j = idx >> 5, kk = (idx & 31) * 2;
                *(__half2*)(sW1 + j * 80 + hperm(kk)) = __floats2half2_rn(w1n[r].x, w1n[r].y);
            }
            if (t < 64) sB1[t] = b1n;
            #pragma unroll
            for (int r = 0; r < 4; r++) {
                int idx = t + r * 512;
                int c = idx >> 5, jj = (idx & 31) * 2;
                w2n[r] = *(const float2*)(f2w + (size_t)c * FFD + jb2 + jj);
            }
        }

        // ---- GEMM2: O(256 x 64c) += H @ W2^T (K = 64 j of this chunk) ----
        #pragma unroll
        for (int k0 = 0; k0 < 64; k0 += 16) {
            unsigned a[2][4];
            #pragma unroll
            for (int mt = 0; mt < 2; mt++) {
                int r0 = mrow + mt * 16;
                ull vlo = *(const ull*)(sH + (r0 + qr) * 80 + k0 + 4 * qc);
                ull vhi = *(const ull*)(sH + (r0 + 8 + qr) * 80 + k0 + 4 * qc);
                a[mt][0] = (unsigned)vlo; a[mt][2] = (unsigned)(vlo >> 32);
                a[mt][1] = (unsigned)vhi; a[mt][3] = (unsigned)(vhi >> 32);
            }
            #pragma unroll
            for (int nt = 0; nt < 4; nt++) {
                ull bv = *(const ull*)(sW2 + (nbase + nt * 8 + qr) * 80 + k0 + 4 * qc);
                unsigned b[2] = { (unsigned)bv, (unsigned)(bv >> 32) };
                mma_f16(acc2[0][nt], a[0], b);
                mma_f16(acc2[1][nt], a[1], b);
            }
        }
        __syncthreads();   // sync2: sH/sW2 free

        if (ch < NCH - 1) {
            #pragma unroll
            for (int r = 0; r < 4; r++) {
                int idx = t + r * 512;
                int c = idx >> 5, jj = (idx & 31) * 2;
                *(__half2*)(sW2 + c * 80 + hperm(jj)) = __floats2half2_rn(w2n[r].x, w2n[r].y);
            }
        }
    }

    // ---- epilogue: bias + residual (exact fp32 from g_e) -> sO, then LN2 ----
    #pragma unroll
    for (int nt = 0; nt < 4; nt++) {
        int col = nbase + nt * 8 + 2 * qc;
        float bias0 = ff2b[l * OC + col];
        float bias1 = ff2b[l * OC + col + 1];
        #pragma unroll
        for (int mt = 0; mt < 2; mt++) {
            int r0 = mrow + mt * 16 + qr;
            int r1 = r0 + 8;
            float2 e0 = *(const float2*)(g_e + (tok0 + r0) * 64 + col);
            float2 e1 = *(const float2*)(g_e + (tok0 + r1) * 64 + col);
            sO[r0 * 72 + col]     = acc2[mt][nt][0] + bias0 + e0.x;
            sO[r0 * 72 + col + 1] = acc2[mt][nt][1] + bias1 + e0.y;
            sO[r1 * 72 + col]     = acc2[mt][nt][2] + bias0 + e1.x;
            sO[r1 * 72 + col + 1] = acc2[mt][nt][3] + bias1 + e1.y;
        }
    }
    __syncthreads();

    // LN2: 2 threads per token (256 tokens)
    int tk2 = t >> 1, half = t & 1;
    const float* ob = sO + tk2 * 72 + half * 32;
    float s = 0.f, s2 = 0.f;
    #pragma unroll
    for (int i = 0; i < 32; i++) { float v = ob[i]; s += v; s2 += v * v; }
    s  += __shfl_xor_sync(0xffffffffu, s, 1);
    s2 += __shfl_xor_sync(0xffffffffu, s2, 1);
    float mu   = s * (1.f / 64.f);
    float rstd = rsqrtf(s2 * (1.f / 64.f) - mu * mu + LN_EPS);
    float* go = g_e + (tok0 + tk2) * 64 + half * 32;
    #pragma unroll
    for (int i = 0; i < 32; i++) {
        int c = half * 32 + i;
        go[i] = (ob[i] - mu) * rstd * g2[l * OC + c] + b2[l * OC + c];
    }
}

// =====================================================================
// K5: head
// =====================================================================
__global__ void __launch_bounds__(256) k_head(
    const float* __restrict__ r1w, const float* __restrict__ r1b,
    const float* __restrict__ r2w, const float* __restrict__ r2b,
    float* __restrict__ out)
{
    __shared__ float sR1T[64 * 65];
    __shared__ float sR2[64];
    __shared__ float sP[8][64];
    int t = threadIdx.x;
    for (int i = t; i < 4096; i += 256) {
        int c = i >> 6, k = i & 63;
        sR1T[k * 65 + c] = r1w[c * 64 + k];
    }
    if (t < 64) sR2[t] = r2w[t];
    __syncthreads();
    int w = t >> 5, lane = t & 31;
    int n = blockIdx.x * 8 + w;
    const float* eb = g_e + (size_t)n * 256;
    float p0 = (eb[lane] + eb[64 + lane] + eb[128 + lane] + eb[192 + lane]) * 0.25f;
    float p1 = (eb[32 + lane] + eb[96 + lane] + eb[160 + lane] + eb[224 + lane]) * 0.25f;
    sP[w][lane]      = p0;
    sP[w][lane + 32] = p1;
    __syncwarp();
    float a0 = r1b[lane], a1 = r1b[lane + 32];
    #pragma unroll 8
    for (int k = 0; k < 64; k++) {
        float pv = sP[w][k];
        a0 = fmaf(pv, sR1T[k * 65 + lane], a0);
        a1 = fmaf(pv, sR1T[k * 65 + lane + 32], a1);
    }
    a0 = fmaxf(a0, 0.f); a1 = fmaxf(a1, 0.f);
    float acc = a0 * sR2[lane] + a1 * sR2[lane + 32];
    #pragma unroll
    for (int off = 16; off; off >>= 1) acc += __shfl_xor_sync(0xffffffffu, acc, off);
    if (lane == 0) out[n] = acc + r2b[0];
}

// =====================================================================
extern "C" void kernel_launch(void* const* d_in, const int* in_sizes, int n_in,
                              void* d_out, int out_size) {
    const float* x    = (const float*)d_in[0];
    const int*   ei   = (const int*)  d_in[1];
    const float* mpw  = (const float*)d_in[2];
    const float* W0   = (const float*)d_in[3];
    const float* b0   = (const float*)d_in[4];
    const float* Wl   = (const float*)d_in[5];
    const float* bl   = (const float*)d_in[6];
    const float* W1   = (const float*)d_in[7];
    const float* b1   = (const float*)d_in[8];
    const float* Wo   = (const float*)d_in[9];
    const float* bo   = (const float*)d_in[10];
    const float* tinw = (const float*)d_in[11];
    const float* tinb = (const float*)d_in[12];
    const float* tow  = (const float*)d_in[13];
    const float* tob  = (const float*)d_in[14];
    const float* ln1g = (const float*)d_in[15];
    const float* ln1b = (const float*)d_in[16];
    const float* ff1w = (const float*)d_in[17];
    const float* ff1b = (const float*)d_in[18];
    const float* ff2w = (const float*)d_in[19];
    const float* ff2b = (const float*)d_in[20];
    const float* ln2g = (const float*)d_in[21];
    const float* ln2b = (const float*)d_in[22];
    const float* r1w  = (const float*)d_in[23];
    const float* r1b  = (const float*)d_in[24];
    const float* r2w  = (const float*)d_in[25];
    const float* r2b  = (const float*)d_in[26];
    float* out = (float*)d_out;
    (void)in_sizes; (void)n_in; (void)out_size;

    cudaFuncSetAttribute(k_xw,   cudaFuncAttributeMaxDynamicSharedMemorySize, 17984 * 4);
    cudaFuncSetAttribute(k_attn, cudaFuncAttributeMaxDynamicSharedMemorySize, 31104 * 4);
    cudaFuncSetAttribute(k_ff,   cudaFuncAttributeMaxDynamicSharedMemorySize, 102656);

    // launch order: ncu (-s 5 -c 1) captures k_ff (6th launch)
    dim3 gx(469, 4);
    k_xw<<<gx, 256, 17984 * 4>>>(x, W0, b0, Wl, bl, W1, b1);                 // 1
    k_zero<<<7500, 256>>>();                                                 // 2
    k_scatter<<<120000, 256>>>(ei);                                          // 3
    k_gnn<<<gx, 256>>>(Wo, bo, mpw);                                         // 4
    k_attn<<<3750, 512, 31104 * 4>>>(tinw, tinb, tow, tob, ln1g, ln1b, 0);   // 5
    k_ff<<<NBLK, 512, 102656>>>(ff1w, ff1b, ff2w, ff2b, ln2g, ln2b, 0);      // 6 <- ncu
    k_attn<<<3750, 512, 31104 * 4>>>(tinw, tinb, tow, tob, ln1g, ln1b, 1);
    k_ff<<<NBLK, 512, 102656>>>(ff1w, ff1b, ff2w, ff2b, ln2g, ln2b, 1);
    k_head<<<3750, 256>>>(r1w, r1b, r2w, r2b, out);
}

// round 9
// speedup vs baseline: 5.1396x; 1.3057x over previous
#include <cuda_runtime.h>
#include <cuda_fp16.h>
#include <cstdint>

typedef unsigned long long ull;

#define NN   30000
#define INC  128
#define OC   64
#define MP   4
#define EE   480000
#define FFD  2048
#define TOK  (NN*MP)
#define TB   256                     // tokens per ff/attn block
#define NBLK ((TOK + TB - 1) / TB)   // 469
#define TOKP (NBLK * TB)             // 120064 (padded)
#define JC   64                      // j per chunk (ff)
#define NCH  (FFD / JC)              // 32 chunks
#define LN_EPS 1e-5f

// ---- device scratch (allocation-free rule: __device__ globals) ----
__device__ float g_y[(size_t)MP * NN * OC];     // x @ Wl^T
__device__ float g_c[(size_t)MP * NN * OC];     // x @ Wc^T + bias
__device__ float g_aggY[(size_t)MP * NN * OC];  // scatter target
__device__ float g_e[(size_t)TOKP * OC];        // token embeddings

// ---- packed fp32x2 helpers (exact fp32 semantics) ----
__device__ __forceinline__ ull fma2(ull a, ull b, ull c) {
    ull d; asm("fma.rn.f32x2 %0, %1, %2, %3;" : "=l"(d) : "l"(a), "l"(b), "l"(c)); return d;
}
__device__ __forceinline__ ull splat2(float x) {
    ull v; asm("mov.b64 %0, {%1, %1};" : "=l"(v) : "f"(x)); return v;
}
__device__ __forceinline__ float2 u2f(ull v) {
    float2 f; asm("mov.b64 {%0, %1}, %2;" : "=f"(f.x), "=f"(f.y) : "l"(v)); return f;
}
__device__ __forceinline__ ull f2u(float x, float y) {
    ull v; asm("mov.b64 %0, {%1, %2};" : "=l"(v) : "f"(x), "f"(y)); return v;
}

// ---- fp16 mma helper (m16n8k16, f32 accumulate) ----
__device__ __forceinline__ void mma_f16(float* c, const unsigned* a, const unsigned* b) {
    asm volatile(
        "mma.sync.aligned.m16n8k16.row.col.f32.f16.f16.f32 "
        "{%0,%1,%2,%3}, {%4,%5,%6,%7}, {%8,%9}, {%0,%1,%2,%3};"
        : "+f"(c[0]), "+f"(c[1]), "+f"(c[2]), "+f"(c[3])
        : "r"(a[0]), "r"(a[1]), "r"(a[2]), "r"(a[3]), "r"(b[0]), "r"(b[1]));
}
// interleaved k-pair permutation within 16-groups: thread qc's pairs (2qc,2qc+1,2qc+8,2qc+9)
// land at half-positions 4qc..4qc+3 -> A/B frags are single LDS.64
__device__ __forceinline__ int hperm(int k) {
    return (k & ~15) | ((k & 6) << 1) | ((k & 8) >> 2) | (k & 1);
}

// =====================================================================
// K_xw on fp16 tensor cores: y[m] = x @ Wl[m]^T ; c[m] = x @ Wc[m]^T + bias
// 256-node tile; B = [Wl (rows 0-63) ; Wc (rows 64-127)], K=128.
// pitch 144 halves (72 words % 32 == 8 -> conflict-free frags).
// =====================================================================
__global__ void __launch_bounds__(512, 1) k_xw(
    const float* __restrict__ x,
    const float* __restrict__ W0, const float* __restrict__ b0,
    const float* __restrict__ Wl, const float* __restrict__ bl,
    const float* __restrict__ W1, const float* __restrict__ b1)
{
    extern __shared__ char smb[];
    __half* sX = (__half*)smb;               // [256][144]h = 73728B
    __half* sW = (__half*)(smb + 73728);     // [128][144]h = 36864B
    float*  sB = (float*)(smb + 110592);     // 64 floats
    int t = threadIdx.x, w = t >> 5, lane = t & 31;
    int qr = lane >> 2, qc = lane & 3;
    int m = blockIdx.y;
    int node0 = blockIdx.x * 256;

    // stage x tile (rows clamped for tail block)
    for (int i = t; i < 256 * 64; i += 512) {
        int row = i >> 6, kk = (i & 63) * 2;
        int gn = node0 + row; if (gn >= NN) gn = NN - 1;
        float2 f = *(const float2*)(x + (size_t)gn * INC + kk);
        *(__half2*)(sX + row * 144 + hperm(kk)) = __floats2half2_rn(f.x, f.y);
    }
    // stage weights: rows 0-63 Wl, rows 64-127 W0+W1
    for (int i = t; i < 128 * 64; i += 512) {
        int r = i >> 6, kk = (i & 63) * 2;
        float2 f;
        if (r < 64) {
            f = *(const float2*)(Wl + (size_t)m * 8192 + (size_t)r * 128 + kk);
        } else {
            float2 a = *(const float2*)(W0 + (size_t)m * 8192 + (size_t)(r - 64) * 128 + kk);
            float2 b = *(const float2*)(W1 + (size_t)m * 8192 + (size_t)(r - 64) * 128 + kk);
            f = make_float2(a.x + b.x, a.y + b.y);
        }
        *(__half2*)(sW + r * 144 + hperm(kk)) = __floats2half2_rn(f.x, f.y);
    }
    if (t < 64) sB[t] = b0[m * 64 + t] + bl[m * 64 + t] + b1[m * 64 + t];
    __syncthreads();

    int mrow = (w & 7) * 32;
    int nh   = w >> 3;          // 0 -> y, 1 -> c

    float acc[2][8][4];
    #pragma unroll
    for (int nt = 0; nt < 8; nt++) {
        float bv0 = 0.f, bv1 = 0.f;
        if (nh == 1) { bv0 = sB[nt * 8 + 2 * qc]; bv1 = sB[nt * 8 + 2 * qc + 1]; }
        #pragma unroll
        for (int mt = 0; mt < 2; mt++) {
            acc[mt][nt][0] = bv0; acc[mt][nt][1] = bv1;
            acc[mt][nt][2] = bv0; acc[mt][nt][3] = bv1;
        }
    }
    #pragma unroll
    for (int k0 = 0; k0 < 128; k0 += 16) {
        unsigned a[2][4];
        #pragma unroll
        for (int mt = 0; mt < 2; mt++) {
            int r0 = mrow + mt * 16;
            ull vlo = *(const ull*)(sX + (r0 + qr) * 144 + k0 + 4 * qc);
            ull vhi = *(const ull*)(sX + (r0 + 8 + qr) * 144 + k0 + 4 * qc);
            a[mt][0] = (unsigned)vlo; a[mt][2] = (unsigned)(vlo >> 32);
            a[mt][1] = (unsigned)vhi; a[mt][3] = (unsigned)(vhi >> 32);
        }
        #pragma unroll
        for (int nt = 0; nt < 8; nt++) {
            ull bv = *(const ull*)(sW + (nh * 64 + nt * 8 + qr) * 144 + k0 + 4 * qc);
            unsigned b[2] = { (unsigned)bv, (unsigned)(bv >> 32) };
            mma_f16(acc[0][nt], a[0], b);
            mma_f16(acc[1][nt], a[1], b);
        }
    }
    // store
    float* dst = nh ? g_c : g_y;
    #pragma unroll
    for (int nt = 0; nt < 8; nt++) {
        int col = nt * 8 + 2 * qc;
        #pragma unroll
        for (int mt = 0; mt < 2; mt++) {
            int r0 = mrow + mt * 16 + qr;
            int n0 = node0 + r0, n1 = n0 + 8;
            if (n0 < NN)
                *(float2*)(dst + ((size_t)m * NN + n0) * OC + col) =
                    make_float2(acc[mt][nt][0], acc[mt][nt][1]);
            if (n1 < NN)
                *(float2*)(dst + ((size_t)m * NN + n1) * OC + col) =
                    make_float2(acc[mt][nt][2], acc[mt][nt][3]);
        }
    }
}

// =====================================================================
// K0: zero aggY buffer
// =====================================================================
__global__ void k_zero() {
    size_t i = (size_t)blockIdx.x * 256 + threadIdx.x;
    ((float4*)g_aggY)[i] = make_float4(0.f, 0.f, 0.f, 0.f);
}

// =====================================================================
// K1: edge scatter: aggY[m][src] += y[m][dst]. half-warp per edge.
// =====================================================================
__global__ void k_scatter(const int* __restrict__ ei) {
    int wid  = (blockIdx.x * blockDim.x + threadIdx.x) >> 5;
    int lane = threadIdx.x & 31;
    int pair = lane >> 4;
    int sub  = lane & 15;
    int eg = wid * 2 + pair;
    int m = eg / EE;
    int e = eg - m * EE;
    const int* b = ei + (size_t)m * 2 * EE;
    int src = __ldg(b + e);
    int dst = __ldg(b + EE + e);
    float4 v = ((const float4*)(g_y + ((size_t)m * NN + dst) * OC))[sub];
    atomicAdd(((float4*)(g_aggY + ((size_t)m * NN + src) * OC)) + sub, v);
}

// =====================================================================
// K2: GNN tail: h = relu(aggY + c); e_m = (h@Wo^T + bo)*mpw
// =====================================================================
__global__ void __launch_bounds__(256, 1) k_gnn(
    const float* __restrict__ Wo, const float* __restrict__ bo,
    const float* __restrict__ mpw)
{
    __shared__ float sWoT[64 * 66];
    __shared__ float sBo[64];
    __shared__ float sH[8 * 64];
    int t = threadIdx.x;
    int m = blockIdx.y;

    for (int i = t; i < 4096; i += 256) {
        int j = i >> 6, k = i & 63;
        sWoT[k * 66 + j] = Wo[(size_t)m * 4096 + j * 64 + k];
    }
    if (t < 64) sBo[t] = bo[m * 64 + t];
    __syncthreads();

    float wgt = mpw[m];
    int w = t >> 5, lane = t & 31;
    float* hrow = sH + w * 64;

    for (int n = blockIdx.x * 8 + w; n < NN; n += gridDim.x * 8) {
        size_t base = ((size_t)m * NN + n) * OC;
        hrow[lane]      = fmaxf(g_aggY[base + lane]      + g_c[base + lane], 0.f);
        hrow[lane + 32] = fmaxf(g_aggY[base + lane + 32] + g_c[base + lane + 32], 0.f);
        __syncwarp();
        ull o = f2u(sBo[2 * lane], sBo[2 * lane + 1]);
        #pragma unroll 8
        for (int i = 0; i < 64; i++) {
            o = fma2(*(const ull*)(sWoT + i * 66 + 2 * lane), splat2(hrow[i]), o);
        }
        float2 f = u2f(o);
        *(float2*)(g_e + ((size_t)n * MP + m) * OC + 2 * lane) =
            make_float2(f.x * wgt, f.y * wgt);
        __syncwarp();
    }
}

// =====================================================================
// K3: attention sublayer on fp16 tensor cores. 64 nodes (256 tokens)/block.
// qkv GEMM (fp16) -> fp32 attention core -> proj GEMM (fp16) -> fp32
// residual (re-read g_e) + LN1.
// =====================================================================
__global__ void __launch_bounds__(512, 1) k_attn(
    const float* __restrict__ tinw, const float* __restrict__ tinb,
    const float* __restrict__ tow,  const float* __restrict__ tob,
    const float* __restrict__ g1,   const float* __restrict__ b1v, int l)
{
    extern __shared__ char smb[];
    __half* sE   = (__half*)smb;                 // [256][80]h = 40960 (alias sAO)
    __half* sWin = (__half*)(smb + 40960);       // [192][80]h = 30720
    __half* sQKV = (__half*)(smb + 71680);       // [64 node][768]h = 98304 (alias sO)
    __half* sWo  = (__half*)(smb + 169984);      // [64][80]h  = 10240
    float*  sBin = (float*)(smb + 180224);       // 192
    float*  sBo  = (float*)(smb + 180992);       // 64
    __half* sAO  = sE;                           // attention out, [256][80]h perm
    float*  sO   = (float*)(smb + 71680);        // epilogue [256][72]f = 73728
    int t = threadIdx.x, w = t >> 5, lane = t & 31;
    int qr = lane >> 2, qc = lane & 3;
    size_t tok0 = (size_t)blockIdx.x * TB;

    const float* tw  = tinw + (size_t)l * 192 * 64;
    const float* twO = tow  + (size_t)l * 64 * 64;
    for (int i = t; i < 192 * 32; i += 512) {
        int r = i >> 5, kk = (i & 31) * 2;
        float2 f = *(const float2*)(tw + (size_t)r * 64 + kk);
        *(__half2*)(sWin + r * 80 + hperm(kk)) = __floats2half2_rn(f.x, f.y);
    }
    for (int i = t; i < 64 * 32; i += 512) {
        int r = i >> 5, kk = (i & 31) * 2;
        float2 f = *(const float2*)(twO + (size_t)r * 64 + kk);
        *(__half2*)(sWo + r * 80 + hperm(kk)) = __floats2half2_rn(f.x, f.y);
    }
    for (int i = t; i < TB * 32; i += 512) {
        int row = i >> 5, kk = (i & 31) * 2;
        float2 f = *(const float2*)(g_e + (tok0 + row) * 64 + kk);
        *(__half2*)(sE + row * 80 + hperm(kk)) = __floats2half2_rn(f.x, f.y);
    }
    if (t < 192) sBin[t] = tinb[l * 192 + t];
    if (t >= 192 && t < 256) sBo[t - 192] = tob[l * 64 + (t - 192)];
    __syncthreads();

    int mrow = (w & 7) * 32;
    int nh   = w >> 3;

    // ---- qkv GEMM: [256 tok] x [192] = E @ Win^T + bin, 2 N-passes of 48 ----
    #pragma unroll
    for (int np = 0; np < 2; np++) {
        float acc[2][6][4];
        #pragma unroll
        for (int nt = 0; nt < 6; nt++) {
            int col = nh * 96 + np * 48 + nt * 8 + 2 * qc;
            float bv0 = sBin[col], bv1 = sBin[col + 1];
            #pragma unroll
            for (int mt = 0; mt < 2; mt++) {
                acc[mt][nt][0] = bv0; acc[mt][nt][1] = bv1;
                acc[mt][nt][2] = bv0; acc[mt][nt][3] = bv1;
            }
        }
        #pragma unroll
        for (int k0 = 0; k0 < 64; k0 += 16) {
            unsigned a[2][4];
            #pragma unroll
            for (int mt = 0; mt < 2; mt++) {
                int r0 = mrow + mt * 16;
                ull vlo = *(const ull*)(sE + (r0 + qr) * 80 + k0 + 4 * qc);
                ull vhi = *(const ull*)(sE + (r0 + 8 + qr) * 80 + k0 + 4 * qc);
                a[mt][0] = (unsigned)vlo; a[mt][2] = (unsigned)(vlo >> 32);
                a[mt][1] = (unsigned)vhi; a[mt][3] = (unsigned)(vhi >> 32);
            }
            #pragma unroll
            for (int nt = 0; nt < 6; nt++) {
                ull bv = *(const ull*)(sWin + (nh * 96 + np * 48 + nt * 8 + qr) * 80 + k0 + 4 * qc);
                unsigned b[2] = { (unsigned)bv, (unsigned)(bv >> 32) };
                mma_f16(acc[0][nt], a[0], b);
                mma_f16(acc[1][nt], a[1], b);
            }
        }
        // write qkv (fp16) to sQKV[node][m][192]
        #pragma unroll
        for (int nt = 0; nt < 6; nt++) {
            int col = nh * 96 + np * 48 + nt * 8 + 2 * qc;
            #pragma unroll
            for (int mt = 0; mt < 2; mt++) {
                int r0 = mrow + mt * 16 + qr;
                int r1 = r0 + 8;
                *(__half2*)(sQKV + (r0 >> 2) * 768 + (r0 & 3) * 192 + col) =
                    __floats2half2_rn(acc[mt][nt][0], acc[mt][nt][1]);
                *(__half2*)(sQKV + (r1 >> 2) * 768 + (r1 & 3) * 192 + col) =
                    __floats2half2_rn(acc[mt][nt][2], acc[mt][nt][3]);
            }
        }
    }
    __syncthreads();

    // ---- attention core (fp32 math on fp16 qkv), 2048 units = (node,h,mq) ----
    #pragma unroll
    for (int it = 0; it < 4; it++) {
        int u = it * 512 + t;
        int node = u >> 5, hd = (u >> 2) & 7, mq = u & 3;
        const __half* base = sQKV + node * 768;
        float q[8];
        #pragma unroll
        for (int d = 0; d < 4; d++) {
            float2 f = __half22float2(*(const __half2*)(base + mq * 192 + hd * 8 + 2 * d));
            q[2 * d] = f.x; q[2 * d + 1] = f.y;
        }
        float sc[4];
        #pragma unroll
        for (int mk = 0; mk < 4; mk++) {
            const __half* kp = base + mk * 192 + 64 + hd * 8;
            float a = 0.f;
            #pragma unroll
            for (int d = 0; d < 4; d++) {
                float2 f = __half22float2(*(const __half2*)(kp + 2 * d));
                a = fmaf(q[2 * d], f.x, a); a = fmaf(q[2 * d + 1], f.y, a);
            }
            sc[mk] = a * 0.35355339059327373f;
        }
        float mx = fmaxf(fmaxf(sc[0], sc[1]), fmaxf(sc[2], sc[3]));
        float p[4]; float psum = 0.f;
        #pragma unroll
        for (int mk = 0; mk < 4; mk++) { p[mk] = __expf(sc[mk] - mx); psum += p[mk]; }
        float inv = 1.0f / psum;
        float o[8];
        #pragma unroll
        for (int d = 0; d < 8; d++) o[d] = 0.f;
        #pragma unroll
        for (int mk = 0; mk < 4; mk++) {
            const __half* vp = base + mk * 192 + 128 + hd * 8;
            float pw = p[mk] * inv;
            #pragma unroll
            for (int d = 0; d < 4; d++) {
                float2 f = __half22float2(*(const __half2*)(vp + 2 * d));
                o[2 * d]     = fmaf(pw, f.x, o[2 * d]);
                o[2 * d + 1] = fmaf(pw, f.y, o[2 * d + 1]);
            }
        }
        int row = node * 4 + mq;
        #pragma unroll
        for (int d = 0; d < 4; d++) {
            int col = hd * 8 + 2 * d;
            *(__half2*)(sAO + row * 80 + hperm(col)) = __floats2half2_rn(o[2 * d], o[2 * d + 1]);
        }
    }
    __syncthreads();

    // ---- proj GEMM: [256] x [64] = AO @ Wo^T; epilogue residual+LN1 ----
    {
        float acc[2][4][4];
        #pragma unroll
        for (int mt = 0; mt < 2; mt++)
            #pragma unroll
            for (int nt = 0; nt < 4; nt++)
                #pragma unroll
                for (int q = 0; q < 4; q++) acc[mt][nt][q] = 0.f;
        #pragma unroll
        for (int k0 = 0; k0 < 64; k0 += 16) {
            unsigned a[2][4];
            #pragma unroll
            for (int mt = 0; mt < 2; mt++) {
                int r0 = mrow + mt * 16;
                ull vlo = *(const ull*)(sAO + (r0 + qr) * 80 + k0 + 4 * qc);
                ull vhi = *(const ull*)(sAO + (r0 + 8 + qr) * 80 + k0 + 4 * qc);
                a[mt][0] = (unsigned)vlo; a[mt][2] = (unsigned)(vlo >> 32);
                a[mt][1] = (unsigned)vhi; a[mt][3] = (unsigned)(vhi >> 32);
            }
            #pragma unroll
            for (int nt = 0; nt < 4; nt++) {
                ull bv = *(const ull*)(sWo + (nh * 32 + nt * 8 + qr) * 80 + k0 + 4 * qc);
                unsigned b[2] = { (unsigned)bv, (unsigned)(bv >> 32) };
                mma_f16(acc[0][nt], a[0], b);
                mma_f16(acc[1][nt], a[1], b);
            }
        }
        __syncthreads();   // qkv reads done; sO (aliasing sQKV) safe to write
        #pragma unroll
        for (int nt = 0; nt < 4; nt++) {
            int col = nh * 32 + nt * 8 + 2 * qc;
            float bias0 = sBo[col], bias1 = sBo[col + 1];
            #pragma unroll
            for (int mt = 0; mt < 2; mt++) {
                int r0 = mrow + mt * 16 + qr;
                int r1 = r0 + 8;
                float2 e0 = *(const float2*)(g_e + (tok0 + r0) * 64 + col);
                float2 e1 = *(const float2*)(g_e + (tok0 + r1) * 64 + col);
                sO[r0 * 72 + col]     = acc[mt][nt][0] + bias0 + e0.x;
                sO[r0 * 72 + col + 1] = acc[mt][nt][1] + bias1 + e0.y;
                sO[r1 * 72 + col]     = acc[mt][nt][2] + bias0 + e1.x;
                sO[r1 * 72 + col + 1] = acc[mt][nt][3] + bias1 + e1.y;
            }
        }
    }
    __syncthreads();

    // LN1: 2 threads per token
    int tk2 = t >> 1, half = t & 1;
    const float* ob = sO + tk2 * 72 + half * 32;
    float s = 0.f, s2 = 0.f;
    #pragma unroll
    for (int i = 0; i < 32; i++) { float v = ob[i]; s += v; s2 += v * v; }
    s  += __shfl_xor_sync(0xffffffffu, s, 1);
    s2 += __shfl_xor_sync(0xffffffffu, s2, 1);
    float mu   = s * (1.f / 64.f);
    float rstd = rsqrtf(s2 * (1.f / 64.f) - mu * mu + LN_EPS);
    float* go = g_e + (tok0 + tk2) * 64 + half * 32;
    #pragma unroll
    for (int i = 0; i < 32; i++) {
        int c = half * 32 + i;
        go[i] = (ob[i] - mu) * rstd * g1[l * 64 + c] + b1v[l * 64 + c];
    }
}

// =====================================================================
// K4: FF sublayer on FP16 tensor cores (unchanged from R8).
// =====================================================================
__global__ void __launch_bounds__(512, 1) k_ff(
    const float* __restrict__ ff1w, const float* __restrict__ ff1b,
    const float* __restrict__ ff2w, const float* __restrict__ ff2b,
    const float* __restrict__ g2,   const float* __restrict__ b2, int l)
{
    extern __shared__ char smb[];
    __half* sE  = (__half*)smb;              // [256][80]h = 40960B
    __half* sH  = (__half*)(smb + 40960);    // [256][80]h = 40960B
    __half* sW1 = (__half*)(smb + 81920);    // [64][80]h  = 10240B
    __half* sW2 = (__half*)(smb + 92160);    // [64][80]h  = 10240B
    float*  sB1 = (float*)(smb + 102400);    // 64 floats
    float*  sO  = (float*)smb;               // alias epilogue [256][72]f
    int t = threadIdx.x, w = t >> 5, lane = t & 31;
    int qr = lane >> 2, qc = lane & 3;
    size_t tok0 = (size_t)blockIdx.x * TB;
    int mrow = (w & 7) * 32;
    int nh   = w >> 3;
    int nbase = nh * 32;

    const float* f1w = ff1w + (size_t)l * FFD * OC;
    const float* f1b = ff1b + (size_t)l * FFD;
    const float* f2w = ff2w + (size_t)l * OC * FFD;

    for (int i = t; i < TB * 32; i += 512) {
        int row = i >> 5, kk = (i & 31) * 2;
        float2 f = *(const float2*)(g_e + tok0 * 64 + (size_t)row * 64 + kk);
        *(__half2*)(sE + row * 80 + hperm(kk)) = __floats2half2_rn(f.x, f.y);
    }
    for (int i = t; i < JC * 32; i += 512) {
        int j = i >> 5, kk = (i & 31) * 2;
        float2 f = *(const float2*)(f1w + (size_t)j * 64 + kk);
        *(__half2*)(sW1 + j * 80 + hperm(kk)) = __floats2half2_rn(f.x, f.y);
    }
    for (int i = t; i < 64 * 32; i += 512) {
        int c = i >> 5, jj = (i & 31) * 2;
        float2 f = *(const float2*)(f2w + (size_t)c * FFD + jj);
        *(__half2*)(sW2 + c * 80 + hperm(jj)) = __floats2half2_rn(f.x, f.y);
    }
    if (t < 64) sB1[t] = f1b[t];
    __syncthreads();

    float acc2[2][4][4];
    #pragma unroll
    for (int mt = 0; mt < 2; mt++)
        #pragma unroll
        for (int nt = 0; nt < 4; nt++)
            #pragma unroll
            for (int q = 0; q < 4; q++) acc2[mt][nt][q] = 0.f;

    for (int ch = 0; ch < NCH; ch++) {
        int jb2 = (ch + 1) * JC;
        float2 w1n[4]; float b1n = 0.f;
        if (ch < NCH - 1) {
            #pragma unroll
            for (int r = 0; r < 4; r++) {
                int idx = t + r * 512;
                int j = idx >> 5, kk = (idx & 31) * 2;
                w1n[r] = *(const float2*)(f1w + (size_t)(jb2 + j) * 64 + kk);
            }
            if (t < 64) b1n = f1b[jb2 + t];
        }

        float acc1[2][4][4];
        #pragma unroll
        for (int nt = 0; nt < 4; nt++) {
            float bv0 = sB1[nbase + nt * 8 + 2 * qc];
            float bv1 = sB1[nbase + nt * 8 + 2 * qc + 1];
            #pragma unroll
            for (int mt = 0; mt < 2; mt++) {
                acc1[mt][nt][0] = bv0; acc1[mt][nt][1] = bv1;
                acc1[mt][nt][2] = bv0; acc1[mt][nt][3] = bv1;
            }
        }
        #pragma unroll
        for (int k0 = 0; k0 < 64; k0 += 16) {
            unsigned a[2][4];
            #pragma unroll
            for (int mt = 0; mt < 2; mt++) {
                int r0 = mrow + mt * 16;
                ull vlo = *(const ull*)(sE + (r0 + qr) * 80 + k0 + 4 * qc);
                ull vhi = *(const ull*)(sE + (r0 + 8 + qr) * 80 + k0 + 4 * qc);
                a[mt][0] = (unsigned)vlo; a[mt][2] = (unsigned)(vlo >> 32);
                a[mt][1] = (unsigned)vhi; a[mt][3] = (unsigned)(vhi >> 32);
            }
            #pragma unroll
            for (int nt = 0; nt < 4; nt++) {
                ull bv = *(const ull*)(sW1 + (nbase + nt * 8 + qr) * 80 + k0 + 4 * qc);
                unsigned b[2] = { (unsigned)bv, (unsigned)(bv >> 32) };
                mma_f16(acc1[0][nt], a[0], b);
                mma_f16(acc1[1][nt], a[1], b);
            }
        }
        #pragma unroll
        for (int nt = 0; nt < 4; nt++) {
            int jcol = nbase + nt * 8 + 2 * qc;
            int jpos = hperm(jcol);
            #pragma unroll
            for (int mt = 0; mt < 2; mt++) {
                int r0 = mrow + mt * 16 + qr;
                *(__half2*)(sH + r0 * 80 + jpos) = __floats2half2_rn(
                    fmaxf(acc1[mt][nt][0], 0.f), fmaxf(acc1[mt][nt][1], 0.f));
                *(__half2*)(sH + (r0 + 8) * 80 + jpos) = __floats2half2_rn(
                    fmaxf(acc1[mt][nt][2], 0.f), fmaxf(acc1[mt][nt][3], 0.f));
            }
        }
        __syncthreads();

        float2 w2n[4];
        if (ch < NCH - 1) {
            #pragma unroll
            for (int r = 0; r < 4; r++) {
                int idx = t + r * 512;
                int j = idx >> 5, kk = (idx & 31) * 2;
                *(__half2*)(sW1 + j * 80 + hperm(kk)) = __floats2half2_rn(w1n[r].x, w1n[r].y);
            }
            if (t < 64) sB1[t] = b1n;
            #pragma unroll
            for (int r = 0; r < 4; r++) {
                int idx = t + r * 512;
                int c = idx >> 5, jj = (idx & 31) * 2;
                w2n[r] = *(const float2*)(f2w + (size_t)c * FFD + jb2 + jj);
            }
        }

        #pragma unroll
        for (int k0 = 0; k0 < 64; k0 += 16) {
            unsigned a[2][4];
            #pragma unroll
            for (int mt = 0; mt < 2; mt++) {
                int r0 = mrow + mt * 16;
                ull vlo = *(const ull*)(sH + (r0 + qr) * 80 + k0 + 4 * qc);
                ull vhi = *(const ull*)(sH + (r0 + 8 + qr) * 80 + k0 + 4 * qc);
                a[mt][0] = (unsigned)vlo; a[mt][2] = (unsigned)(vlo >> 32);
                a[mt][1] = (unsigned)vhi; a[mt][3] = (unsigned)(vhi >> 32);
            }
            #pragma unroll
            for (int nt = 0; nt < 4; nt++) {
                ull bv = *(const ull*)(sW2 + (nbase + nt * 8 + qr) * 80 + k0 + 4 * qc);
                unsigned b[2] = { (unsigned)bv, (unsigned)(bv >> 32) };
                mma_f16(acc2[0][nt], a[0], b);
                mma_f16(acc2[1][nt], a[1], b);
            }
        }
        __syncthreads();

        if (ch < NCH - 1) {
            #pragma unroll
            for (int r = 0; r < 4; r++) {
                int idx = t + r * 512;
                int c = idx >> 5, jj = (idx & 31) * 2;
                *(__half2*)(sW2 + c * 80 + hperm(jj)) = __floats2half2_rn(w2n[r].x, w2n[r].y);
            }
        }
    }

    #pragma unroll
    for (int nt = 0; nt < 4; nt++) {
        int col = nbase + nt * 8 + 2 * qc;
        float bias0 = ff2b[l * OC + col];
        float bias1 = ff2b[l * OC + col + 1];
        #pragma unroll
        for (int mt = 0; mt < 2; mt++) {
            int r0 = mrow + mt * 16 + qr;
            int r1 = r0 + 8;
            float2 e0 = *(const float2*)(g_e + (tok0 + r0) * 64 + col);
            float2 e1 = *(const float2*)(g_e + (tok0 + r1) * 64 + col);
            sO[r0 * 72 + col]     = acc2[mt][nt][0] + bias0 + e0.x;
            sO[r0 * 72 + col + 1] = acc2[mt][nt][1] + bias1 + e0.y;
            sO[r1 * 72 + col]     = acc2[mt][nt][2] + bias0 + e1.x;
            sO[r1 * 72 + col + 1] = acc2[mt][nt][3] + bias1 + e1.y;
        }
    }
    __syncthreads();

    int tk2 = t >> 1, half = t & 1;
    const float* ob = sO + tk2 * 72 + half * 32;
    float s = 0.f, s2 = 0.f;
    #pragma unroll
    for (int i = 0; i < 32; i++) { float v = ob[i]; s += v; s2 += v * v; }
    s  += __shfl_xor_sync(0xffffffffu, s, 1);
    s2 += __shfl_xor_sync(0xffffffffu, s2, 1);
    float mu   = s * (1.f / 64.f);
    float rstd = rsqrtf(s2 * (1.f / 64.f) - mu * mu + LN_EPS);
    float* go = g_e + (tok0 + tk2) * 64 + half * 32;
    #pragma unroll
    for (int i = 0; i < 32; i++) {
        int c = half * 32 + i;
        go[i] = (ob[i] - mu) * rstd * g2[l * OC + c] + b2[l * OC + c];
    }
}

// =====================================================================
// K5: head
// =====================================================================
__global__ void __launch_bounds__(256) k_head(
    const float* __restrict__ r1w, const float* __restrict__ r1b,
    const float* __restrict__ r2w, const float* __restrict__ r2b,
    float* __restrict__ out)
{
    __shared__ float sR1T[64 * 65];
    __shared__ float sR2[64];
    __shared__ float sP[8][64];
    int t = threadIdx.x;
    for (int i = t; i < 4096; i += 256) {
        int c = i >> 6, k = i & 63;
        sR1T[k * 65 + c] = r1w[c * 64 + k];
    }
    if (t < 64) sR2[t] = r2w[t];
    __syncthreads();
    int w = t >> 5, lane = t & 31;
    int n = blockIdx.x * 8 + w;
    const float* eb = g_e + (size_t)n * 256;
    float p0 = (eb[lane] + eb[64 + lane] + eb[128 + lane] + eb[192 + lane]) * 0.25f;
    float p1 = (eb[32 + lane] + eb[96 + lane] + eb[160 + lane] + eb[224 + lane]) * 0.25f;
    sP[w][lane]      = p0;
    sP[w][lane + 32] = p1;
    __syncwarp();
    float a0 = r1b[lane], a1 = r1b[lane + 32];
    #pragma unroll 8
    for (int k = 0; k < 64; k++) {
        float pv = sP[w][k];
        a0 = fmaf(pv, sR1T[k * 65 + lane], a0);
        a1 = fmaf(pv, sR1T[k * 65 + lane + 32], a1);
    }
    a0 = fmaxf(a0, 0.f); a1 = fmaxf(a1, 0.f);
    float acc = a0 * sR2[lane] + a1 * sR2[lane + 32];
    #pragma unroll
    for (int off = 16; off; off >>= 1) acc += __shfl_xor_sync(0xffffffffu, acc, off);
    if (lane == 0) out[n] = acc + r2b[0];
}

// =====================================================================
extern "C" void kernel_launch(void* const* d_in, const int* in_sizes, int n_in,
                              void* d_out, int out_size) {
    const float* x    = (const float*)d_in[0];
    const int*   ei   = (const int*)  d_in[1];
    const float* mpw  = (const float*)d_in[2];
    const float* W0   = (const float*)d_in[3];
    const float* b0   = (const float*)d_in[4];
    const float* Wl   = (const float*)d_in[5];
    const float* bl   = (const float*)d_in[6];
    const float* W1   = (const float*)d_in[7];
    const float* b1   = (const float*)d_in[8];
    const float* Wo   = (const float*)d_in[9];
    const float* bo   = (const float*)d_in[10];
    const float* tinw = (const float*)d_in[11];
    const float* tinb = (const float*)d_in[12];
    const float* tow  = (const float*)d_in[13];
    const float* tob  = (const float*)d_in[14];
    const float* ln1g = (const float*)d_in[15];
    const float* ln1b = (const float*)d_in[16];
    const float* ff1w = (const float*)d_in[17];
    const float* ff1b = (const float*)d_in[18];
    const float* ff2w = (const float*)d_in[19];
    const float* ff2b = (const float*)d_in[20];
    const float* ln2g = (const float*)d_in[21];
    const float* ln2b = (const float*)d_in[22];
    const float* r1w  = (const float*)d_in[23];
    const float* r1b  = (const float*)d_in[24];
    const float* r2w  = (const float*)d_in[25];
    const float* r2b  = (const float*)d_in[26];
    float* out = (float*)d_out;
    (void)in_sizes; (void)n_in; (void)out_size;

    cudaFuncSetAttribute(k_xw,   cudaFuncAttributeMaxDynamicSharedMemorySize, 110848);
    cudaFuncSetAttribute(k_attn, cudaFuncAttributeMaxDynamicSharedMemorySize, 181248);
    cudaFuncSetAttribute(k_ff,   cudaFuncAttributeMaxDynamicSharedMemorySize, 102656);

    // launch order: ncu (-s 5 -c 1) captures k_ff (6th launch)
    dim3 gxw(118, 4);
    dim3 gg(469, 4);
    k_xw<<<gxw, 512, 110848>>>(x, W0, b0, Wl, bl, W1, b1);                   // 1
    k_zero<<<7500, 256>>>();                                                 // 2
    k_scatter<<<120000, 256>>>(ei);                                          // 3
    k_gnn<<<gg, 256>>>(Wo, bo, mpw);                                         // 4
    k_attn<<<NBLK, 512, 181248>>>(tinw, tinb, tow, tob, ln1g, ln1b, 0);      // 5
    k_ff<<<NBLK, 512, 102656>>>(ff1w, ff1b, ff2w, ff2b, ln2g, ln2b, 0);      // 6 <- ncu
    k_attn<<<NBLK, 512, 181248>>>(tinw, tinb, tow, tob, ln1g, ln1b, 1);
    k_ff<<<NBLK, 512, 102656>>>(ff1w, ff1b, ff2w, ff2b, ln2g, ln2b, 1);
    k_head<<<3750, 256>>>(r1w, r1b, r2w, r2b, out);
}

// round 10
// speedup vs baseline: 5.9631x; 1.1602x over previous
#include <cuda_runtime.h>
#include <cuda_fp16.h>
#include <cstdint>

typedef unsigned long long ull;

#define NN   30000
#define INC  128
#define OC   64
#define MP   4
#define EE   480000
#define FFD  2048
#define TOK  (NN*MP)
#define TB   256                     // tokens per ff/attn block
#define NBLK ((TOK + TB - 1) / TB)   // 469
#define TOKP (NBLK * TB)             // 120064 (padded)
#define JC   64                      // j per chunk (ff)
#define NCH  (FFD / JC)              // 32 chunks
#define LN_EPS 1e-5f

// ---- device scratch (allocation-free rule: __device__ globals) ----
__device__ float g_y[(size_t)MP * NN * OC];     // x @ Wl^T
__device__ float g_c[(size_t)MP * NN * OC];     // x @ Wc^T + bias
__device__ float g_aggY[(size_t)MP * NN * OC];  // scatter target
__device__ float g_e[(size_t)TOKP * OC];        // token embeddings

// ---- fp16 mma helper (m16n8k16, f32 accumulate) ----
__device__ __forceinline__ void mma_f16(float* c, const unsigned* a, const unsigned* b) {
    asm volatile(
        "mma.sync.aligned.m16n8k16.row.col.f32.f16.f16.f32 "
        "{%0,%1,%2,%3}, {%4,%5,%6,%7}, {%8,%9}, {%0,%1,%2,%3};"
        : "+f"(c[0]), "+f"(c[1]), "+f"(c[2]), "+f"(c[3])
        : "r"(a[0]), "r"(a[1]), "r"(a[2]), "r"(a[3]), "r"(b[0]), "r"(b[1]));
}
// interleaved k-pair permutation within 16-groups: thread qc's halves
// (2qc,2qc+1,2qc+8,2qc+9) land at positions 4qc..4qc+3 -> frags are single LDS.64
__device__ __forceinline__ int hperm(int k) {
    return (k & ~15) | ((k & 6) << 1) | ((k & 8) >> 2) | (k & 1);
}
__device__ __forceinline__ unsigned pack_h2(float x, float y) {
    __half2 h = __floats2half2_rn(x, y);
    return *(unsigned*)&h;
}

// =====================================================================
// K_xw on fp16 tensor cores: y[m] = x @ Wl[m]^T ; c[m] = x @ Wc[m]^T + bias
// =====================================================================
__global__ void __launch_bounds__(512, 1) k_xw(
    const float* __restrict__ x,
    const float* __restrict__ W0, const float* __restrict__ b0,
    const float* __restrict__ Wl, const float* __restrict__ bl,
    const float* __restrict__ W1, const float* __restrict__ b1)
{
    extern __shared__ char smb[];
    __half* sX = (__half*)smb;               // [256][144]h = 73728B
    __half* sW = (__half*)(smb + 73728);     // [128][144]h = 36864B
    float*  sB = (float*)(smb + 110592);     // 64 floats
    int t = threadIdx.x, w = t >> 5, lane = t & 31;
    int qr = lane >> 2, qc = lane & 3;
    int m = blockIdx.y;
    int node0 = blockIdx.x * 256;

    for (int i = t; i < 256 * 64; i += 512) {
        int row = i >> 6, kk = (i & 63) * 2;
        int gn = node0 + row; if (gn >= NN) gn = NN - 1;
        float2 f = *(const float2*)(x + (size_t)gn * INC + kk);
        *(__half2*)(sX + row * 144 + hperm(kk)) = __floats2half2_rn(f.x, f.y);
    }
    for (int i = t; i < 128 * 64; i += 512) {
        int r = i >> 6, kk = (i & 63) * 2;
        float2 f;
        if (r < 64) {
            f = *(const float2*)(Wl + (size_t)m * 8192 + (size_t)r * 128 + kk);
        } else {
            float2 a = *(const float2*)(W0 + (size_t)m * 8192 + (size_t)(r - 64) * 128 + kk);
            float2 b = *(const float2*)(W1 + (size_t)m * 8192 + (size_t)(r - 64) * 128 + kk);
            f = make_float2(a.x + b.x, a.y + b.y);
        }
        *(__half2*)(sW + r * 144 + hperm(kk)) = __floats2half2_rn(f.x, f.y);
    }
    if (t < 64) sB[t] = b0[m * 64 + t] + bl[m * 64 + t] + b1[m * 64 + t];
    __syncthreads();

    int mrow = (w & 7) * 32;
    int nh   = w >> 3;          // 0 -> y, 1 -> c

    float acc[2][8][4];
    #pragma unroll
    for (int nt = 0; nt < 8; nt++) {
        float bv0 = 0.f, bv1 = 0.f;
        if (nh == 1) { bv0 = sB[nt * 8 + 2 * qc]; bv1 = sB[nt * 8 + 2 * qc + 1]; }
        #pragma unroll
        for (int mt = 0; mt < 2; mt++) {
            acc[mt][nt][0] = bv0; acc[mt][nt][1] = bv1;
            acc[mt][nt][2] = bv0; acc[mt][nt][3] = bv1;
        }
    }
    #pragma unroll
    for (int k0 = 0; k0 < 128; k0 += 16) {
        unsigned a[2][4];
        #pragma unroll
        for (int mt = 0; mt < 2; mt++) {
            int r0 = mrow + mt * 16;
            ull vlo = *(const ull*)(sX + (r0 + qr) * 144 + k0 + 4 * qc);
            ull vhi = *(const ull*)(sX + (r0 + 8 + qr) * 144 + k0 + 4 * qc);
            a[mt][0] = (unsigned)vlo; a[mt][2] = (unsigned)(vlo >> 32);
            a[mt][1] = (unsigned)vhi; a[mt][3] = (unsigned)(vhi >> 32);
        }
        #pragma unroll
        for (int nt = 0; nt < 8; nt++) {
            ull bv = *(const ull*)(sW + (nh * 64 + nt * 8 + qr) * 144 + k0 + 4 * qc);
            unsigned b[2] = { (unsigned)bv, (unsigned)(bv >> 32) };
            mma_f16(acc[0][nt], a[0], b);
            mma_f16(acc[1][nt], a[1], b);
        }
    }
    float* dst = nh ? g_c : g_y;
    #pragma unroll
    for (int nt = 0; nt < 8; nt++) {
        int col = nt * 8 + 2 * qc;
        #pragma unroll
        for (int mt = 0; mt < 2; mt++) {
            int r0 = mrow + mt * 16 + qr;
            int n0 = node0 + r0, n1 = n0 + 8;
            if (n0 < NN)
                *(float2*)(dst + ((size_t)m * NN + n0) * OC + col) =
                    make_float2(acc[mt][nt][0], acc[mt][nt][1]);
            if (n1 < NN)
                *(float2*)(dst + ((size_t)m * NN + n1) * OC + col) =
                    make_float2(acc[mt][nt][2], acc[mt][nt][3]);
        }
    }
}

// =====================================================================
// K0: zero aggY buffer
// =====================================================================
__global__ void k_zero() {
    size_t i = (size_t)blockIdx.x * 256 + threadIdx.x;
    ((float4*)g_aggY)[i] = make_float4(0.f, 0.f, 0.f, 0.f);
}

// =====================================================================
// K1: edge scatter: aggY[m][src] += y[m][dst]. half-warp per edge.
// =====================================================================
__global__ void k_scatter(const int* __restrict__ ei) {
    int wid  = (blockIdx.x * blockDim.x + threadIdx.x) >> 5;
    int lane = threadIdx.x & 31;
    int pair = lane >> 4;
    int sub  = lane & 15;
    int eg = wid * 2 + pair;
    int m = eg / EE;
    int e = eg - m * EE;
    const int* b = ei + (size_t)m * 2 * EE;
    int src = __ldg(b + e);
    int dst = __ldg(b + EE + e);
    float4 v = ((const float4*)(g_y + ((size_t)m * NN + dst) * OC))[sub];
    atomicAdd(((float4*)(g_aggY + ((size_t)m * NN + src) * OC)) + sub, v);
}

// =====================================================================
// K2: GNN tail on fp16 MMA: h = relu(aggY + c); e_m = (h@Wo^T + bo)*mpw
// 256 nodes/block; same fragment machinery as attn proj GEMM.
// =====================================================================
__global__ void __launch_bounds__(512, 1) k_gnn(
    const float* __restrict__ Wo, const float* __restrict__ bo,
    const float* __restrict__ mpw)
{
    extern __shared__ char smb[];
    __half* sH  = (__half*)smb;              // [256][80]h = 40960B
    __half* sWo = (__half*)(smb + 40960);    // [64][80]h  = 10240B
    float*  sBo = (float*)(smb + 51200);     // 64
    int t = threadIdx.x, w = t >> 5, lane = t & 31;
    int qr = lane >> 2, qc = lane & 3;
    int m = blockIdx.y;
    int node0 = blockIdx.x * 256;

    for (int i = t; i < 256 * 32; i += 512) {
        int row = i >> 5, kk = (i & 31) * 2;
        int gn = node0 + row; if (gn >= NN) gn = NN - 1;
        size_t base = ((size_t)m * NN + gn) * OC + kk;
        float2 a = *(const float2*)(g_aggY + base);
        float2 c = *(const float2*)(g_c + base);
        *(__half2*)(sH + row * 80 + hperm(kk)) =
            __floats2half2_rn(fmaxf(a.x + c.x, 0.f), fmaxf(a.y + c.y, 0.f));
    }
    for (int i = t; i < 64 * 32; i += 512) {
        int r = i >> 5, kk = (i & 31) * 2;
        float2 f = *(const float2*)(Wo + (size_t)m * 4096 + (size_t)r * 64 + kk);
        *(__half2*)(sWo + r * 80 + hperm(kk)) = __floats2half2_rn(f.x, f.y);
    }
    if (t < 64) sBo[t] = bo[m * 64 + t];
    __syncthreads();

    int mrow = (w & 7) * 32;
    int nh   = w >> 3;
    float wgt = mpw[m];

    float acc[2][4][4];
    #pragma unroll
    for (int mt = 0; mt < 2; mt++)
        #pragma unroll
        for (int nt = 0; nt < 4; nt++)
            #pragma unroll
            for (int q = 0; q < 4; q++) acc[mt][nt][q] = 0.f;

    #pragma unroll
    for (int k0 = 0; k0 < 64; k0 += 16) {
        unsigned a[2][4];
        #pragma unroll
        for (int mt = 0; mt < 2; mt++) {
            int r0 = mrow + mt * 16;
            ull vlo = *(const ull*)(sH + (r0 + qr) * 80 + k0 + 4 * qc);
            ull vhi = *(const ull*)(sH + (r0 + 8 + qr) * 80 + k0 + 4 * qc);
            a[mt][0] = (unsigned)vlo; a[mt][2] = (unsigned)(vlo >> 32);
            a[mt][1] = (unsigned)vhi; a[mt][3] = (unsigned)(vhi >> 32);
        }
        #pragma unroll
        for (int nt = 0; nt < 4; nt++) {
            ull bv = *(const ull*)(sWo + (nh * 32 + nt * 8 + qr) * 80 + k0 + 4 * qc);
            unsigned b[2] = { (unsigned)bv, (unsigned)(bv >> 32) };
            mma_f16(acc[0][nt], a[0], b);
            mma_f16(acc[1][nt], a[1], b);
        }
    }
    #pragma unroll
    for (int nt = 0; nt < 4; nt++) {
        int col = nh * 32 + nt * 8 + 2 * qc;
        float bias0 = sBo[col], bias1 = sBo[col + 1];
        #pragma unroll
        for (int mt = 0; mt < 2; mt++) {
            int r0 = mrow + mt * 16 + qr;
            int n0 = node0 + r0, n1 = n0 + 8;
            if (n0 < NN)
                *(float2*)(g_e + ((size_t)n0 * MP + m) * OC + col) =
                    make_float2((acc[mt][nt][0] + bias0) * wgt, (acc[mt][nt][1] + bias1) * wgt);
            if (n1 < NN)
                *(float2*)(g_e + ((size_t)n1 * MP + m) * OC + col) =
                    make_float2((acc[mt][nt][2] + bias0) * wgt, (acc[mt][nt][3] + bias1) * wgt);
        }
    }
}

// =====================================================================
// K3: attention sublayer on fp16 tensor cores (unchanged from R9).
// =====================================================================
__global__ void __launch_bounds__(512, 1) k_attn(
    const float* __restrict__ tinw, const float* __restrict__ tinb,
    const float* __restrict__ tow,  const float* __restrict__ tob,
    const float* __restrict__ g1,   const float* __restrict__ b1v, int l)
{
    extern __shared__ char smb[];
    __half* sE   = (__half*)smb;                 // [256][80]h = 40960 (alias sAO)
    __half* sWin = (__half*)(smb + 40960);       // [192][80]h = 30720
    __half* sQKV = (__half*)(smb + 71680);       // [64 node][768]h = 98304 (alias sO)
    __half* sWo  = (__half*)(smb + 169984);      // [64][80]h  = 10240
    float*  sBin = (float*)(smb + 180224);       // 192
    float*  sBo  = (float*)(smb + 180992);       // 64
    __half* sAO  = sE;
    float*  sO   = (float*)(smb + 71680);        // epilogue [256][72]f
    int t = threadIdx.x, w = t >> 5, lane = t & 31;
    int qr = lane >> 2, qc = lane & 3;
    size_t tok0 = (size_t)blockIdx.x * TB;

    const float* tw  = tinw + (size_t)l * 192 * 64;
    const float* twO = tow  + (size_t)l * 64 * 64;
    for (int i = t; i < 192 * 32; i += 512) {
        int r = i >> 5, kk = (i & 31) * 2;
        float2 f = *(const float2*)(tw + (size_t)r * 64 + kk);
        *(__half2*)(sWin + r * 80 + hperm(kk)) = __floats2half2_rn(f.x, f.y);
    }
    for (int i = t; i < 64 * 32; i += 512) {
        int r = i >> 5, kk = (i & 31) * 2;
        float2 f = *(const float2*)(twO + (size_t)r * 64 + kk);
        *(__half2*)(sWo + r * 80 + hperm(kk)) = __floats2half2_rn(f.x, f.y);
    }
    for (int i = t; i < TB * 32; i += 512) {
        int row = i >> 5, kk = (i & 31) * 2;
        float2 f = *(const float2*)(g_e + (tok0 + row) * 64 + kk);
        *(__half2*)(sE + row * 80 + hperm(kk)) = __floats2half2_rn(f.x, f.y);
    }
    if (t < 192) sBin[t] = tinb[l * 192 + t];
    if (t >= 192 && t < 256) sBo[t - 192] = tob[l * 64 + (t - 192)];
    __syncthreads();

    int mrow = (w & 7) * 32;
    int nh   = w >> 3;

    #pragma unroll
    for (int np = 0; np < 2; np++) {
        float acc[2][6][4];
        #pragma unroll
        for (int nt = 0; nt < 6; nt++) {
            int col = nh * 96 + np * 48 + nt * 8 + 2 * qc;
            float bv0 = sBin[col], bv1 = sBin[col + 1];
            #pragma unroll
            for (int mt = 0; mt < 2; mt++) {
                acc[mt][nt][0] = bv0; acc[mt][nt][1] = bv1;
                acc[mt][nt][2] = bv0; acc[mt][nt][3] = bv1;
            }
        }
        #pragma unroll
        for (int k0 = 0; k0 < 64; k0 += 16) {
            unsigned a[2][4];
            #pragma unroll
            for (int mt = 0; mt < 2; mt++) {
                int r0 = mrow + mt * 16;
                ull vlo = *(const ull*)(sE + (r0 + qr) * 80 + k0 + 4 * qc);
                ull vhi = *(const ull*)(sE + (r0 + 8 + qr) * 80 + k0 + 4 * qc);
                a[mt][0] = (unsigned)vlo; a[mt][2] = (unsigned)(vlo >> 32);
                a[mt][1] = (unsigned)vhi; a[mt][3] = (unsigned)(vhi >> 32);
            }
            #pragma unroll
            for (int nt = 0; nt < 6; nt++) {
                ull bv = *(const ull*)(sWin + (nh * 96 + np * 48 + nt * 8 + qr) * 80 + k0 + 4 * qc);
                unsigned b[2] = { (unsigned)bv, (unsigned)(bv >> 32) };
                mma_f16(acc[0][nt], a[0], b);
                mma_f16(acc[1][nt], a[1], b);
            }
        }
        #pragma unroll
        for (int nt = 0; nt < 6; nt++) {
            int col = nh * 96 + np * 48 + nt * 8 + 2 * qc;
            #pragma unroll
            for (int mt = 0; mt < 2; mt++) {
                int r0 = mrow + mt * 16 + qr;
                int r1 = r0 + 8;
                *(__half2*)(sQKV + (r0 >> 2) * 768 + (r0 & 3) * 192 + col) =
                    __floats2half2_rn(acc[mt][nt][0], acc[mt][nt][1]);
                *(__half2*)(sQKV + (r1 >> 2) * 768 + (r1 & 3) * 192 + col) =
                    __floats2half2_rn(acc[mt][nt][2], acc[mt][nt][3]);
            }
        }
    }
    __syncthreads();

    #pragma unroll
    for (int it = 0; it < 4; it++) {
        int u = it * 512 + t;
        int node = u >> 5, hd = (u >> 2) & 7, mq = u & 3;
        const __half* base = sQKV + node * 768;
        float q[8];
        #pragma unroll
        for (int d = 0; d < 4; d++) {
            float2 f = __half22float2(*(const __half2*)(base + mq * 192 + hd * 8 + 2 * d));
            q[2 * d] = f.x; q[2 * d + 1] = f.y;
        }
        float sc[4];
        #pragma unroll
        for (int mk = 0; mk < 4; mk++) {
            const __half* kp = base + mk * 192 + 64 + hd * 8;
            float a = 0.f;
            #pragma unroll
            for (int d = 0; d < 4; d++) {
                float2 f = __half22float2(*(const __half2*)(kp + 2 * d));
                a = fmaf(q[2 * d], f.x, a); a = fmaf(q[2 * d + 1], f.y, a);
            }
            sc[mk] = a * 0.35355339059327373f;
        }
        float mx = fmaxf(fmaxf(sc[0], sc[1]), fmaxf(sc[2], sc[3]));
        float p[4]; float psum = 0.f;
        #pragma unroll
        for (int mk = 0; mk < 4; mk++) { p[mk] = __expf(sc[mk] - mx); psum += p[mk]; }
        float inv = 1.0f / psum;
        float o[8];
        #pragma unroll
        for (int d = 0; d < 8; d++) o[d] = 0.f;
        #pragma unroll
        for (int mk = 0; mk < 4; mk++) {
            const __half* vp = base + mk * 192 + 128 + hd * 8;
            float pw = p[mk] * inv;
            #pragma unroll
            for (int d = 0; d < 4; d++) {
                float2 f = __half22float2(*(const __half2*)(vp + 2 * d));
                o[2 * d]     = fmaf(pw, f.x, o[2 * d]);
                o[2 * d + 1] = fmaf(pw, f.y, o[2 * d + 1]);
            }
        }
        int row = node * 4 + mq;
        #pragma unroll
        for (int d = 0; d < 4; d++) {
            int col = hd * 8 + 2 * d;
            *(__half2*)(sAO + row * 80 + hperm(col)) = __floats2half2_rn(o[2 * d], o[2 * d + 1]);
        }
    }
    __syncthreads();

    {
        float acc[2][4][4];
        #pragma unroll
        for (int mt = 0; mt < 2; mt++)
            #pragma unroll
            for (int nt = 0; nt < 4; nt++)
                #pragma unroll
                for (int q = 0; q < 4; q++) acc[mt][nt][q] = 0.f;
        #pragma unroll
        for (int k0 = 0; k0 < 64; k0 += 16) {
            unsigned a[2][4];
            #pragma unroll
            for (int mt = 0; mt < 2; mt++) {
                int r0 = mrow + mt * 16;
                ull vlo = *(const ull*)(sAO + (r0 + qr) * 80 + k0 + 4 * qc);
                ull vhi = *(const ull*)(sAO + (r0 + 8 + qr) * 80 + k0 + 4 * qc);
                a[mt][0] = (unsigned)vlo; a[mt][2] = (unsigned)(vlo >> 32);
                a[mt][1] = (unsigned)vhi; a[mt][3] = (unsigned)(vhi >> 32);
            }
            #pragma unroll
            for (int nt = 0; nt < 4; nt++) {
                ull bv = *(const ull*)(sWo + (nh * 32 + nt * 8 + qr) * 80 + k0 + 4 * qc);
                unsigned b[2] = { (unsigned)bv, (unsigned)(bv >> 32) };
                mma_f16(acc[0][nt], a[0], b);
                mma_f16(acc[1][nt], a[1], b);
            }
        }
        __syncthreads();
        #pragma unroll
        for (int nt = 0; nt < 4; nt++) {
            int col = nh * 32 + nt * 8 + 2 * qc;
            float bias0 = sBo[col], bias1 = sBo[col + 1];
            #pragma unroll
            for (int mt = 0; mt < 2; mt++) {
                int r0 = mrow + mt * 16 + qr;
                int r1 = r0 + 8;
                float2 e0 = *(const float2*)(g_e + (tok0 + r0) * 64 + col);
                float2 e1 = *(const float2*)(g_e + (tok0 + r1) * 64 + col);
                sO[r0 * 72 + col]     = acc[mt][nt][0] + bias0 + e0.x;
                sO[r0 * 72 + col + 1] = acc[mt][nt][1] + bias1 + e0.y;
                sO[r1 * 72 + col]     = acc[mt][nt][2] + bias0 + e1.x;
                sO[r1 * 72 + col + 1] = acc[mt][nt][3] + bias1 + e1.y;
            }
        }
    }
    __syncthreads();

    int tk2 = t >> 1, half = t & 1;
    const float* ob = sO + tk2 * 72 + half * 32;
    float s = 0.f, s2 = 0.f;
    #pragma unroll
    for (int i = 0; i < 32; i++) { float v = ob[i]; s += v; s2 += v * v; }
    s  += __shfl_xor_sync(0xffffffffu, s, 1);
    s2 += __shfl_xor_sync(0xffffffffu, s2, 1);
    float mu   = s * (1.f / 64.f);
    float rstd = rsqrtf(s2 * (1.f / 64.f) - mu * mu + LN_EPS);
    float* go = g_e + (tok0 + tk2) * 64 + half * 32;
    #pragma unroll
    for (int i = 0; i < 32; i++) {
        int c = half * 32 + i;
        go[i] = (ob[i] - mu) * rstd * g1[l * 64 + c] + b1v[l * 64 + c];
    }
}

// =====================================================================
// K4: FF on fp16 MMA, H kept in registers (C-frag == A-frag identity),
// double-buffered weights, ONE sync per chunk. warp = 16 rows, all 64 N.
// =====================================================================
__global__ void __launch_bounds__(512, 1) k_ff(
    const float* __restrict__ ff1w, const float* __restrict__ ff1b,
    const float* __restrict__ ff2w, const float* __restrict__ ff2b,
    const float* __restrict__ g2,   const float* __restrict__ b2, int l)
{
    extern __shared__ char smb[];
    __half* sE  = (__half*)smb;              // [256][80]h = 40960B
    __half* sW1 = (__half*)(smb + 40960);    // [2][64][80]h = 20480B
    __half* sW2 = (__half*)(smb + 61440);    // [2][64][80]h = 20480B
    float*  sB1 = (float*)(smb + 81920);     // [2][64] = 512B
    float*  sO  = (float*)smb;               // alias epilogue [256][72]f = 73728B
    int t = threadIdx.x, w = t >> 5, lane = t & 31;
    int qr = lane >> 2, qc = lane & 3;
    size_t tok0 = (size_t)blockIdx.x * TB;
    int mrow = w * 16;                       // 16 rows per warp

    const float* f1w = ff1w + (size_t)l * FFD * OC;
    const float* f1b = ff1b + (size_t)l * FFD;
    const float* f2w = ff2w + (size_t)l * OC * FFD;

    for (int i = t; i < TB * 32; i += 512) {
        int row = i >> 5, kk = (i & 31) * 2;
        float2 f = *(const float2*)(g_e + tok0 * 64 + (size_t)row * 64 + kk);
        *(__half2*)(sE + row * 80 + hperm(kk)) = __floats2half2_rn(f.x, f.y);
    }
    for (int i = t; i < JC * 32; i += 512) {
        int j = i >> 5, kk = (i & 31) * 2;
        float2 f = *(const float2*)(f1w + (size_t)j * 64 + kk);
        *(__half2*)(sW1 + j * 80 + hperm(kk)) = __floats2half2_rn(f.x, f.y);
    }
    for (int i = t; i < 64 * 32; i += 512) {
        int c = i >> 5, jj = (i & 31) * 2;
        float2 f = *(const float2*)(f2w + (size_t)c * FFD + jj);
        *(__half2*)(sW2 + c * 80 + hperm(jj)) = __floats2half2_rn(f.x, f.y);
    }
    if (t < 64) sB1[t] = f1b[t];
    __syncthreads();

    float acc2[8][4];
    #pragma unroll
    for (int nt = 0; nt < 8; nt++)
        #pragma unroll
        for (int q = 0; q < 4; q++) acc2[nt][q] = 0.f;

    for (int ch = 0; ch < NCH; ch++) {
        int buf = ch & 1, nb = buf ^ 1;
        const __half* w1 = sW1 + buf * 5120;
        const __half* w2 = sW2 + buf * 5120;
        const float*  bb = sB1 + buf * 64;
        int jb2 = (ch + 1) * JC;

        // prefetch next chunk's weights into registers
        float2 w1n[4], w2n[4]; float b1n = 0.f;
        if (ch < NCH - 1) {
            #pragma unroll
            for (int r = 0; r < 4; r++) {
                int idx = t + r * 512;
                int j = idx >> 5, kk = (idx & 31) * 2;
                w1n[r] = *(const float2*)(f1w + (size_t)(jb2 + j) * 64 + kk);
            }
            #pragma unroll
            for (int r = 0; r < 4; r++) {
                int idx = t + r * 512;
                int c = idx >> 5, jj = (idx & 31) * 2;
                w2n[r] = *(const float2*)(f2w + (size_t)c * FFD + jb2 + jj);
            }
            if (t < 64) b1n = f1b[jb2 + t];
        }

        // ---- GEMM1: acc1[8 nt][4] = E(16 rows) @ W1^T(64 j) + b1 ----
        float acc1[8][4];
        #pragma unroll
        for (int nt = 0; nt < 8; nt++) {
            float bv0 = bb[nt * 8 + 2 * qc];
            float bv1 = bb[nt * 8 + 2 * qc + 1];
            acc1[nt][0] = bv0; acc1[nt][1] = bv1;
            acc1[nt][2] = bv0; acc1[nt][3] = bv1;
        }
        #pragma unroll
        for (int k0 = 0; k0 < 64; k0 += 16) {
            ull vlo = *(const ull*)(sE + (mrow + qr) * 80 + k0 + 4 * qc);
            ull vhi = *(const ull*)(sE + (mrow + 8 + qr) * 80 + k0 + 4 * qc);
            unsigned a[4] = { (unsigned)vlo, (unsigned)vhi,
                              (unsigned)(vlo >> 32), (unsigned)(vhi >> 32) };
            #pragma unroll
            for (int nt = 0; nt < 8; nt++) {
                ull bv = *(const ull*)(w1 + (nt * 8 + qr) * 80 + k0 + 4 * qc);
                unsigned b[2] = { (unsigned)bv, (unsigned)(bv >> 32) };
                mma_f16(acc1[nt], a, b);
            }
        }

        // ---- relu + pack: C-frag -> A-frags of GEMM2 (no smem) ----
        unsigned afr[4][4];
        #pragma unroll
        for (int kt = 0; kt < 4; kt++) {
            afr[kt][0] = pack_h2(fmaxf(acc1[2 * kt][0], 0.f),     fmaxf(acc1[2 * kt][1], 0.f));
            afr[kt][1] = pack_h2(fmaxf(acc1[2 * kt][2], 0.f),     fmaxf(acc1[2 * kt][3], 0.f));
            afr[kt][2] = pack_h2(fmaxf(acc1[2 * kt + 1][0], 0.f), fmaxf(acc1[2 * kt + 1][1], 0.f));
            afr[kt][3] = pack_h2(fmaxf(acc1[2 * kt + 1][2], 0.f), fmaxf(acc1[2 * kt + 1][3], 0.f));
        }

        // ---- GEMM2: acc2 += H(16 rows, 64 j) @ W2^T(64 c) ----
        #pragma unroll
        for (int kt = 0; kt < 4; kt++) {
            #pragma unroll
            for (int nt = 0; nt < 8; nt++) {
                ull bv = *(const ull*)(w2 + (nt * 8 + qr) * 80 + kt * 16 + 4 * qc);
                unsigned b[2] = { (unsigned)bv, (unsigned)(bv >> 32) };
                mma_f16(acc2[nt], afr[kt], b);
            }
        }

        // store prefetched weights into the idle buffer
        if (ch < NCH - 1) {
            #pragma unroll
            for (int r = 0; r < 4; r++) {
                int idx = t + r * 512;
                int j = idx >> 5, kk = (idx & 31) * 2;
                *(__half2*)(sW1 + nb * 5120 + j * 80 + hperm(kk)) =
                    __floats2half2_rn(w1n[r].x, w1n[r].y);
            }
            #pragma unroll
            for (int r = 0; r < 4; r++) {
                int idx = t + r * 512;
                int c = idx >> 5, jj = (idx & 31) * 2;
                *(__half2*)(sW2 + nb * 5120 + c * 80 + hperm(jj)) =
                    __floats2half2_rn(w2n[r].x, w2n[r].y);
            }
            if (t < 64) sB1[nb * 64 + t] = b1n;
        }
        __syncthreads();
    }

    // ---- epilogue: bias + residual (exact fp32 from g_e) -> sO, then LN2 ----
    #pragma unroll
    for (int nt = 0; nt < 8; nt++) {
        int col = nt * 8 + 2 * qc;
        float bias0 = ff2b[l * OC + col];
        float bias1 = ff2b[l * OC + col + 1];
        int r0 = mrow + qr, r1 = r0 + 8;
        float2 e0 = *(const float2*)(g_e + (tok0 + r0) * 64 + col);
        float2 e1 = *(const float2*)(g_e + (tok0 + r1) * 64 + col);
        sO[r0 * 72 + col]     = acc2[nt][0] + bias0 + e0.x;
        sO[r0 * 72 + col + 1] = acc2[nt][1] + bias1 + e0.y;
        sO[r1 * 72 + col]     = acc2[nt][2] + bias0 + e1.x;
        sO[r1 * 72 + col + 1] = acc2[nt][3] + bias1 + e1.y;
    }
    __syncthreads();

    int tk2 = t >> 1, half = t & 1;
    const float* ob = sO + tk2 * 72 + half * 32;
    float s = 0.f, s2 = 0.f;
    #pragma unroll
    for (int i = 0; i < 32; i++) { float v = ob[i]; s += v; s2 += v * v; }
    s  += __shfl_xor_sync(0xffffffffu, s, 1);
    s2 += __shfl_xor_sync(0xffffffffu, s2, 1);
    float mu   = s * (1.f / 64.f);
    float rstd = rsqrtf(s2 * (1.f / 64.f) - mu * mu + LN_EPS);
    float* go = g_e + (tok0 + tk2) * 64 + half * 32;
    #pragma unroll
    for (int i = 0; i < 32; i++) {
        int c = half * 32 + i;
        go[i] = (ob[i] - mu) * rstd * g2[l * OC + c] + b2[l * OC + c];
    }
}

// =====================================================================
// K5: head
// =====================================================================
__global__ void __launch_bounds__(256) k_head(
    const float* __restrict__ r1w, const float* __restrict__ r1b,
    const float* __restrict__ r2w, const float* __restrict__ r2b,
    float* __restrict__ out)
{
    __shared__ float sR1T[64 * 65];
    __shared__ float sR2[64];
    __shared__ float sP[8][64];
    int t = threadIdx.x;
    for (int i = t; i < 4096; i += 256) {
        int c = i >> 6, k = i & 63;
        sR1T[k * 65 + c] = r1w[c * 64 + k];
    }
    if (t < 64) sR2[t] = r2w[t];
    __syncthreads();
    int w = t >> 5, lane = t & 31;
    int n = blockIdx.x * 8 + w;
    const float* eb = g_e + (size_t)n * 256;
    float p0 = (eb[lane] + eb[64 + lane] + eb[128 + lane] + eb[192 + lane]) * 0.25f;
    float p1 = (eb[32 + lane] + eb[96 + lane] + eb[160 + lane] + eb[224 + lane]) * 0.25f;
    sP[w][lane]      = p0;
    sP[w][lane + 32] = p1;
    __syncwarp();
    float a0 = r1b[lane], a1 = r1b[lane + 32];
    #pragma unroll 8
    for (int k = 0; k < 64; k++) {
        float pv = sP[w][k];
        a0 = fmaf(pv, sR1T[k * 65 + lane], a0);
        a1 = fmaf(pv, sR1T[k * 65 + lane + 32], a1);
    }
    a0 = fmaxf(a0, 0.f); a1 = fmaxf(a1, 0.f);
    float acc = a0 * sR2[lane] + a1 * sR2[lane + 32];
    #pragma unroll
    for (int off = 16; off; off >>= 1) acc += __shfl_xor_sync(0xffffffffu, acc, off);
    if (lane == 0) out[n] = acc + r2b[0];
}

// =====================================================================
extern "C" void kernel_launch(void* const* d_in, const int* in_sizes, int n_in,
                              void* d_out, int out_size) {
    const float* x    = (const float*)d_in[0];
    const int*   ei   = (const int*)  d_in[1];
    const float* mpw  = (const float*)d_in[2];
    const float* W0   = (const float*)d_in[3];
    const float* b0   = (const float*)d_in[4];
    const float* Wl   = (const float*)d_in[5];
    const float* bl   = (const float*)d_in[6];
    const float* W1   = (const float*)d_in[7];
    const float* b1   = (const float*)d_in[8];
    const float* Wo   = (const float*)d_in[9];
    const float* bo   = (const float*)d_in[10];
    const float* tinw = (const float*)d_in[11];
    const float* tinb = (const float*)d_in[12];
    const float* tow  = (const float*)d_in[13];
    const float* tob  = (const float*)d_in[14];
    const float* ln1g = (const float*)d_in[15];
    const float* ln1b = (const float*)d_in[16];
    const float* ff1w = (const float*)d_in[17];
    const float* ff1b = (const float*)d_in[18];
    const float* ff2w = (const float*)d_in[19];
    const float* ff2b = (const float*)d_in[20];
    const float* ln2g = (const float*)d_in[21];
    const float* ln2b = (const float*)d_in[22];
    const float* r1w  = (const float*)d_in[23];
    const float* r1b  = (const float*)d_in[24];
    const float* r2w  = (const float*)d_in[25];
    const float* r2b  = (const float*)d_in[26];
    float* out = (float*)d_out;
    (void)in_sizes; (void)n_in; (void)out_size;

    cudaFuncSetAttribute(k_xw,   cudaFuncAttributeMaxDynamicSharedMemorySize, 110848);
    cudaFuncSetAttribute(k_gnn,  cudaFuncAttributeMaxDynamicSharedMemorySize, 51456);
    cudaFuncSetAttribute(k_attn, cudaFuncAttributeMaxDynamicSharedMemorySize, 181248);
    cudaFuncSetAttribute(k_ff,   cudaFuncAttributeMaxDynamicSharedMemorySize, 82432);

    // launch order: ncu (-s 5 -c 1) captures k_ff (6th launch)
    dim3 gxw(118, 4);
    k_xw<<<gxw, 512, 110848>>>(x, W0, b0, Wl, bl, W1, b1);                   // 1
    k_zero<<<7500, 256>>>();                                                 // 2
    k_scatter<<<120000, 256>>>(ei);                                          // 3
    k_gnn<<<gxw, 512, 51456>>>(Wo, bo, mpw);                                 // 4
    k_attn<<<NBLK, 512, 181248>>>(tinw, tinb, tow, tob, ln1g, ln1b, 0);      // 5
    k_ff<<<NBLK, 512, 82432>>>(ff1w, ff1b, ff2w, ff2b, ln2g, ln2b, 0);       // 6 <- ncu
    k_attn<<<NBLK, 512, 181248>>>(tinw, tinb, tow, tob, ln1g, ln1b, 1);
    k_ff<<<NBLK, 512, 82432>>>(ff1w, ff1b, ff2w, ff2b, ln2g, ln2b, 1);
    k_head<<<3750, 256>>>(r1w, r1b, r2w, r2b, out);
}

// round 11
// speedup vs baseline: 6.1488x; 1.0311x over previous
#include <cuda_runtime.h>
#include <cuda_fp16.h>
#include <cstdint>

typedef unsigned long long ull;

#define NN   30000
#define INC  128
#define OC   64
#define MP   4
#define EE   480000
#define FFD  2048
#define TOK  (NN*MP)
#define TB   256                     // tokens per ff/attn block
#define NBLK ((TOK + TB - 1) / TB)   // 469
#define TOKP (NBLK * TB)             // 120064 (padded)
#define JC   64                      // j per chunk (ff)
#define NCH  (FFD / JC)              // 32 chunks
#define CAP  64                      // bucket capacity per (m,node)
#define OVF_MAX 4096
#define LN_EPS 1e-5f

// ---- device scratch (allocation-free rule: __device__ globals) ----
__device__ float g_y[(size_t)MP * NN * OC];     // x @ Wl^T
__device__ float g_c[(size_t)MP * NN * OC];     // x @ Wc^T + bias
__device__ float g_aggY[(size_t)MP * NN * OC];  // aggregation result
__device__ float g_e[(size_t)TOKP * OC];        // token embeddings
__device__ int   g_cnt[MP * NN];                // per-(m,src) edge count
__device__ int   g_bkt[(size_t)MP * NN * CAP];  // dst indices  (30.7 MB)
__device__ int   g_ovf[2 * OVF_MAX];
__device__ int   g_ovf_cnt;

// ---- fp16 mma helper (m16n8k16, f32 accumulate) ----
__device__ __forceinline__ void mma_f16(float* c, const unsigned* a, const unsigned* b) {
    asm volatile(
        "mma.sync.aligned.m16n8k16.row.col.f32.f16.f16.f32 "
        "{%0,%1,%2,%3}, {%4,%5,%6,%7}, {%8,%9}, {%0,%1,%2,%3};"
        : "+f"(c[0]), "+f"(c[1]), "+f"(c[2]), "+f"(c[3])
        : "r"(a[0]), "r"(a[1]), "r"(a[2]), "r"(a[3]), "r"(b[0]), "r"(b[1]));
}
// interleaved k-pair permutation within 16-groups
__device__ __forceinline__ int hperm(int k) {
    return (k & ~15) | ((k & 6) << 1) | ((k & 8) >> 2) | (k & 1);
}
__device__ __forceinline__ unsigned pack_h2(float x, float y) {
    __half2 h = __floats2half2_rn(x, y);
    return *(unsigned*)&h;
}

// =====================================================================
// K_xw on fp16 tensor cores: y[m] = x @ Wl[m]^T ; c[m] = x @ Wc[m]^T + bias
// =====================================================================
__global__ void __launch_bounds__(512, 1) k_xw(
    const float* __restrict__ x,
    const float* __restrict__ W0, const float* __restrict__ b0,
    const float* __restrict__ Wl, const float* __restrict__ bl,
    const float* __restrict__ W1, const float* __restrict__ b1)
{
    extern __shared__ char smb[];
    __half* sX = (__half*)smb;               // [256][144]h = 73728B
    __half* sW = (__half*)(smb + 73728);     // [128][144]h = 36864B
    float*  sB = (float*)(smb + 110592);     // 64 floats
    int t = threadIdx.x, w = t >> 5, lane = t & 31;
    int qr = lane >> 2, qc = lane & 3;
    int m = blockIdx.y;
    int node0 = blockIdx.x * 256;

    for (int i = t; i < 256 * 64; i += 512) {
        int row = i >> 6, kk = (i & 63) * 2;
        int gn = node0 + row; if (gn >= NN) gn = NN - 1;
        float2 f = *(const float2*)(x + (size_t)gn * INC + kk);
        *(__half2*)(sX + row * 144 + hperm(kk)) = __floats2half2_rn(f.x, f.y);
    }
    for (int i = t; i < 128 * 64; i += 512) {
        int r = i >> 6, kk = (i & 63) * 2;
        float2 f;
        if (r < 64) {
            f = *(const float2*)(Wl + (size_t)m * 8192 + (size_t)r * 128 + kk);
        } else {
            float2 a = *(const float2*)(W0 + (size_t)m * 8192 + (size_t)(r - 64) * 128 + kk);
            float2 b = *(const float2*)(W1 + (size_t)m * 8192 + (size_t)(r - 64) * 128 + kk);
            f = make_float2(a.x + b.x, a.y + b.y);
        }
        *(__half2*)(sW + r * 144 + hperm(kk)) = __floats2half2_rn(f.x, f.y);
    }
    if (t < 64) sB[t] = b0[m * 64 + t] + bl[m * 64 + t] + b1[m * 64 + t];
    __syncthreads();

    int mrow = (w & 7) * 32;
    int nh   = w >> 3;          // 0 -> y, 1 -> c

    float acc[2][8][4];
    #pragma unroll
    for (int nt = 0; nt < 8; nt++) {
        float bv0 = 0.f, bv1 = 0.f;
        if (nh == 1) { bv0 = sB[nt * 8 + 2 * qc]; bv1 = sB[nt * 8 + 2 * qc + 1]; }
        #pragma unroll
        for (int mt = 0; mt < 2; mt++) {
            acc[mt][nt][0] = bv0; acc[mt][nt][1] = bv1;
            acc[mt][nt][2] = bv0; acc[mt][nt][3] = bv1;
        }
    }
    #pragma unroll
    for (int k0 = 0; k0 < 128; k0 += 16) {
        unsigned a[2][4];
        #pragma unroll
        for (int mt = 0; mt < 2; mt++) {
            int r0 = mrow + mt * 16;
            ull vlo = *(const ull*)(sX + (r0 + qr) * 144 + k0 + 4 * qc);
            ull vhi = *(const ull*)(sX + (r0 + 8 + qr) * 144 + k0 + 4 * qc);
            a[mt][0] = (unsigned)vlo; a[mt][2] = (unsigned)(vlo >> 32);
            a[mt][1] = (unsigned)vhi; a[mt][3] = (unsigned)(vhi >> 32);
        }
        #pragma unroll
        for (int nt = 0; nt < 8; nt++) {
            ull bv = *(const ull*)(sW + (nh * 64 + nt * 8 + qr) * 144 + k0 + 4 * qc);
            unsigned b[2] = { (unsigned)bv, (unsigned)(bv >> 32) };
            mma_f16(acc[0][nt], a[0], b);
            mma_f16(acc[1][nt], a[1], b);
        }
    }
    float* dst = nh ? g_c : g_y;
    #pragma unroll
    for (int nt = 0; nt < 8; nt++) {
        int col = nt * 8 + 2 * qc;
        #pragma unroll
        for (int mt = 0; mt < 2; mt++) {
            int r0 = mrow + mt * 16 + qr;
            int n0 = node0 + r0, n1 = n0 + 8;
            if (n0 < NN)
                *(float2*)(dst + ((size_t)m * NN + n0) * OC + col) =
                    make_float2(acc[mt][nt][0], acc[mt][nt][1]);
            if (n1 < NN)
                *(float2*)(dst + ((size_t)m * NN + n1) * OC + col) =
                    make_float2(acc[mt][nt][2], acc[mt][nt][3]);
        }
    }
}

// =====================================================================
// K0: zero counters + overflow counter
// =====================================================================
__global__ void k_zero_cnt() {
    int i = blockIdx.x * 256 + threadIdx.x;
    if (i < MP * NN) g_cnt[i] = 0;
    if (i == 0) g_ovf_cnt = 0;
}

// =====================================================================
// K1a: bucket edges by (m, src): store dst index only.
// =====================================================================
__global__ void k_bucket(const int* __restrict__ ei) {
    int eg = blockIdx.x * 256 + threadIdx.x;          // 0 .. MP*EE-1
    int m = eg / EE;
    int e = eg - m * EE;
    const int* b = ei + (size_t)m * 2 * EE;
    int src = __ldg(b + e);
    int dst = __ldg(b + EE + e);
    int gid = m * NN + src;
    int pos = atomicAdd(&g_cnt[gid], 1);
    if (pos < CAP) {
        g_bkt[(size_t)gid * CAP + pos] = dst;
    } else {
        int oi = atomicAdd(&g_ovf_cnt, 1);
        if (oi < OVF_MAX) { g_ovf[2 * oi] = gid; g_ovf[2 * oi + 1] = dst; }
    }
}

// =====================================================================
// K1b: gather-aggregate: aggY[gid] = sum over bucket dsts of y[m][dst].
// warp per (m,node); plain stores (also zeroes empty rows).
// =====================================================================
__global__ void __launch_bounds__(512) k_agg() {
    int gid  = blockIdx.x * 16 + (threadIdx.x >> 5);  // 0 .. MP*NN-1
    int lane = threadIdx.x & 31;
    int m = gid / NN;
    int cnt = g_cnt[gid]; if (cnt > CAP) cnt = CAP;
    const float* yb = g_y + (size_t)m * NN * OC;
    const int*   bk = g_bkt + (size_t)gid * CAP;
    float ax = 0.f, ay = 0.f;
    for (int base = 0; base < cnt; base += 32) {
        int d = 0;
        if (base + lane < cnt) d = bk[base + lane];
        int lim = cnt - base; if (lim > 32) lim = 32;
        for (int j = 0; j < lim; j++) {
            int dd = __shfl_sync(0xffffffffu, d, j);
            float2 v = *(const float2*)(yb + (size_t)dd * OC + 2 * lane);
            ax += v.x; ay += v.y;
        }
    }
    *(float2*)(g_aggY + (size_t)gid * OC + 2 * lane) = make_float2(ax, ay);
}

// =====================================================================
// K1c: apply (rare) overflow edges atomically.
// =====================================================================
__global__ void k_ovf() {
    int cnt = g_ovf_cnt; if (cnt > OVF_MAX) cnt = OVF_MAX;
    for (int i = 0; i < cnt; i++) {
        int gid = g_ovf[2 * i], dst = g_ovf[2 * i + 1];
        int m = gid / NN;
        atomicAdd(&g_aggY[(size_t)gid * OC + threadIdx.x],
                  g_y[((size_t)m * NN + dst) * OC + threadIdx.x]);
    }
}

// =====================================================================
// K2: GNN tail on fp16 MMA: h = relu(aggY + c); e_m = (h@Wo^T + bo)*mpw
// =====================================================================
__global__ void __launch_bounds__(512, 1) k_gnn(
    const float* __restrict__ Wo, const float* __restrict__ bo,
    const float* __restrict__ mpw)
{
    extern __shared__ char smb[];
    __half* sH  = (__half*)smb;              // [256][80]h = 40960B
    __half* sWo = (__half*)(smb + 40960);    // [64][80]h  = 10240B
    float*  sBo = (float*)(smb + 51200);     // 64
    int t = threadIdx.x, w = t >> 5, lane = t & 31;
    int qr = lane >> 2, qc = lane & 3;
    int m = blockIdx.y;
    int node0 = blockIdx.x * 256;

    for (int i = t; i < 256 * 32; i += 512) {
        int row = i >> 5, kk = (i & 31) * 2;
        int gn = node0 + row; if (gn >= NN) gn = NN - 1;
        size_t base = ((size_t)m * NN + gn) * OC + kk;
        float2 a = *(const float2*)(g_aggY + base);
        float2 c = *(const float2*)(g_c + base);
        *(__half2*)(sH + row * 80 + hperm(kk)) =
            __floats2half2_rn(fmaxf(a.x + c.x, 0.f), fmaxf(a.y + c.y, 0.f));
    }
    for (int i = t; i < 64 * 32; i += 512) {
        int r = i >> 5, kk = (i & 31) * 2;
        float2 f = *(const float2*)(Wo + (size_t)m * 4096 + (size_t)r * 64 + kk);
        *(__half2*)(sWo + r * 80 + hperm(kk)) = __floats2half2_rn(f.x, f.y);
    }
    if (t < 64) sBo[t] = bo[m * 64 + t];
    __syncthreads();

    int mrow = (w & 7) * 32;
    int nh   = w >> 3;
    float wgt = mpw[m];

    float acc[2][4][4];
    #pragma unroll
    for (int mt = 0; mt < 2; mt++)
        #pragma unroll
        for (int nt = 0; nt < 4; nt++)
            #pragma unroll
            for (int q = 0; q < 4; q++) acc[mt][nt][q] = 0.f;

    #pragma unroll
    for (int k0 = 0; k0 < 64; k0 += 16) {
        unsigned a[2][4];
        #pragma unroll
        for (int mt = 0; mt < 2; mt++) {
            int r0 = mrow + mt * 16;
            ull vlo = *(const ull*)(sH + (r0 + qr) * 80 + k0 + 4 * qc);
            ull vhi = *(const ull*)(sH + (r0 + 8 + qr) * 80 + k0 + 4 * qc);
            a[mt][0] = (unsigned)vlo; a[mt][2] = (unsigned)(vlo >> 32);
            a[mt][1] = (unsigned)vhi; a[mt][3] = (unsigned)(vhi >> 32);
        }
        #pragma unroll
        for (int nt = 0; nt < 4; nt++) {
            ull bv = *(const ull*)(sWo + (nh * 32 + nt * 8 + qr) * 80 + k0 + 4 * qc);
            unsigned b[2] = { (unsigned)bv, (unsigned)(bv >> 32) };
            mma_f16(acc[0][nt], a[0], b);
            mma_f16(acc[1][nt], a[1], b);
        }
    }
    #pragma unroll
    for (int nt = 0; nt < 4; nt++) {
        int col = nh * 32 + nt * 8 + 2 * qc;
        float bias0 = sBo[col], bias1 = sBo[col + 1];
        #pragma unroll
        for (int mt = 0; mt < 2; mt++) {
            int r0 = mrow + mt * 16 + qr;
            int n0 = node0 + r0, n1 = n0 + 8;
            if (n0 < NN)
                *(float2*)(g_e + ((size_t)n0 * MP + m) * OC + col) =
                    make_float2((acc[mt][nt][0] + bias0) * wgt, (acc[mt][nt][1] + bias1) * wgt);
            if (n1 < NN)
                *(float2*)(g_e + ((size_t)n1 * MP + m) * OC + col) =
                    make_float2((acc[mt][nt][2] + bias0) * wgt, (acc[mt][nt][3] + bias1) * wgt);
        }
    }
}

// =====================================================================
// K3: attention sublayer on fp16 tensor cores (unchanged from R10).
// =====================================================================
__global__ void __launch_bounds__(512, 1) k_attn(
    const float* __restrict__ tinw, const float* __restrict__ tinb,
    const float* __restrict__ tow,  const float* __restrict__ tob,
    const float* __restrict__ g1,   const float* __restrict__ b1v, int l)
{
    extern __shared__ char smb[];
    __half* sE   = (__half*)smb;                 // [256][80]h (alias sAO)
    __half* sWin = (__half*)(smb + 40960);       // [192][80]h
    __half* sQKV = (__half*)(smb + 71680);       // [64 node][768]h (alias sO)
    __half* sWo  = (__half*)(smb + 169984);      // [64][80]h
    float*  sBin = (float*)(smb + 180224);       // 192
    float*  sBo  = (float*)(smb + 180992);       // 64
    __half* sAO  = sE;
    float*  sO   = (float*)(smb + 71680);        // epilogue [256][72]f
    int t = threadIdx.x, w = t >> 5, lane = t & 31;
    int qr = lane >> 2, qc = lane & 3;
    size_t tok0 = (size_t)blockIdx.x * TB;

    const float* tw  = tinw + (size_t)l * 192 * 64;
    const float* twO = tow  + (size_t)l * 64 * 64;
    for (int i = t; i < 192 * 32; i += 512) {
        int r = i >> 5, kk = (i & 31) * 2;
        float2 f = *(const float2*)(tw + (size_t)r * 64 + kk);
        *(__half2*)(sWin + r * 80 + hperm(kk)) = __floats2half2_rn(f.x, f.y);
    }
    for (int i = t; i < 64 * 32; i += 512) {
        int r = i >> 5, kk = (i & 31) * 2;
        float2 f = *(const float2*)(twO + (size_t)r * 64 + kk);
        *(__half2*)(sWo + r * 80 + hperm(kk)) = __floats2half2_rn(f.x, f.y);
    }
    for (int i = t; i < TB * 32; i += 512) {
        int row = i >> 5, kk = (i & 31) * 2;
        float2 f = *(const float2*)(g_e + (tok0 + row) * 64 + kk);
        *(__half2*)(sE + row * 80 + hperm(kk)) = __floats2half2_rn(f.x, f.y);
    }
    if (t < 192) sBin[t] = tinb[l * 192 + t];
    if (t >= 192 && t < 256) sBo[t - 192] = tob[l * 64 + (t - 192)];
    __syncthreads();

    int mrow = (w & 7) * 32;
    int nh   = w >> 3;

    #pragma unroll
    for (int np = 0; np < 2; np++) {
        float acc[2][6][4];
        #pragma unroll
        for (int nt = 0; nt < 6; nt++) {
            int col = nh * 96 + np * 48 + nt * 8 + 2 * qc;
            float bv0 = sBin[col], bv1 = sBin[col + 1];
            #pragma unroll
            for (int mt = 0; mt < 2; mt++) {
                acc[mt][nt][0] = bv0; acc[mt][nt][1] = bv1;
                acc[mt][nt][2] = bv0; acc[mt][nt][3] = bv1;
            }
        }
        #pragma unroll
        for (int k0 = 0; k0 < 64; k0 += 16) {
            unsigned a[2][4];
            #pragma unroll
            for (int mt = 0; mt < 2; mt++) {
                int r0 = mrow + mt * 16;
                ull vlo = *(const ull*)(sE + (r0 + qr) * 80 + k0 + 4 * qc);
                ull vhi = *(const ull*)(sE + (r0 + 8 + qr) * 80 + k0 + 4 * qc);
                a[mt][0] = (unsigned)vlo; a[mt][2] = (unsigned)(vlo >> 32);
                a[mt][1] = (unsigned)vhi; a[mt][3] = (unsigned)(vhi >> 32);
            }
            #pragma unroll
            for (int nt = 0; nt < 6; nt++) {
                ull bv = *(const ull*)(sWin + (nh * 96 + np * 48 + nt * 8 + qr) * 80 + k0 + 4 * qc);
                unsigned b[2] = { (unsigned)bv, (unsigned)(bv >> 32) };
                mma_f16(acc[0][nt], a[0], b);
                mma_f16(acc[1][nt], a[1], b);
            }
        }
        #pragma unroll
        for (int nt = 0; nt < 6; nt++) {
            int col = nh * 96 + np * 48 + nt * 8 + 2 * qc;
            #pragma unroll
            for (int mt = 0; mt < 2; mt++) {
                int r0 = mrow + mt * 16 + qr;
                int r1 = r0 + 8;
                *(__half2*)(sQKV + (r0 >> 2) * 768 + (r0 & 3) * 192 + col) =
                    __floats2half2_rn(acc[mt][nt][0], acc[mt][nt][1]);
                *(__half2*)(sQKV + (r1 >> 2) * 768 + (r1 & 3) * 192 + col) =
                    __floats2half2_rn(acc[mt][nt][2], acc[mt][nt][3]);
            }
        }
    }
    __syncthreads();

    #pragma unroll
    for (int it = 0; it < 4; it++) {
        int u = it * 512 + t;
        int node = u >> 5, hd = (u >> 2) & 7, mq = u & 3;
        const __half* base = sQKV + node * 768;
        float q[8];
        #pragma unroll
        for (int d = 0; d < 4; d++) {
            float2 f = __half22float2(*(const __half2*)(base + mq * 192 + hd * 8 + 2 * d));
            q[2 * d] = f.x; q[2 * d + 1] = f.y;
        }
        float sc[4];
        #pragma unroll
        for (int mk = 0; mk < 4; mk++) {
            const __half* kp = base + mk * 192 + 64 + hd * 8;
            float a = 0.f;
            #pragma unroll
            for (int d = 0; d < 4; d++) {
                float2 f = __half22float2(*(const __half2*)(kp + 2 * d));
                a = fmaf(q[2 * d], f.x, a); a = fmaf(q[2 * d + 1], f.y, a);
            }
            sc[mk] = a * 0.35355339059327373f;
        }
        float mx = fmaxf(fmaxf(sc[0], sc[1]), fmaxf(sc[2], sc[3]));
        float p[4]; float psum = 0.f;
        #pragma unroll
        for (int mk = 0; mk < 4; mk++) { p[mk] = __expf(sc[mk] - mx); psum += p[mk]; }
        float inv = 1.0f / psum;
        float o[8];
        #pragma unroll
        for (int d = 0; d < 8; d++) o[d] = 0.f;
        #pragma unroll
        for (int mk = 0; mk < 4; mk++) {
            const __half* vp = base + mk * 192 + 128 + hd * 8;
            float pw = p[mk] * inv;
            #pragma unroll
            for (int d = 0; d < 4; d++) {
                float2 f = __half22float2(*(const __half2*)(vp + 2 * d));
                o[2 * d]     = fmaf(pw, f.x, o[2 * d]);
                o[2 * d + 1] = fmaf(pw, f.y, o[2 * d + 1]);
            }
        }
        int row = node * 4 + mq;
        #pragma unroll
        for (int d = 0; d < 4; d++) {
            int col = hd * 8 + 2 * d;
            *(__half2*)(sAO + row * 80 + hperm(col)) = __floats2half2_rn(o[2 * d], o[2 * d + 1]);
        }
    }
    __syncthreads();

    {
        float acc[2][4][4];
        #pragma unroll
        for (int mt = 0; mt < 2; mt++)
            #pragma unroll
            for (int nt = 0; nt < 4; nt++)
                #pragma unroll
                for (int q = 0; q < 4; q++) acc[mt][nt][q] = 0.f;
        #pragma unroll
        for (int k0 = 0; k0 < 64; k0 += 16) {
            unsigned a[2][4];
            #pragma unroll
            for (int mt = 0; mt < 2; mt++) {
                int r0 = mrow + mt * 16;
                ull vlo = *(const ull*)(sAO + (r0 + qr) * 80 + k0 + 4 * qc);
                ull vhi = *(const ull*)(sAO + (r0 + 8 + qr) * 80 + k0 + 4 * qc);
                a[mt][0] = (unsigned)vlo; a[mt][2] = (unsigned)(vlo >> 32);
                a[mt][1] = (unsigned)vhi; a[mt][3] = (unsigned)(vhi >> 32);
            }
            #pragma unroll
            for (int nt = 0; nt < 4; nt++) {
                ull bv = *(const ull*)(sWo + (nh * 32 + nt * 8 + qr) * 80 + k0 + 4 * qc);
                unsigned b[2] = { (unsigned)bv, (unsigned)(bv >> 32) };
                mma_f16(acc[0][nt], a[0], b);
                mma_f16(acc[1][nt], a[1], b);
            }
        }
        __syncthreads();
        #pragma unroll
        for (int nt = 0; nt < 4; nt++) {
            int col = nh * 32 + nt * 8 + 2 * qc;
            float bias0 = sBo[col], bias1 = sBo[col + 1];
            #pragma unroll
            for (int mt = 0; mt < 2; mt++) {
                int r0 = mrow + mt * 16 + qr;
                int r1 = r0 + 8;
                float2 e0 = *(const float2*)(g_e + (tok0 + r0) * 64 + col);
                float2 e1 = *(const float2*)(g_e + (tok0 + r1) * 64 + col);
                sO[r0 * 72 + col]     = acc[mt][nt][0] + bias0 + e0.x;
                sO[r0 * 72 + col + 1] = acc[mt][nt][1] + bias1 + e0.y;
                sO[r1 * 72 + col]     = acc[mt][nt][2] + bias0 + e1.x;
                sO[r1 * 72 + col + 1] = acc[mt][nt][3] + bias1 + e1.y;
            }
        }
    }
    __syncthreads();

    int tk2 = t >> 1, half = t & 1;
    const float* ob = sO + tk2 * 72 + half * 32;
    float s = 0.f, s2 = 0.f;
    #pragma unroll
    for (int i = 0; i < 32; i++) { float v = ob[i]; s += v; s2 += v * v; }
    s  += __shfl_xor_sync(0xffffffffu, s, 1);
    s2 += __shfl_xor_sync(0xffffffffu, s2, 1);
    float mu   = s * (1.f / 64.f);
    float rstd = rsqrtf(s2 * (1.f / 64.f) - mu * mu + LN_EPS);
    float* go = g_e + (tok0 + tk2) * 64 + half * 32;
    #pragma unroll
    for (int i = 0; i < 32; i++) {
        int c = half * 32 + i;
        go[i] = (ob[i] - mu) * rstd * g1[l * 64 + c] + b1v[l * 64 + c];
    }
}

// =====================================================================
// K4: FF on fp16 MMA, register-resident H, double-buffered weights.
// =====================================================================
__global__ void __launch_bounds__(512, 1) k_ff(
    const float* __restrict__ ff1w, const float* __restrict__ ff1b,
    const float* __restrict__ ff2w, const float* __restrict__ ff2b,
    const float* __restrict__ g2,   const float* __restrict__ b2, int l)
{
    extern __shared__ char smb[];
    __half* sE  = (__half*)smb;              // [256][80]h = 40960B
    __half* sW1 = (__half*)(smb + 40960);    // [2][64][80]h
    __half* sW2 = (__half*)(smb + 61440);    // [2][64][80]h
    float*  sB1 = (float*)(smb + 81920);     // [2][64]
    float*  sO  = (float*)smb;               // alias epilogue [256][72]f
    int t = threadIdx.x, w = t >> 5, lane = t & 31;
    int qr = lane >> 2, qc = lane & 3;
    size_t tok0 = (size_t)blockIdx.x * TB;
    int mrow = w * 16;

    const float* f1w = ff1w + (size_t)l * FFD * OC;
    const float* f1b = ff1b + (size_t)l * FFD;
    const float* f2w = ff2w + (size_t)l * OC * FFD;

    for (int i = t; i < TB * 32; i += 512) {
        int row = i >> 5, kk = (i & 31) * 2;
        float2 f = *(const float2*)(g_e + tok0 * 64 + (size_t)row * 64 + kk);
        *(__half2*)(sE + row * 80 + hperm(kk)) = __floats2half2_rn(f.x, f.y);
    }
    for (int i = t; i < JC * 32; i += 512) {
        int j = i >> 5, kk = (i & 31) * 2;
        float2 f = *(const float2*)(f1w + (size_t)j * 64 + kk);
        *(__half2*)(sW1 + j * 80 + hperm(kk)) = __floats2half2_rn(f.x, f.y);
    }
    for (int i = t; i < 64 * 32; i += 512) {
        int c = i >> 5, jj = (i & 31) * 2;
        float2 f = *(const float2*)(f2w + (size_t)c * FFD + jj);
        *(__half2*)(sW2 + c * 80 + hperm(jj)) = __floats2half2_rn(f.x, f.y);
    }
    if (t < 64) sB1[t] = f1b[t];
    __syncthreads();

    float acc2[8][4];
    #pragma unroll
    for (int nt = 0; nt < 8; nt++)
        #pragma unroll
        for (int q = 0; q < 4; q++) acc2[nt][q] = 0.f;

    for (int ch = 0; ch < NCH; ch++) {
        int buf = ch & 1, nb = buf ^ 1;
        const __half* w1 = sW1 + buf * 5120;
        const __half* w2 = sW2 + buf * 5120;
        const float*  bb = sB1 + buf * 64;
        int jb2 = (ch + 1) * JC;

        float2 w1n[4], w2n[4]; float b1n = 0.f;
        if (ch < NCH - 1) {
            #pragma unroll
            for (int r = 0; r < 4; r++) {
                int idx = t + r * 512;
                int j = idx >> 5, kk = (idx & 31) * 2;
                w1n[r] = *(const float2*)(f1w + (size_t)(jb2 + j) * 64 + kk);
            }
            #pragma unroll
            for (int r = 0; r < 4; r++) {
                int idx = t + r * 512;
                int c = idx >> 5, jj = (idx & 31) * 2;
                w2n[r] = *(const float2*)(f2w + (size_t)c * FFD + jb2 + jj);
            }
            if (t < 64) b1n = f1b[jb2 + t];
        }

        float acc1[8][4];
        #pragma unroll
        for (int nt = 0; nt < 8; nt++) {
            float bv0 = bb[nt * 8 + 2 * qc];
            float bv1 = bb[nt * 8 + 2 * qc + 1];
            acc1[nt][0] = bv0; acc1[nt][1] = bv1;
            acc1[nt][2] = bv0; acc1[nt][3] = bv1;
        }
        #pragma unroll
        for (int k0 = 0; k0 < 64; k0 += 16) {
            ull vlo = *(const ull*)(sE + (mrow + qr) * 80 + k0 + 4 * qc);
            ull vhi = *(const ull*)(sE + (mrow + 8 + qr) * 80 + k0 + 4 * qc);
            unsigned a[4] = { (unsigned)vlo, (unsigned)vhi,
                              (unsigned)(vlo >> 32), (unsigned)(vhi >> 32) };
            #pragma unroll
            for (int nt = 0; nt < 8; nt++) {
                ull bv = *(const ull*)(w1 + (nt * 8 + qr) * 80 + k0 + 4 * qc);
                unsigned b[2] = { (unsigned)bv, (unsigned)(bv >> 32) };
                mma_f16(acc1[nt], a, b);
            }
        }

        unsigned afr[4][4];
        #pragma unroll
        for (int kt = 0; kt < 4; kt++) {
            afr[kt][0] = pack_h2(fmaxf(acc1[2 * kt][0], 0.f),     fmaxf(acc1[2 * kt][1], 0.f));
            afr[kt][1] = pack_h2(fmaxf(acc1[2 * kt][2], 0.f),     fmaxf(acc1[2 * kt][3], 0.f));
            afr[kt][2] = pack_h2(fmaxf(acc1[2 * kt + 1][0], 0.f), fmaxf(acc1[2 * kt + 1][1], 0.f));
            afr[kt][3] = pack_h2(fmaxf(acc1[2 * kt + 1][2], 0.f), fmaxf(acc1[2 * kt + 1][3], 0.f));
        }

        #pragma unroll
        for (int kt = 0; kt < 4; kt++) {
            #pragma unroll
            for (int nt = 0; nt < 8; nt++) {
                ull bv = *(const ull*)(w2 + (nt * 8 + qr) * 80 + kt * 16 + 4 * qc);
                unsigned b[2] = { (unsigned)bv, (unsigned)(bv >> 32) };
                mma_f16(acc2[nt], afr[kt], b);
            }
        }

        if (ch < NCH - 1) {
            #pragma unroll
            for (int r = 0; r < 4; r++) {
                int idx = t + r * 512;
                int j = idx >> 5, kk = (idx & 31) * 2;
                *(__half2*)(sW1 + nb * 5120 + j * 80 + hperm(kk)) =
                    __floats2half2_rn(w1n[r].x, w1n[r].y);
            }
            #pragma unroll
            for (int r = 0; r < 4; r++) {
                int idx = t + r * 512;
                int c = idx >> 5, jj = (idx & 31) * 2;
                *(__half2*)(sW2 + nb * 5120 + c * 80 + hperm(jj)) =
                    __floats2half2_rn(w2n[r].x, w2n[r].y);
            }
            if (t < 64) sB1[nb * 64 + t] = b1n;
        }
        __syncthreads();
    }

    #pragma unroll
    for (int nt = 0; nt < 8; nt++) {
        int col = nt * 8 + 2 * qc;
        float bias0 = ff2b[l * OC + col];
        float bias1 = ff2b[l * OC + col + 1];
        int r0 = mrow + qr, r1 = r0 + 8;
        float2 e0 = *(const float2*)(g_e + (tok0 + r0) * 64 + col);
        float2 e1 = *(const float2*)(g_e + (tok0 + r1) * 64 + col);
        sO[r0 * 72 + col]     = acc2[nt][0] + bias0 + e0.x;
        sO[r0 * 72 + col + 1] = acc2[nt][1] + bias1 + e0.y;
        sO[r1 * 72 + col]     = acc2[nt][2] + bias0 + e1.x;
        sO[r1 * 72 + col + 1] = acc2[nt][3] + bias1 + e1.y;
    }
    __syncthreads();

    int tk2 = t >> 1, half = t & 1;
    const float* ob = sO + tk2 * 72 + half * 32;
    float s = 0.f, s2 = 0.f;
    #pragma unroll
    for (int i = 0; i < 32; i++) { float v = ob[i]; s += v; s2 += v * v; }
    s  += __shfl_xor_sync(0xffffffffu, s, 1);
    s2 += __shfl_xor_sync(0xffffffffu, s2, 1);
    float mu   = s * (1.f / 64.f);
    float rstd = rsqrtf(s2 * (1.f / 64.f) - mu * mu + LN_EPS);
    float* go = g_e + (tok0 + tk2) * 64 + half * 32;
    #pragma unroll
    for (int i = 0; i < 32; i++) {
        int c = half * 32 + i;
        go[i] = (ob[i] - mu) * rstd * g2[l * OC + c] + b2[l * OC + c];
    }
}

// =====================================================================
// K5: head
// =====================================================================
__global__ void __launch_bounds__(256) k_head(
    const float* __restrict__ r1w, const float* __restrict__ r1b,
    const float* __restrict__ r2w, const float* __restrict__ r2b,
    float* __restrict__ out)
{
    __shared__ float sR1T[64 * 65];
    __shared__ float sR2[64];
    __shared__ float sP[8][64];
    int t = threadIdx.x;
    for (int i = t; i < 4096; i += 256) {
        int c = i >> 6, k = i & 63;
        sR1T[k * 65 + c] = r1w[c * 64 + k];
    }
    if (t < 64) sR2[t] = r2w[t];
    __syncthreads();
    int w = t >> 5, lane = t & 31;
    int n = blockIdx.x * 8 + w;
    const float* eb = g_e + (size_t)n * 256;
    float p0 = (eb[lane] + eb[64 + lane] + eb[128 + lane] + eb[192 + lane]) * 0.25f;
    float p1 = (eb[32 + lane] + eb[96 + lane] + eb[160 + lane] + eb[224 + lane]) * 0.25f;
    sP[w][lane]      = p0;
    sP[w][lane + 32] = p1;
    __syncwarp();
    float a0 = r1b[lane], a1 = r1b[lane + 32];
    #pragma unroll 8
    for (int k = 0; k < 64; k++) {
        float pv = sP[w][k];
        a0 = fmaf(pv, sR1T[k * 65 + lane], a0);
        a1 = fmaf(pv, sR1T[k * 65 + lane + 32], a1);
    }
    a0 = fmaxf(a0, 0.f); a1 = fmaxf(a1, 0.f);
    float acc = a0 * sR2[lane] + a1 * sR2[lane + 32];
    #pragma unroll
    for (int off = 16; off; off >>= 1) acc += __shfl_xor_sync(0xffffffffu, acc, off);
    if (lane == 0) out[n] = acc + r2b[0];
}

// =====================================================================
extern "C" void kernel_launch(void* const* d_in, const int* in_sizes, int n_in,
                              void* d_out, int out_size) {
    const float* x    = (const float*)d_in[0];
    const int*   ei   = (const int*)  d_in[1];
    const float* mpw  = (const float*)d_in[2];
    const float* W0   = (const float*)d_in[3];
    const float* b0   = (const float*)d_in[4];
    const float* Wl   = (const float*)d_in[5];
    const float* bl   = (const float*)d_in[6];
    const float* W1   = (const float*)d_in[7];
    const float* b1   = (const float*)d_in[8];
    const float* Wo   = (const float*)d_in[9];
    const float* bo   = (const float*)d_in[10];
    const float* tinw = (const float*)d_in[11];
    const float* tinb = (const float*)d_in[12];
    const float* tow  = (const float*)d_in[13];
    const float* tob  = (const float*)d_in[14];
    const float* ln1g = (const float*)d_in[15];
    const float* ln1b = (const float*)d_in[16];
    const float* ff1w = (const float*)d_in[17];
    const float* ff1b = (const float*)d_in[18];
    const float* ff2w = (const float*)d_in[19];
    const float* ff2b = (const float*)d_in[20];
    const float* ln2g = (const float*)d_in[21];
    const float* ln2b = (const float*)d_in[22];
    const float* r1w  = (const float*)d_in[23];
    const float* r1b  = (const float*)d_in[24];
    const float* r2w  = (const float*)d_in[25];
    const float* r2b  = (const float*)d_in[26];
    float* out = (float*)d_out;
    (void)in_sizes; (void)n_in; (void)out_size;

    cudaFuncSetAttribute(k_xw,   cudaFuncAttributeMaxDynamicSharedMemorySize, 110848);
    cudaFuncSetAttribute(k_gnn,  cudaFuncAttributeMaxDynamicSharedMemorySize, 51456);
    cudaFuncSetAttribute(k_attn, cudaFuncAttributeMaxDynamicSharedMemorySize, 181248);
    cudaFuncSetAttribute(k_ff,   cudaFuncAttributeMaxDynamicSharedMemorySize, 82432);

    dim3 gxw(118, 4);
    k_zero_cnt<<<469, 256>>>();                                              // 1
    k_xw<<<gxw, 512, 110848>>>(x, W0, b0, Wl, bl, W1, b1);                   // 2
    k_bucket<<<7500, 256>>>(ei);                                             // 3
    k_agg<<<7500, 512>>>();                                                  // 4
    k_ovf<<<1, 64>>>();                                                      // 5
    k_gnn<<<gxw, 512, 51456>>>(Wo, bo, mpw);                                 // 6 <- ncu
    k_attn<<<NBLK, 512, 181248>>>(tinw, tinb, tow, tob, ln1g, ln1b, 0);
    k_ff<<<NBLK, 512, 82432>>>(ff1w, ff1b, ff2w, ff2b, ln2g, ln2b, 0);
    k_attn<<<NBLK, 512, 181248>>>(tinw, tinb, tow, tob, ln1g, ln1b, 1);
    k_ff<<<NBLK, 512, 82432>>>(ff1w, ff1b, ff2w, ff2b, ln2g, ln2b, 1);
    k_head<<<3750, 256>>>(r1w, r1b, r2w, r2b, out);
}

// round 16
// speedup vs baseline: 6.2176x; 1.0112x over previous
#include <cuda_runtime.h>
#include <cuda_fp16.h>
#include <cstdint>

typedef unsigned long long ull;

#define NN   30000
#define INC  128
#define OC   64
#define MP   4
#define EE   480000
#define FFD  2048
#define TOK  (NN*MP)
#define TB   256                     // tokens per ff block
#define NBLK ((TOK + TB - 1) / TB)   // 469
#define TOKP (NBLK * TB)             // 120064 (padded)
#define TBA  128                     // tokens per attn block
#define NBA  (TOKP / TBA)            // 938
#define JC   64                      // j per chunk (ff)
#define NCH  (FFD / JC)              // 32 chunks
#define CAP  64
#define OVF_MAX 4096
#define LN_EPS 1e-5f

// ---- device scratch (zero-initialized at module load) ----
__device__ float g_y[(size_t)MP * NN * OC];
__device__ float g_c[(size_t)MP * NN * OC];
__device__ float g_aggY[(size_t)MP * NN * OC];
__device__ float g_e[(size_t)TOKP * OC];
__device__ int   g_cnt[MP * NN];
__device__ int   g_bkt[(size_t)MP * NN * CAP];
__device__ int   g_ovf[2 * OVF_MAX];
__device__ int   g_ovf_cnt;

// ---- fp16 mma.sync helper ----
__device__ __forceinline__ void mma_f16(float* c, const unsigned* a, const unsigned* b) {
    asm volatile(
        "mma.sync.aligned.m16n8k16.row.col.f32.f16.f16.f32 "
        "{%0,%1,%2,%3}, {%4,%5,%6,%7}, {%8,%9}, {%0,%1,%2,%3};"
        : "+f"(c[0]), "+f"(c[1]), "+f"(c[2]), "+f"(c[3])
        : "r"(a[0]), "r"(a[1]), "r"(a[2]), "r"(a[3]), "r"(b[0]), "r"(b[1]));
}
__device__ __forceinline__ int hperm(int k) {
    return (k & ~15) | ((k & 6) << 1) | ((k & 8) >> 2) | (k & 1);
}
__device__ __forceinline__ unsigned pack_h2(float x, float y) {
    __half2 h = __floats2half2_rn(x, y);
    return *(unsigned*)&h;
}

// =====================================================================
// K_xw: y = x@Wl^T ; c = x@Wc^T + bias, fp16 mma.sync
// =====================================================================
__global__ void __launch_bounds__(512, 1) k_xw(
    const float* __restrict__ x,
    const float* __restrict__ W0, const float* __restrict__ b0,
    const float* __restrict__ Wl, const float* __restrict__ bl,
    const float* __restrict__ W1, const float* __restrict__ b1)
{
    extern __shared__ char smb[];
    __half* sX = (__half*)smb;               // [256][144]h
    __half* sW = (__half*)(smb + 73728);     // [128][144]h
    float*  sB = (float*)(smb + 110592);     // 64
    int t = threadIdx.x, w = t >> 5, lane = t & 31;
    int qr = lane >> 2, qc = lane & 3;
    int m = blockIdx.y;
    int node0 = blockIdx.x * 256;

    for (int i = t; i < 256 * 64; i += 512) {
        int row = i >> 6, kk = (i & 63) * 2;
        int gn = node0 + row; if (gn >= NN) gn = NN - 1;
        float2 f = *(const float2*)(x + (size_t)gn * INC + kk);
        *(__half2*)(sX + row * 144 + hperm(kk)) = __floats2half2_rn(f.x, f.y);
    }
    for (int i = t; i < 128 * 64; i += 512) {
        int r = i >> 6, kk = (i & 63) * 2;
        float2 f;
        if (r < 64) {
            f = *(const float2*)(Wl + (size_t)m * 8192 + (size_t)r * 128 + kk);
        } else {
            float2 a = *(const float2*)(W0 + (size_t)m * 8192 + (size_t)(r - 64) * 128 + kk);
            float2 b = *(const float2*)(W1 + (size_t)m * 8192 + (size_t)(r - 64) * 128 + kk);
            f = make_float2(a.x + b.x, a.y + b.y);
        }
        *(__half2*)(sW + r * 144 + hperm(kk)) = __floats2half2_rn(f.x, f.y);
    }
    if (t < 64) sB[t] = b0[m * 64 + t] + bl[m * 64 + t] + b1[m * 64 + t];
    __syncthreads();

    int mrow = (w & 7) * 32;
    int nh   = w >> 3;          // 0 -> y, 1 -> c

    float acc[2][8][4];
    #pragma unroll
    for (int nt = 0; nt < 8; nt++) {
        float bv0 = 0.f, bv1 = 0.f;
        if (nh == 1) { bv0 = sB[nt * 8 + 2 * qc]; bv1 = sB[nt * 8 + 2 * qc + 1]; }
        #pragma unroll
        for (int mt = 0; mt < 2; mt++) {
            acc[mt][nt][0] = bv0; acc[mt][nt][1] = bv1;
            acc[mt][nt][2] = bv0; acc[mt][nt][3] = bv1;
        }
    }
    #pragma unroll
    for (int k0 = 0; k0 < 128; k0 += 16) {
        unsigned a[2][4];
        #pragma unroll
        for (int mt = 0; mt < 2; mt++) {
            int r0 = mrow + mt * 16;
            ull vlo = *(const ull*)(sX + (r0 + qr) * 144 + k0 + 4 * qc);
            ull vhi = *(const ull*)(sX + (r0 + 8 + qr) * 144 + k0 + 4 * qc);
            a[mt][0] = (unsigned)vlo; a[mt][2] = (unsigned)(vlo >> 32);
            a[mt][1] = (unsigned)vhi; a[mt][3] = (unsigned)(vhi >> 32);
        }
        #pragma unroll
        for (int nt = 0; nt < 8; nt++) {
            ull bv = *(const ull*)(sW + (nh * 64 + nt * 8 + qr) * 144 + k0 + 4 * qc);
            unsigned b[2] = { (unsigned)bv, (unsigned)(bv >> 32) };
            mma_f16(acc[0][nt], a[0], b);
            mma_f16(acc[1][nt], a[1], b);
        }
    }
    float* dst = nh ? g_c : g_y;
    #pragma unroll
    for (int nt = 0; nt < 8; nt++) {
        int col = nt * 8 + 2 * qc;
        #pragma unroll
        for (int mt = 0; mt < 2; mt++) {
            int r0 = mrow + mt * 16 + qr;
            int n0 = node0 + r0, n1 = n0 + 8;
            if (n0 < NN)
                *(float2*)(dst + ((size_t)m * NN + n0) * OC + col) =
                    make_float2(acc[mt][nt][0], acc[mt][nt][1]);
            if (n1 < NN)
                *(float2*)(dst + ((size_t)m * NN + n1) * OC + col) =
                    make_float2(acc[mt][nt][2], acc[mt][nt][3]);
        }
    }
}

// =====================================================================
// K1a: bucket edges by (m, src). (g_cnt zeroed by k_agg of previous run;
// zero-initialized at module load for the first run.)
// =====================================================================
__global__ void k_bucket(const int* __restrict__ ei) {
    int eg = blockIdx.x * 256 + threadIdx.x;
    int m = eg / EE;
    int e = eg - m * EE;
    const int* b = ei + (size_t)m * 2 * EE;
    int src = __ldg(b + e);
    int dst = __ldg(b + EE + e);
    int gid = m * NN + src;
    int pos = atomicAdd(&g_cnt[gid], 1);
    if (pos < CAP) {
        g_bkt[(size_t)gid * CAP + pos] = dst;
    } else {
        int oi = atomicAdd(&g_ovf_cnt, 1);
        if (oi < OVF_MAX) { g_ovf[2 * oi] = gid; g_ovf[2 * oi + 1] = dst; }
    }
}

// =====================================================================
// K1b: gather-aggregate; zeroes g_cnt after use (self-cleaning).
// =====================================================================
__global__ void __launch_bounds__(512) k_agg() {
    int gid  = blockIdx.x * 16 + (threadIdx.x >> 5);
    int lane = threadIdx.x & 31;
    int m = gid / NN;
    int cnt = g_cnt[gid]; if (cnt > CAP) cnt = CAP;
    const float* yb = g_y + (size_t)m * NN * OC;
    const int*   bk = g_bkt + (size_t)gid * CAP;
    float ax = 0.f, ay = 0.f;
    for (int base = 0; base < cnt; base += 32) {
        int d = 0;
        if (base + lane < cnt) d = bk[base + lane];
        int lim = cnt - base; if (lim > 32) lim = 32;
        for (int j = 0; j < lim; j++) {
            int dd = __shfl_sync(0xffffffffu, d, j);
            float2 v = *(const float2*)(yb + (size_t)dd * OC + 2 * lane);
            ax += v.x; ay += v.y;
        }
    }
    *(float2*)(g_aggY + (size_t)gid * OC + 2 * lane) = make_float2(ax, ay);
    if (lane == 0) g_cnt[gid] = 0;
}

// =====================================================================
// K1c: overflow fixup; resets overflow counter (self-cleaning).
// =====================================================================
__global__ void k_ovf() {
    int cnt = g_ovf_cnt; if (cnt > OVF_MAX) cnt = OVF_MAX;
    for (int i = 0; i < cnt; i++) {
        int gid = g_ovf[2 * i], dst = g_ovf[2 * i + 1];
        int m = gid / NN;
        atomicAdd(&g_aggY[(size_t)gid * OC + threadIdx.x],
                  g_y[((size_t)m * NN + dst) * OC + threadIdx.x]);
    }
    __syncthreads();
    if (threadIdx.x == 0) g_ovf_cnt = 0;
}

// =====================================================================
// K2: GNN tail: h = relu(aggY + c); e_m = (h@Wo^T + bo)*mpw
// =====================================================================
__global__ void __launch_bounds__(512, 1) k_gnn(
    const float* __restrict__ Wo, const float* __restrict__ bo,
    const float* __restrict__ mpw)
{
    extern __shared__ char smb[];
    __half* sH  = (__half*)smb;              // [256][80]h
    __half* sWo = (__half*)(smb + 40960);    // [64][80]h
    float*  sBo = (float*)(smb + 51200);     // 64
    int t = threadIdx.x, w = t >> 5, lane = t & 31;
    int qr = lane >> 2, qc = lane & 3;
    int m = blockIdx.y;
    int node0 = blockIdx.x * 256;

    for (int i = t; i < 256 * 32; i += 512) {
        int row = i >> 5, kk = (i & 31) * 2;
        int gn = node0 + row; if (gn >= NN) gn = NN - 1;
        size_t base = ((size_t)m * NN + gn) * OC + kk;
        float2 a = *(const float2*)(g_aggY + base);
        float2 c = *(const float2*)(g_c + base);
        *(__half2*)(sH + row * 80 + hperm(kk)) =
            __floats2half2_rn(fmaxf(a.x + c.x, 0.f), fmaxf(a.y + c.y, 0.f));
    }
    for (int i = t; i < 64 * 32; i += 512) {
        int r = i >> 5, kk = (i & 31) * 2;
        float2 f = *(const float2*)(Wo + (size_t)m * 4096 + (size_t)r * 64 + kk);
        *(__half2*)(sWo + r * 80 + hperm(kk)) = __floats2half2_rn(f.x, f.y);
    }
    if (t < 64) sBo[t] = bo[m * 64 + t];
    __syncthreads();

    int mrow = (w & 7) * 32;
    int nh   = w >> 3;
    float wgt = mpw[m];

    float acc[2][4][4];
    #pragma unroll
    for (int mt = 0; mt < 2; mt++)
        #pragma unroll
        for (int nt = 0; nt < 4; nt++)
            #pragma unroll
            for (int q = 0; q < 4; q++) acc[mt][nt][q] = 0.f;

    #pragma unroll
    for (int k0 = 0; k0 < 64; k0 += 16) {
        unsigned a[2][4];
        #pragma unroll
        for (int mt = 0; mt < 2; mt++) {
            int r0 = mrow + mt * 16;
            ull vlo = *(const ull*)(sH + (r0 + qr) * 80 + k0 + 4 * qc);
            ull vhi = *(const ull*)(sH + (r0 + 8 + qr) * 80 + k0 + 4 * qc);
            a[mt][0] = (unsigned)vlo; a[mt][2] = (unsigned)(vlo >> 32);
            a[mt][1] = (unsigned)vhi; a[mt][3] = (unsigned)(vhi >> 32);
        }
        #pragma unroll
        for (int nt = 0; nt < 4; nt++) {
            ull bv = *(const ull*)(sWo + (nh * 32 + nt * 8 + qr) * 80 + k0 + 4 * qc);
            unsigned b[2] = { (unsigned)bv, (unsigned)(bv >> 32) };
            mma_f16(acc[0][nt], a[0], b);
            mma_f16(acc[1][nt], a[1], b);
        }
    }
    #pragma unroll
    for (int nt = 0; nt < 4; nt++) {
        int col = nh * 32 + nt * 8 + 2 * qc;
        float bias0 = sBo[col], bias1 = sBo[col + 1];
        #pragma unroll
        for (int mt = 0; mt < 2; mt++) {
            int r0 = mrow + mt * 16 + qr;
            int n0 = node0 + r0, n1 = n0 + 8;
            if (n0 < NN)
                *(float2*)(g_e + ((size_t)n0 * MP + m) * OC + col) =
                    make_float2((acc[mt][nt][0] + bias0) * wgt, (acc[mt][nt][1] + bias1) * wgt);
            if (n1 < NN)
                *(float2*)(g_e + ((size_t)n1 * MP + m) * OC + col) =
                    make_float2((acc[mt][nt][2] + bias0) * wgt, (acc[mt][nt][3] + bias1) * wgt);
        }
    }
}

// =====================================================================
// K3: attention sublayer, 128-token tile (32 nodes), 256 threads.
// smem ~109 KB -> 2 CTAs/SM for cross-CTA latency hiding.
// =====================================================================
__global__ void __launch_bounds__(256, 2) k_attn(
    const float* __restrict__ tinw, const float* __restrict__ tinb,
    const float* __restrict__ tow,  const float* __restrict__ tob,
    const float* __restrict__ g1,   const float* __restrict__ b1v, int l)
{
    extern __shared__ char smb[];
    __half* sE   = (__half*)smb;                 // [128][80]h = 20480 (alias sAO)
    __half* sWin = (__half*)(smb + 20480);       // [192][80]h = 30720
    __half* sQKV = (__half*)(smb + 51200);       // [32 node][768]h = 49152 (alias sO)
    __half* sWo  = (__half*)(smb + 100352);      // [64][80]h = 10240
    float*  sBin = (float*)(smb + 110592);       // 192
    float*  sBo  = (float*)(smb + 111360);       // 64
    __half* sAO  = sE;
    float*  sO   = (float*)(smb + 51200);        // epilogue [128][72]f = 36864
    int t = threadIdx.x, w = t >> 5, lane = t & 31;
    int qr = lane >> 2, qc = lane & 3;
    size_t tok0 = (size_t)blockIdx.x * TBA;

    const float* tw  = tinw + (size_t)l * 192 * 64;
    const float* twO = tow  + (size_t)l * 64 * 64;
    for (int i = t; i < 192 * 32; i += 256) {
        int r = i >> 5, kk = (i & 31) * 2;
        float2 f = *(const float2*)(tw + (size_t)r * 64 + kk);
        *(__half2*)(sWin + r * 80 + hperm(kk)) = __floats2half2_rn(f.x, f.y);
    }
    for (int i = t; i < 64 * 32; i += 256) {
        int r = i >> 5, kk = (i & 31) * 2;
        float2 f = *(const float2*)(twO + (size_t)r * 64 + kk);
        *(__half2*)(sWo + r * 80 + hperm(kk)) = __floats2half2_rn(f.x, f.y);
    }
    for (int i = t; i < TBA * 32; i += 256) {
        int row = i >> 5, kk = (i & 31) * 2;
        float2 f = *(const float2*)(g_e + (tok0 + row) * 64 + kk);
        *(__half2*)(sE + row * 80 + hperm(kk)) = __floats2half2_rn(f.x, f.y);
    }
    if (t < 192) sBin[t] = tinb[l * 192 + t];
    if (t >= 192 && t < 256) sBo[t - 192] = tob[l * 64 + (t - 192)];
    __syncthreads();

    int mrow = (w & 3) * 32;     // 4 m-strips of 32 rows
    int nh   = w >> 2;           // 2 n-halves

    // ---- qkv GEMM: [128 tok] x [192], 2 N-passes of 48 per half ----
    #pragma unroll
    for (int np = 0; np < 2; np++) {
        float acc[2][6][4];
        #pragma unroll
        for (int nt = 0; nt < 6; nt++) {
            int col = nh * 96 + np * 48 + nt * 8 + 2 * qc;
            float bv0 = sBin[col], bv1 = sBin[col + 1];
            #pragma unroll
            for (int mt = 0; mt < 2; mt++) {
                acc[mt][nt][0] = bv0; acc[mt][nt][1] = bv1;
                acc[mt][nt][2] = bv0; acc[mt][nt][3] = bv1;
            }
        }
        #pragma unroll
        for (int k0 = 0; k0 < 64; k0 += 16) {
            unsigned a[2][4];
            #pragma unroll
            for (int mt = 0; mt < 2; mt++) {
                int r0 = mrow + mt * 16;
                ull vlo = *(const ull*)(sE + (r0 + qr) * 80 + k0 + 4 * qc);
                ull vhi = *(const ull*)(sE + (r0 + 8 + qr) * 80 + k0 + 4 * qc);
                a[mt][0] = (unsigned)vlo; a[mt][2] = (unsigned)(vlo >> 32);
                a[mt][1] = (unsigned)vhi; a[mt][3] = (unsigned)(vhi >> 32);
            }
            #pragma unroll
            for (int nt = 0; nt < 6; nt++) {
                ull bv = *(const ull*)(sWin + (nh * 96 + np * 48 + nt * 8 + qr) * 80 + k0 + 4 * qc);
                unsigned b[2] = { (unsigned)bv, (unsigned)(bv >> 32) };
                mma_f16(acc[0][nt], a[0], b);
                mma_f16(acc[1][nt], a[1], b);
            }
        }
        #pragma unroll
        for (int nt = 0; nt < 6; nt++) {
            int col = nh * 96 + np * 48 + nt * 8 + 2 * qc;
            #pragma unroll
            for (int mt = 0; mt < 2; mt++) {
                int r0 = mrow + mt * 16 + qr;
                int r1 = r0 + 8;
                *(__half2*)(sQKV + (r0 >> 2) * 768 + (r0 & 3) * 192 + col) =
                    __floats2half2_rn(acc[mt][nt][0], acc[mt][nt][1]);
                *(__half2*)(sQKV + (r1 >> 2) * 768 + (r1 & 3) * 192 + col) =
                    __floats2half2_rn(acc[mt][nt][2], acc[mt][nt][3]);
            }
        }
    }
    __syncthreads();

    // ---- attention core: 1024 units = (node 0..31, h, mq), 4 iters ----
    #pragma unroll
    for (int it = 0; it < 4; it++) {
        int u = it * 256 + t;
        int node = u >> 5, hd = (u >> 2) & 7, mq = u & 3;
        const __half* base = sQKV + node * 768;
        float q[8];
        #pragma unroll
        for (int d = 0; d < 4; d++) {
            float2 f = __half22float2(*(const __half2*)(base + mq * 192 + hd * 8 + 2 * d));
            q[2 * d] = f.x; q[2 * d + 1] = f.y;
        }
        float sc[4];
        #pragma unroll
        for (int mk = 0; mk < 4; mk++) {
            const __half* kp = base + mk * 192 + 64 + hd * 8;
            float a = 0.f;
            #pragma unroll
            for (int d = 0; d < 4; d++) {
                float2 f = __half22float2(*(const __half2*)(kp + 2 * d));
                a = fmaf(q[2 * d], f.x, a); a = fmaf(q[2 * d + 1], f.y, a);
            }
            sc[mk] = a * 0.35355339059327373f;
        }
        float mx = fmaxf(fmaxf(sc[0], sc[1]), fmaxf(sc[2], sc[3]));
        float p[4]; float psum = 0.f;
        #pragma unroll
        for (int mk = 0; mk < 4; mk++) { p[mk] = __expf(sc[mk] - mx); psum += p[mk]; }
        float inv = 1.0f / psum;
        float o[8];
        #pragma unroll
        for (int d = 0; d < 8; d++) o[d] = 0.f;
        #pragma unroll
        for (int mk = 0; mk < 4; mk++) {
            const __half* vp = base + mk * 192 + 128 + hd * 8;
            float pw = p[mk] * inv;
            #pragma unroll
            for (int d = 0; d < 4; d++) {
                float2 f = __half22float2(*(const __half2*)(vp + 2 * d));
                o[2 * d]     = fmaf(pw, f.x, o[2 * d]);
                o[2 * d + 1] = fmaf(pw, f.y, o[2 * d + 1]);
            }
        }
        int row = node * 4 + mq;
        #pragma unroll
        for (int d = 0; d < 4; d++) {
            int col = hd * 8 + 2 * d;
            *(__half2*)(sAO + row * 80 + hperm(col)) = __floats2half2_rn(o[2 * d], o[2 * d + 1]);
        }
    }
    __syncthreads();

    // ---- proj GEMM + residual into sO, then LN1 ----
    {
        float acc[2][4][4];
        #pragma unroll
        for (int mt = 0; mt < 2; mt++)
            #pragma unroll
            for (int nt = 0; nt < 4; nt++)
                #pragma unroll
                for (int q = 0; q < 4; q++) acc[mt][nt][q] = 0.f;
        #pragma unroll
        for (int k0 = 0; k0 < 64; k0 += 16) {
            unsigned a[2][4];
            #pragma unroll
            for (int mt = 0; mt < 2; mt++) {
                int r0 = mrow + mt * 16;
                ull vlo = *(const ull*)(sAO + (r0 + qr) * 80 + k0 + 4 * qc);
                ull vhi = *(const ull*)(sAO + (r0 + 8 + qr) * 80 + k0 + 4 * qc);
                a[mt][0] = (unsigned)vlo; a[mt][2] = (unsigned)(vlo >> 32);
                a[mt][1] = (unsigned)vhi; a[mt][3] = (unsigned)(vhi >> 32);
            }
            #pragma unroll
            for (int nt = 0; nt < 4; nt++) {
                ull bv = *(const ull*)(sWo + (nh * 32 + nt * 8 + qr) * 80 + k0 + 4 * qc);
                unsigned b[2] = { (unsigned)bv, (unsigned)(bv >> 32) };
                mma_f16(acc[0][nt], a[0], b);
                mma_f16(acc[1][nt], a[1], b);
            }
        }
        __syncthreads();   // qkv reads done; sO (aliasing sQKV) safe to write
        #pragma unroll
        for (int nt = 0; nt < 4; nt++) {
            int col = nh * 32 + nt * 8 + 2 * qc;
            float bias0 = sBo[col], bias1 = sBo[col + 1];
            #pragma unroll
            for (int mt = 0; mt < 2; mt++) {
                int r0 = mrow + mt * 16 + qr;
                int r1 = r0 + 8;
                float2 e0 = *(const float2*)(g_e + (tok0 + r0) * 64 + col);
                float2 e1 = *(const float2*)(g_e + (tok0 + r1) * 64 + col);
                sO[r0 * 72 + col]     = acc[mt][nt][0] + bias0 + e0.x;
                sO[r0 * 72 + col + 1] = acc[mt][nt][1] + bias1 + e0.y;
                sO[r1 * 72 + col]     = acc[mt][nt][2] + bias0 + e1.x;
                sO[r1 * 72 + col + 1] = acc[mt][nt][3] + bias1 + e1.y;
            }
        }
    }
    __syncthreads();

    // LN1: 2 threads per token (128 tokens)
    int tk2 = t >> 1, half = t & 1;
    const float* ob = sO + tk2 * 72 + half * 32;
    float s = 0.f, s2 = 0.f;
    #pragma unroll
    for (int i = 0; i < 32; i++) { float v = ob[i]; s += v; s2 += v * v; }
    s  += __shfl_xor_sync(0xffffffffu, s, 1);
    s2 += __shfl_xor_sync(0xffffffffu, s2, 1);
    float mu   = s * (1.f / 64.f);
    float rstd = rsqrtf(s2 * (1.f / 64.f) - mu * mu + LN_EPS);
    float* go = g_e + (tok0 + tk2) * 64 + half * 32;
    #pragma unroll
    for (int i = 0; i < 32; i++) {
        int c = half * 32 + i;
        go[i] = (ob[i] - mu) * rstd * g1[l * 64 + c] + b1v[l * 64 + c];
    }
}

// =====================================================================
// K4: FF on fp16 mma.sync, register-resident H, double-buffered weights.
// =====================================================================
__global__ void __launch_bounds__(512, 1) k_ff(
    const float* __restrict__ ff1w, const float* __restrict__ ff1b,
    const float* __restrict__ ff2w, const float* __restrict__ ff2b,
    const float* __restrict__ g2,   const float* __restrict__ b2, int l)
{
    extern __shared__ char smb[];
    __half* sE  = (__half*)smb;              // [256][80]h = 40960B
    __half* sW1 = (__half*)(smb + 40960);    // [2][64][80]h
    __half* sW2 = (__half*)(smb + 61440);    // [2][64][80]h
    float*  sB1 = (float*)(smb + 81920);     // [2][64]
    float*  sO  = (float*)smb;               // alias epilogue [256][72]f
    int t = threadIdx.x, w = t >> 5, lane = t & 31;
    int qr = lane >> 2, qc = lane & 3;
    size_t tok0 = (size_t)blockIdx.x * TB;
    int mrow = w * 16;

    const float* f1w = ff1w + (size_t)l * FFD * OC;
    const float* f1b = ff1b + (size_t)l * FFD;
    const float* f2w = ff2w + (size_t)l * OC * FFD;

    for (int i = t; i < TB * 32; i += 512) {
        int row = i >> 5, kk = (i & 31) * 2;
        float2 f = *(const float2*)(g_e + tok0 * 64 + (size_t)row * 64 + kk);
        *(__half2*)(sE + row * 80 + hperm(kk)) = __floats2half2_rn(f.x, f.y);
    }
    for (int i = t; i < JC * 32; i += 512) {
        int j = i >> 5, kk = (i & 31) * 2;
        float2 f = *(const float2*)(f1w + (size_t)j * 64 + kk);
        *(__half2*)(sW1 + j * 80 + hperm(kk)) = __floats2half2_rn(f.x, f.y);
    }
    for (int i = t; i < 64 * 32; i += 512) {
        int c = i >> 5, jj = (i & 31) * 2;
        float2 f = *(const float2*)(f2w + (size_t)c * FFD + jj);
        *(__half2*)(sW2 + c * 80 + hperm(jj)) = __floats2half2_rn(f.x, f.y);
    }
    if (t < 64) sB1[t] = f1b[t];
    __syncthreads();

    float acc2[8][4];
    #pragma unroll
    for (int nt = 0; nt < 8; nt++)
        #pragma unroll
        for (int q = 0; q < 4; q++) acc2[nt][q] = 0.f;

    for (int ch = 0; ch < NCH; ch++) {
        int buf = ch & 1, nb = buf ^ 1;
        const __half* w1 = sW1 + buf * 5120;
        const __half* w2 = sW2 + buf * 5120;
        const float*  bb = sB1 + buf * 64;
        int jb2 = (ch + 1) * JC;

        float2 w1n[4], w2n[4]; float b1n = 0.f;
        if (ch < NCH - 1) {
            #pragma unroll
            for (int r = 0; r < 4; r++) {
                int idx = t + r * 512;
                int j = idx >> 5, kk = (idx & 31) * 2;
                w1n[r] = *(const float2*)(f1w + (size_t)(jb2 + j) * 64 + kk);
            }
            #pragma unroll
            for (int r = 0; r < 4; r++) {
                int idx = t + r * 512;
                int c = idx >> 5, jj = (idx & 31) * 2;
                w2n[r] = *(const float2*)(f2w + (size_t)c * FFD + jb2 + jj);
            }
            if (t < 64) b1n = f1b[jb2 + t];
        }

        float acc1[8][4];
        #pragma unroll
        for (int nt = 0; nt < 8; nt++) {
            float bv0 = bb[nt * 8 + 2 * qc];
            float bv1 = bb[nt * 8 + 2 * qc + 1];
            acc1[nt][0] = bv0; acc1[nt][1] = bv1;
            acc1[nt][2] = bv0; acc1[nt][3] = bv1;
        }
        #pragma unroll
        for (int k0 = 0; k0 < 64; k0 += 16) {
            ull vlo = *(const ull*)(sE + (mrow + qr) * 80 + k0 + 4 * qc);
            ull vhi = *(const ull*)(sE + (mrow + 8 + qr) * 80 + k0 + 4 * qc);
            unsigned a[4] = { (unsigned)vlo, (unsigned)vhi,
                              (unsigned)(vlo >> 32), (unsigned)(vhi >> 32) };
            #pragma unroll
            for (int nt = 0; nt < 8; nt++) {
                ull bv = *(const ull*)(w1 + (nt * 8 + qr) * 80 + k0 + 4 * qc);
                unsigned b[2] = { (unsigned)bv, (unsigned)(bv >> 32) };
                mma_f16(acc1[nt], a, b);
            }
        }

        unsigned afr[4][4];
        #pragma unroll
        for (int kt = 0; kt < 4; kt++) {
            afr[kt][0] = pack_h2(fmaxf(acc1[2 * kt][0], 0.f),     fmaxf(acc1[2 * kt][1], 0.f));
            afr[kt][1] = pack_h2(fmaxf(acc1[2 * kt][2], 0.f),     fmaxf(acc1[2 * kt][3], 0.f));
            afr[kt][2] = pack_h2(fmaxf(acc1[2 * kt + 1][0], 0.f), fmaxf(acc1[2 * kt + 1][1], 0.f));
            afr[kt][3] = pack_h2(fmaxf(acc1[2 * kt + 1][2], 0.f), fmaxf(acc1[2 * kt + 1][3], 0.f));
        }

        #pragma unroll
        for (int kt = 0; kt < 4; kt++) {
            #pragma unroll
            for (int nt = 0; nt < 8; nt++) {
                ull bv = *(const ull*)(w2 + (nt * 8 + qr) * 80 + kt * 16 + 4 * qc);
                unsigned b[2] = { (unsigned)bv, (unsigned)(bv >> 32) };
                mma_f16(acc2[nt], afr[kt], b);
            }
        }

        if (ch < NCH - 1) {
            #pragma unroll
            for (int r = 0; r < 4; r++) {
                int idx = t + r * 512;
                int j = idx >> 5, kk = (idx & 31) * 2;
                *(__half2*)(sW1 + nb * 5120 + j * 80 + hperm(kk)) =
                    __floats2half2_rn(w1n[r].x, w1n[r].y);
            }
            #pragma unroll
            for (int r = 0; r < 4; r++) {
                int idx = t + r * 512;
                int c = idx >> 5, jj = (idx & 31) * 2;
                *(__half2*)(sW2 + nb * 5120 + c * 80 + hperm(jj)) =
                    __floats2half2_rn(w2n[r].x, w2n[r].y);
            }
            if (t < 64) sB1[nb * 64 + t] = b1n;
        }
        __syncthreads();
    }

    #pragma unroll
    for (int nt = 0; nt < 8; nt++) {
        int col = nt * 8 + 2 * qc;
        float bias0 = ff2b[l * OC + col];
        float bias1 = ff2b[l * OC + col + 1];
        int r0 = mrow + qr, r1 = r0 + 8;
        float2 e0 = *(const float2*)(g_e + (tok0 + r0) * 64 + col);
        float2 e1 = *(const float2*)(g_e + (tok0 + r1) * 64 + col);
        sO[r0 * 72 + col]     = acc2[nt][0] + bias0 + e0.x;
        sO[r0 * 72 + col + 1] = acc2[nt][1] + bias1 + e0.y;
        sO[r1 * 72 + col]     = acc2[nt][2] + bias0 + e1.x;
        sO[r1 * 72 + col + 1] = acc2[nt][3] + bias1 + e1.y;
    }
    __syncthreads();

    int tk2 = t >> 1, half = t & 1;
    const float* ob = sO + tk2 * 72 + half * 32;
    float s = 0.f, s2 = 0.f;
    #pragma unroll
    for (int i = 0; i < 32; i++) { float v = ob[i]; s += v; s2 += v * v; }
    s  += __shfl_xor_sync(0xffffffffu, s, 1);
    s2 += __shfl_xor_sync(0xffffffffu, s2, 1);
    float mu   = s * (1.f / 64.f);
    float rstd = rsqrtf(s2 * (1.f / 64.f) - mu * mu + LN_EPS);
    float* go = g_e + (tok0 + tk2) * 64 + half * 32;
    #pragma unroll
    for (int i = 0; i < 32; i++) {
        int c = half * 32 + i;
        go[i] = (ob[i] - mu) * rstd * g2[l * OC + c] + b2[l * OC + c];
    }
}

// =====================================================================
// K5: head
// =====================================================================
__global__ void __launch_bounds__(256) k_head(
    const float* __restrict__ r1w, const float* __restrict__ r1b,
    const float* __restrict__ r2w, const float* __restrict__ r2b,
    float* __restrict__ out)
{
    __shared__ float sR1T[64 * 65];
    __shared__ float sR2[64];
    __shared__ float sP[8][64];
    int t = threadIdx.x;
    for (int i = t; i < 4096; i += 256) {
        int c = i >> 6, k = i & 63;
        sR1T[k * 65 + c] = r1w[c * 64 + k];
    }
    if (t < 64) sR2[t] = r2w[t];
    __syncthreads();
    int w = t >> 5, lane = t & 31;
    int n = blockIdx.x * 8 + w;
    const float* eb = g_e + (size_t)n * 256;
    float p0 = (eb[lane] + eb[64 + lane] + eb[128 + lane] + eb[192 + lane]) * 0.25f;
    float p1 = (eb[32 + lane] + eb[96 + lane] + eb[160 + lane] + eb[224 + lane]) * 0.25f;
    sP[w][lane]      = p0;
    sP[w][lane + 32] = p1;
    __syncwarp();
    float a0 = r1b[lane], a1 = r1b[lane + 32];
    #pragma unroll 8
    for (int k = 0; k < 64; k++) {
        float pv = sP[w][k];
        a0 = fmaf(pv, sR1T[k * 65 + lane], a0);
        a1 = fmaf(pv, sR1T[k * 65 + lane + 32], a1);
    }
    a0 = fmaxf(a0, 0.f); a1 = fmaxf(a1, 0.f);
    float acc = a0 * sR2[lane] + a1 * sR2[lane + 32];
    #pragma unroll
    for (int off = 16; off; off >>= 1) acc += __shfl_xor_sync(0xffffffffu, acc, off);
    if (lane == 0) out[n] = acc + r2b[0];
}

// =====================================================================
extern "C" void kernel_launch(void* const* d_in, const int* in_sizes, int n_in,
                              void* d_out, int out_size) {
    const float* x    = (const float*)d_in[0];
    const int*   ei   = (const int*)  d_in[1];
    const float* mpw  = (const float*)d_in[2];
    const float* W0   = (const float*)d_in[3];
    const float* b0   = (const float*)d_in[4];
    const float* Wl   = (const float*)d_in[5];
    const float* bl   = (const float*)d_in[6];
    const float* W1   = (const float*)d_in[7];
    const float* b1   = (const float*)d_in[8];
    const float* Wo   = (const float*)d_in[9];
    const float* bo   = (const float*)d_in[10];
    const float* tinw = (const float*)d_in[11];
    const float* tinb = (const float*)d_in[12];
    const float* tow  = (const float*)d_in[13];
    const float* tob  = (const float*)d_in[14];
    const float* ln1g = (const float*)d_in[15];
    const float* ln1b = (const float*)d_in[16];
    const float* ff1w = (const float*)d_in[17];
    const float* ff1b = (const float*)d_in[18];
    const float* ff2w = (const float*)d_in[19];
    const float* ff2b = (const float*)d_in[20];
    const float* ln2g = (const float*)d_in[21];
    const float* ln2b = (const float*)d_in[22];
    const float* r1w  = (const float*)d_in[23];
    const float* r1b  = (const float*)d_in[24];
    const float* r2w  = (const float*)d_in[25];
    const float* r2b  = (const float*)d_in[26];
    float* out = (float*)d_out;
    (void)in_sizes; (void)n_in; (void)out_size;

    cudaFuncSetAttribute(k_xw,   cudaFuncAttributeMaxDynamicSharedMemorySize, 110848);
    cudaFuncSetAttribute(k_gnn,  cudaFuncAttributeMaxDynamicSharedMemorySize, 51456);
    cudaFuncSetAttribute(k_attn, cudaFuncAttributeMaxDynamicSharedMemorySize, 111616);
    cudaFuncSetAttribute(k_ff,   cudaFuncAttributeMaxDynamicSharedMemorySize, 82432);

    dim3 gxw(118, 4);
    k_bucket<<<7500, 256>>>(ei);                                             // 1
    k_xw<<<gxw, 512, 110848>>>(x, W0, b0, Wl, bl, W1, b1);                   // 2
    k_agg<<<7500, 512>>>();                                                  // 3
    k_ovf<<<1, 64>>>();                                                      // 4
    k_gnn<<<gxw, 512, 51456>>>(Wo, bo, mpw);                                 // 5
    k_attn<<<NBA, 256, 111616>>>(tinw, tinb, tow, tob, ln1g, ln1b, 0);       // 6 <- ncu
    k_ff<<<NBLK, 512, 82432>>>(ff1w, ff1b, ff2w, ff2b, ln2g, ln2b, 0);       // 7
    k_attn<<<NBA, 256, 111616>>>(tinw, tinb, tow, tob, ln1g, ln1b, 1);       // 8
    k_ff<<<NBLK, 512, 82432>>>(ff1w, ff1b, ff2w, ff2b, ln2g, ln2b, 1);       // 9
    k_head<<<3750, 256>>>(r1w, r1b, r2w, r2b, out);                          // 10
}